// round 1
// baseline (speedup 1.0000x reference)
#include <cuda_runtime.h>
#include <math.h>
#include <stdint.h>

#define FULLMASK 0xffffffffu

// problem dims
#define NTOK   343
#define NHEAD  6
#define HD     32
#define CDIM   192
#define LTOT   21952   // 28^3
#define NWIN   128     // 2 batches * 64 windows
#define NROWS  43904   // 128*343 = 2*21952

// ---------------- device scratch (static allocation; no cudaMalloc allowed) ----
__device__ float g_hb[2197 * 6];
__device__ float g_rpb[6 * 343 * 343];
__device__ float g_q[(size_t)NWIN * NHEAD * NTOK * HD];       // 8.43M
__device__ float g_k[(size_t)NWIN * NHEAD * NTOK * HD];
__device__ float g_v[(size_t)NWIN * NHEAD * NTOK * HD];
__device__ float g_attnout[(size_t)NWIN * NTOK * CDIM];       // [b_][n][h*32+d]
__device__ float g_xa[(size_t)2 * LTOT * CDIM];               // proj result, scattered
__device__ float g_x1[(size_t)2 * LTOT * CDIM];
__device__ float g_m[(size_t)2 * LTOT * CDIM];
__device__ float g_hmid[(size_t)NROWS * 768];                 // 134.9MB

// ---------------- CPB MLP: hb[t][h] ------------------------------------------
__device__ __forceinline__ float cpb_coord(int i) {
    float v = (float)(i - 6) * (8.0f / 6.0f);
    float av = fabsf(v);
    float r = log2f(av + 1.0f) * (1.0f / 3.0f);   // log2(8)=3
    return (v < 0.f) ? -r : r;
}

__global__ void __launch_bounds__(256) cpb_kernel(const float* __restrict__ w1,
                                                  const float* __restrict__ b1,
                                                  const float* __restrict__ w2) {
    __shared__ float hid[512];
    int t = blockIdx.x;                    // 0..2196
    int a = t / 169;
    int rem = t - a * 169;
    int b = rem / 13;
    int c = rem - b * 13;
    float c0 = cpb_coord(a), c1 = cpb_coord(b), c2 = cpb_coord(c);
    for (int j = threadIdx.x; j < 512; j += blockDim.x) {
        float hv = c0 * w1[j * 3 + 0] + c1 * w1[j * 3 + 1] + c2 * w1[j * 3 + 2] + b1[j];
        hid[j] = fmaxf(hv, 0.f);
    }
    __syncthreads();
    if (threadIdx.x < 192) {
        int hh = threadIdx.x >> 5, lane = threadIdx.x & 31;
        float s = 0.f;
        for (int j = lane; j < 512; j += 32) s += hid[j] * w2[hh * 512 + j];
#pragma unroll
        for (int off = 16; off; off >>= 1) s += __shfl_xor_sync(FULLMASK, s, off);
        if (lane == 0) g_hb[t * 6 + hh] = s;
    }
}

// ---------------- rpb[h][i][j] = 16*sigmoid(hb[rpi(i,j)][h]) -------------------
__global__ void rpb_kernel() {
    const int total = 6 * 343 * 343;
    for (int idx = blockIdx.x * blockDim.x + threadIdx.x; idx < total;
         idx += gridDim.x * blockDim.x) {
        int hh = idx / 117649;
        int rem = idx - hh * 117649;
        int i = rem / 343;
        int j = rem - i * 343;
        int dh = i / 49 - j / 49 + 6;
        int dw = (i / 7) % 7 - (j / 7) % 7 + 6;
        int dd = i % 7 - j % 7 + 6;
        int tix = (dh * 13 + dw) * 13 + dd;
        float v = g_hb[tix * 6 + hh];
        g_rpb[idx] = 16.f / (1.f + __expf(-v));
    }
}

// ---------------- tiled SGEMM: BM=64 BN=64 BK=16, 256 thr, 4x4 microtile -------
// MODE 0: QKV  (A = x, gathered via shift+window; out -> g_q/g_k/g_v + biases)
// MODE 1: PROJ (A = g_attnout; out -> g_xa scattered via window-reverse+roll)
// MODE 2: FC1  (A = g_x1; out -> g_hmid with exact GELU)
// MODE 3: FC2  (A = g_hmid; out -> g_m)
template <int MODE>
__global__ void __launch_bounds__(256) gemm_tile(const float* __restrict__ A,
                                                 const float* __restrict__ W,
                                                 const float* __restrict__ b1,
                                                 const float* __restrict__ b2,
                                                 float* __restrict__ OUT,
                                                 int K, int N) {
    __shared__ __align__(16) float As[16 * 64];
    __shared__ __align__(16) float Bs[16 * 64];
    const int tid = threadIdx.x;
    const int tx = tid & 15, ty = tid >> 4;
    const int m0 = blockIdx.y * 64, n0 = blockIdx.x * 64;

    const int lm = tid >> 2;          // 0..63
    const int lk = (tid & 3) * 4;     // 0,4,8,12

    const float* aptr = nullptr;
    bool avalid = true;
    if (MODE == 0) {
        int n = m0 + lm;
        avalid = (n < NTOK);
        int b_ = blockIdx.z;
        int bb = b_ >> 6, win = b_ & 63;
        int wa = win >> 4, wb = (win >> 2) & 3, wc = win & 3;
        int i = n / 49, j = (n / 7) % 7, kk = n % 7;
        if (avalid) {
            int hs = (wa * 7 + i + 3) % 28;
            int ws = (wb * 7 + j + 3) % 28;
            int ds = (wc * 7 + kk + 3) % 28;
            aptr = A + ((size_t)bb * LTOT + (hs * 784 + ws * 28 + ds)) * CDIM;
        }
    } else if (MODE == 1) {
        int n = m0 + lm;
        avalid = (n < NTOK);
        aptr = g_attnout + ((size_t)blockIdx.z * NTOK + (avalid ? n : 0)) * CDIM;
    } else if (MODE == 2) {
        aptr = g_x1 + (size_t)(m0 + lm) * K;
    } else {
        aptr = g_hmid + (size_t)(m0 + lm) * K;
    }
    const float* bptr = W + (size_t)(n0 + lm) * K;

    float acc[4][4] = {};
    for (int kc = 0; kc < K; kc += 16) {
        float4 av = make_float4(0.f, 0.f, 0.f, 0.f);
        if (avalid) av = *(const float4*)(aptr + kc + lk);
        float4 bv = *(const float4*)(bptr + kc + lk);
        __syncthreads();
        As[(lk + 0) * 64 + lm] = av.x;
        As[(lk + 1) * 64 + lm] = av.y;
        As[(lk + 2) * 64 + lm] = av.z;
        As[(lk + 3) * 64 + lm] = av.w;
        Bs[(lk + 0) * 64 + lm] = bv.x;
        Bs[(lk + 1) * 64 + lm] = bv.y;
        Bs[(lk + 2) * 64 + lm] = bv.z;
        Bs[(lk + 3) * 64 + lm] = bv.w;
        __syncthreads();
#pragma unroll
        for (int k = 0; k < 16; ++k) {
            float4 a4 = *(const float4*)&As[k * 64 + ty * 4];
            float4 b4 = *(const float4*)&Bs[k * 64 + tx * 4];
            float aa[4] = {a4.x, a4.y, a4.z, a4.w};
            float bb[4] = {b4.x, b4.y, b4.z, b4.w};
#pragma unroll
            for (int i = 0; i < 4; ++i)
#pragma unroll
                for (int j = 0; j < 4; ++j) acc[i][j] += aa[i] * bb[j];
        }
    }

    if (MODE == 0) {
        int b_ = blockIdx.z;
#pragma unroll
        for (int i = 0; i < 4; ++i) {
            int n = m0 + ty * 4 + i;
            if (n >= NTOK) continue;
#pragma unroll
            for (int j = 0; j < 4; ++j) {
                int o = n0 + tx * 4 + j;
                float v = acc[i][j];
                int sct = o / 192;
                int remc = o - sct * 192;
                int hh = remc >> 5, dd = remc & 31;
                size_t dst = ((size_t)(b_ * 6 + hh) * NTOK + n) * HD + dd;
                if (sct == 0) g_q[dst] = v + b1[remc];
                else if (sct == 1) g_k[dst] = v;
                else g_v[dst] = v + b2[remc];
            }
        }
    } else if (MODE == 1) {
        int b_ = blockIdx.z;
        int bb = b_ >> 6, win = b_ & 63;
        int wa = win >> 4, wb = (win >> 2) & 3, wc = win & 3;
#pragma unroll
        for (int i = 0; i < 4; ++i) {
            int n = m0 + ty * 4 + i;
            if (n >= NTOK) continue;
            int i3 = n / 49, j3 = (n / 7) % 7, k3 = n % 7;
            int hd_ = (wa * 7 + i3 + 3) % 28;
            int wd_ = (wb * 7 + j3 + 3) % 28;
            int dd_ = (wc * 7 + k3 + 3) % 28;
            size_t dst = ((size_t)bb * LTOT + (hd_ * 784 + wd_ * 28 + dd_)) * CDIM;
#pragma unroll
            for (int j = 0; j < 4; ++j) {
                int col = n0 + tx * 4 + j;
                g_xa[dst + col] = acc[i][j] + b1[col];
            }
        }
    } else if (MODE == 2) {
#pragma unroll
        for (int i = 0; i < 4; ++i) {
            int row = m0 + ty * 4 + i;
#pragma unroll
            for (int j = 0; j < 4; ++j) {
                int col = n0 + tx * 4 + j;
                float xv = acc[i][j] + b1[col];
                g_hmid[(size_t)row * 768 + col] =
                    0.5f * xv * (1.f + erff(xv * 0.70710678118654752f));
            }
        }
    } else {
#pragma unroll
        for (int i = 0; i < 4; ++i) {
            int row = m0 + ty * 4 + i;
#pragma unroll
            for (int j = 0; j < 4; ++j) {
                int col = n0 + tx * 4 + j;
                g_m[(size_t)row * 192 + col] = acc[i][j] + b1[col];
            }
        }
    }
}

// ---------------- attention: one block per (window, head) ---------------------
// smem: Ks[343][33] (padded), Vs[343][32], Ps[8 warps][4 rows][344], region[343]
#define ATTN_SMEM_FLOATS (343 * 33 + 343 * 32 + 8 * 4 * 344)
#define ATTN_SMEM_BYTES (ATTN_SMEM_FLOATS * 4 + 384)

__global__ void __launch_bounds__(256) attn_kernel(const float* __restrict__ logit_scale) {
    extern __shared__ float sm[];
    float* Ks = sm;                                 // 343*33
    float* Vs = Ks + 343 * 33;                      // 343*32
    float* Ps = Vs + 343 * 32;                      // 8*4*344
    unsigned char* region = (unsigned char*)(Ps + 8 * 4 * 344);

    const int bh = blockIdx.x;           // 0..767
    const int b_ = bh / 6, h = bh - (bh / 6) * 6;
    const int tid = threadIdx.x;
    const int lane = tid & 31, w = tid >> 5;

    const size_t kvbase = (size_t)bh * (NTOK * HD);
    const float* kg = g_k + kvbase;
    const float* vg = g_v + kvbase;

    for (int idx = tid; idx < NTOK * HD; idx += 256) {
        int r = idx >> 5, d = idx & 31;
        Ks[r * 33 + d] = kg[idx];
        Vs[idx] = vg[idx];
    }
    {
        int win = b_ & 63;
        int wa = win >> 4, wb = (win >> 2) & 3, wc = win & 3;
        for (int t = tid; t < NTOK; t += 256) {
            int ih = t / 49, iw = (t / 7) % 7, id = t % 7;
            int rH = (wa < 3) ? 0 : ((ih < 4) ? 1 : 2);
            int rW = (wb < 3) ? 0 : ((iw < 4) ? 1 : 2);
            int rD = (wc < 3) ? 0 : ((id < 4) ? 1 : 2);
            region[t] = (unsigned char)(rH * 9 + rW * 3 + rD);
        }
    }
    __syncthreads();
    // normalize K rows in smem
    for (int r = tid; r < NTOK; r += 256) {
        float s = 0.f;
#pragma unroll
        for (int d = 0; d < 32; ++d) { float vv = Ks[r * 33 + d]; s += vv * vv; }
        float inv = 1.f / fmaxf(sqrtf(s), 1e-12f);
#pragma unroll
        for (int d = 0; d < 32; ++d) Ks[r * 33 + d] *= inv;
    }
    __syncthreads();

    const float scale = __expf(fminf(logit_scale[h], 4.6051701859880914f));  // ln(100)
    const float* rpbh = g_rpb + (size_t)h * 343 * 343;
    float* Pw = Ps + w * 4 * 344;

    for (int g = w; g * 4 < NTOK; g += 8) {
        const int r0 = g * 4;
        float qv[4];
#pragma unroll
        for (int u = 0; u < 4; ++u) {
            int r = r0 + u;
            qv[u] = (r < NTOK) ? g_q[kvbase + (size_t)r * HD + lane] : 0.f;
        }
#pragma unroll
        for (int u = 0; u < 4; ++u) {
            float s = qv[u] * qv[u];
#pragma unroll
            for (int off = 16; off; off >>= 1) s += __shfl_xor_sync(FULLMASK, s, off);
            float inv = scale / fmaxf(sqrtf(s), 1e-12f);
            qv[u] *= inv;
        }
        unsigned char regq[4];
#pragma unroll
        for (int u = 0; u < 4; ++u) {
            int r = r0 + u;
            regq[u] = region[(r < NTOK) ? r : (NTOK - 1)];
        }
        float mx[4] = {-1e30f, -1e30f, -1e30f, -1e30f};

        for (int t = 0; t < 11; ++t) {
            int jj = t * 32 + lane;
            bool valid = jj < NTOK;
            const float* kp = Ks + (valid ? jj : (NTOK - 1)) * 33;
            float a0 = 0.f, a1 = 0.f, a2 = 0.f, a3 = 0.f;
#pragma unroll
            for (int d = 0; d < 32; ++d) {
                float kd = kp[d];
                a0 += __shfl_sync(FULLMASK, qv[0], d) * kd;
                a1 += __shfl_sync(FULLMASK, qv[1], d) * kd;
                a2 += __shfl_sync(FULLMASK, qv[2], d) * kd;
                a3 += __shfl_sync(FULLMASK, qv[3], d) * kd;
            }
            float accs[4] = {a0, a1, a2, a3};
            unsigned char regk = region[valid ? jj : 0];
#pragma unroll
            for (int u = 0; u < 4; ++u) {
                int r = r0 + u;
                if (valid && r < NTOK) {
                    float s = accs[u] + rpbh[(size_t)r * 343 + jj];
                    if (regq[u] != regk) s -= 100.f;
                    Pw[u * 344 + jj] = s;
                    mx[u] = fmaxf(mx[u], s);
                }
            }
        }
#pragma unroll
        for (int u = 0; u < 4; ++u)
#pragma unroll
            for (int off = 16; off; off >>= 1)
                mx[u] = fmaxf(mx[u], __shfl_xor_sync(FULLMASK, mx[u], off));

        float sums[4] = {0.f, 0.f, 0.f, 0.f};
        for (int t = 0; t < 11; ++t) {
            int jj = t * 32 + lane;
            if (jj < NTOK) {
#pragma unroll
                for (int u = 0; u < 4; ++u) {
                    int r = r0 + u;
                    if (r < NTOK) {
                        float p = __expf(Pw[u * 344 + jj] - mx[u]);
                        Pw[u * 344 + jj] = p;
                        sums[u] += p;
                    }
                }
            }
        }
#pragma unroll
        for (int u = 0; u < 4; ++u)
#pragma unroll
            for (int off = 16; off; off >>= 1)
                sums[u] += __shfl_xor_sync(FULLMASK, sums[u], off);

        __syncwarp();
        float o0 = 0.f, o1 = 0.f, o2 = 0.f, o3 = 0.f;
        for (int j = 0; j < NTOK; ++j) {
            float vv = Vs[j * 32 + lane];
            o0 += Pw[0 * 344 + j] * vv;
            o1 += Pw[1 * 344 + j] * vv;
            o2 += Pw[2 * 344 + j] * vv;
            o3 += Pw[3 * 344 + j] * vv;
        }
        float outs[4] = {o0, o1, o2, o3};
#pragma unroll
        for (int u = 0; u < 4; ++u) {
            int r = r0 + u;
            if (r < NTOK) {
                g_attnout[((size_t)b_ * NTOK + r) * CDIM + h * HD + lane] =
                    outs[u] * (1.f / sums[u]);
            }
        }
        __syncwarp();
    }
}

// ---------------- layernorm + residual add (warp per row) ---------------------
// WHICH 0: out=g_x1, a=g_xa, base=param(x)
// WHICH 1: out=param(d_out), a=g_m, base=g_x1
template <int WHICH>
__global__ void __launch_bounds__(256) ln_kernel(const float* __restrict__ base_p,
                                                 const float* __restrict__ gw,
                                                 const float* __restrict__ bw,
                                                 float* __restrict__ out_p) {
    int gid = blockIdx.x * blockDim.x + threadIdx.x;
    int row = gid >> 5;
    int lane = gid & 31;
    if (row >= NROWS) return;
    const float* a = ((WHICH == 0) ? g_xa : g_m) + (size_t)row * CDIM;
    const float* bs = ((WHICH == 0) ? base_p : g_x1) + (size_t)row * CDIM;
    float* o = ((WHICH == 0) ? g_x1 : out_p) + (size_t)row * CDIM;
    float v[6];
    float s = 0.f, sq = 0.f;
#pragma unroll
    for (int u = 0; u < 6; ++u) {
        float t = a[lane + u * 32];
        v[u] = t;
        s += t;
        sq += t * t;
    }
#pragma unroll
    for (int off = 16; off; off >>= 1) {
        s += __shfl_xor_sync(FULLMASK, s, off);
        sq += __shfl_xor_sync(FULLMASK, sq, off);
    }
    float mean = s * (1.f / 192.f);
    float var = sq * (1.f / 192.f) - mean * mean;
    float inv = rsqrtf(var + 1e-5f);
#pragma unroll
    for (int u = 0; u < 6; ++u) {
        int c = lane + u * 32;
        o[c] = bs[c] + (v[u] - mean) * inv * gw[c] + bw[c];
    }
}

// ---------------- launch -------------------------------------------------------
extern "C" void kernel_launch(void* const* d_in, const int* in_sizes, int n_in,
                              void* d_out, int out_size) {
    (void)in_sizes; (void)n_in; (void)out_size;
    const float* x = (const float*)d_in[0];
    const float* qkv_w = (const float*)d_in[1];
    const float* q_bias = (const float*)d_in[2];
    const float* v_bias = (const float*)d_in[3];
    const float* logit_scale = (const float*)d_in[4];
    const float* cpb_w1 = (const float*)d_in[5];
    const float* cpb_b1 = (const float*)d_in[6];
    const float* cpb_w2 = (const float*)d_in[7];
    const float* proj_w = (const float*)d_in[8];
    const float* proj_b = (const float*)d_in[9];
    const float* norm1_g = (const float*)d_in[10];
    const float* norm1_b = (const float*)d_in[11];
    const float* fc1_w = (const float*)d_in[12];
    const float* fc1_b = (const float*)d_in[13];
    const float* fc2_w = (const float*)d_in[14];
    const float* fc2_b = (const float*)d_in[15];
    const float* norm2_g = (const float*)d_in[16];
    const float* norm2_b = (const float*)d_in[17];
    float* out = (float*)d_out;

    // constants
    cpb_kernel<<<2197, 256>>>(cpb_w1, cpb_b1, cpb_w2);
    rpb_kernel<<<864, 256>>>();

    // qkv (fused shift + window gather)
    gemm_tile<0><<<dim3(9, 6, 128), 256>>>(x, qkv_w, q_bias, v_bias, nullptr, 192, 576);

    // attention
    cudaFuncSetAttribute(attn_kernel, cudaFuncAttributeMaxDynamicSharedMemorySize,
                         ATTN_SMEM_BYTES);
    attn_kernel<<<768, 256, ATTN_SMEM_BYTES>>>(logit_scale);

    // proj (fused window reverse + roll scatter)
    gemm_tile<1><<<dim3(3, 6, 128), 256>>>(nullptr, proj_w, proj_b, nullptr, nullptr, 192, 192);

    // x1 = x + LN(xa)
    ln_kernel<0><<<5488, 256>>>(x, norm1_g, norm1_b, nullptr);

    // MLP
    gemm_tile<2><<<dim3(12, 686, 1), 256>>>(nullptr, fc1_w, fc1_b, nullptr, nullptr, 192, 768);
    gemm_tile<3><<<dim3(3, 686, 1), 256>>>(nullptr, fc2_w, fc2_b, nullptr, nullptr, 768, 192);

    // out = x1 + LN(m)
    ln_kernel<1><<<5488, 256>>>(nullptr, norm2_g, norm2_b, out);
}

// round 3
// speedup vs baseline: 1.5025x; 1.5025x over previous
#include <cuda_runtime.h>
#include <math.h>
#include <stdint.h>

#define FULLMASK 0xffffffffu

// problem dims
#define NTOK   343
#define NHEAD  6
#define HD     32
#define CDIM   192
#define LTOT   21952   // 28^3
#define NWIN   128     // 2 batches * 64 windows
#define NROWS  43904   // 128*343 = 2*21952

// ---------------- device scratch ------------------------------------------------
__device__ float g_hb[2197 * 6];
__device__ float g_rpb[6 * 343 * 343];
__device__ float g_q[(size_t)NWIN * NHEAD * NTOK * HD];
__device__ float g_k[(size_t)NWIN * NHEAD * NTOK * HD];
__device__ float g_v[(size_t)NWIN * NHEAD * NTOK * HD];
__device__ float g_attnout[(size_t)NWIN * NTOK * CDIM];
__device__ float g_xa[(size_t)2 * LTOT * CDIM];
__device__ float g_x1[(size_t)2 * LTOT * CDIM];
__device__ float g_m[(size_t)2 * LTOT * CDIM];
__device__ float g_hmid[(size_t)NROWS * 768];

// ---------------- helpers -------------------------------------------------------
__device__ __forceinline__ uint32_t f2tf32(float x) {
    uint32_t r;
    asm("cvt.rna.tf32.f32 %0, %1;" : "=r"(r) : "f"(x));
    return r;
}

__device__ __forceinline__ void mma_tf32(float* c, const uint32_t* a, const uint32_t* b) {
    asm volatile(
        "mma.sync.aligned.m16n8k8.row.col.f32.tf32.tf32.f32 "
        "{%0,%1,%2,%3}, {%4,%5,%6,%7}, {%8,%9}, {%0,%1,%2,%3};"
        : "+f"(c[0]), "+f"(c[1]), "+f"(c[2]), "+f"(c[3])
        : "r"(a[0]), "r"(a[1]), "r"(a[2]), "r"(a[3]), "r"(b[0]), "r"(b[1]));
}

// ---------------- CPB MLP -------------------------------------------------------
__device__ __forceinline__ float cpb_coord(int i) {
    float v = (float)(i - 6) * (8.0f / 6.0f);
    float av = fabsf(v);
    float r = log2f(av + 1.0f) * (1.0f / 3.0f);
    return (v < 0.f) ? -r : r;
}

__global__ void __launch_bounds__(256) cpb_kernel(const float* __restrict__ w1,
                                                  const float* __restrict__ b1,
                                                  const float* __restrict__ w2) {
    __shared__ float hid[512];
    int t = blockIdx.x;
    int a = t / 169;
    int rem = t - a * 169;
    int b = rem / 13;
    int c = rem - b * 13;
    float c0 = cpb_coord(a), c1 = cpb_coord(b), c2 = cpb_coord(c);
    for (int j = threadIdx.x; j < 512; j += blockDim.x) {
        float hv = c0 * w1[j * 3 + 0] + c1 * w1[j * 3 + 1] + c2 * w1[j * 3 + 2] + b1[j];
        hid[j] = fmaxf(hv, 0.f);
    }
    __syncthreads();
    if (threadIdx.x < 192) {
        int hh = threadIdx.x >> 5, lane = threadIdx.x & 31;
        float s = 0.f;
        for (int j = lane; j < 512; j += 32) s += hid[j] * w2[hh * 512 + j];
#pragma unroll
        for (int off = 16; off; off >>= 1) s += __shfl_xor_sync(FULLMASK, s, off);
        if (lane == 0) g_hb[t * 6 + hh] = s;
    }
}

__global__ void rpb_kernel() {
    const int total = 6 * 343 * 343;
    for (int idx = blockIdx.x * blockDim.x + threadIdx.x; idx < total;
         idx += gridDim.x * blockDim.x) {
        int hh = idx / 117649;
        int rem = idx - hh * 117649;
        int i = rem / 343;
        int j = rem - i * 343;
        int dh = i / 49 - j / 49 + 6;
        int dw = (i / 7) % 7 - (j / 7) % 7 + 6;
        int dd = i % 7 - j % 7 + 6;
        int tix = (dh * 13 + dw) * 13 + dd;
        float v = g_hb[tix * 6 + hh];
        g_rpb[idx] = 16.f / (1.f + __expf(-v));
    }
}

// ---------------- tf32 mma.sync GEMM --------------------------------------------
// C[M x N] = A[M x K] * W[N x K]^T, BM=128 BN=96 BK=16, 256 threads, 8 warps 4Mx2N
// MODE 0: QKV (A gathered from x via shift+window; out -> g_q/g_k/g_v + biases)
// MODE 1: PROJ (A=g_attnout; out -> g_xa scattered via window-reverse+roll)
// MODE 2: FC1 (A=g_x1 -> g_hmid with exact GELU)
// MODE 3: FC2 (A=g_hmid -> g_m)
#define BM 128
#define BN 96
#define BK 16
#define SPAD 20

template <int MODE>
__global__ void __launch_bounds__(256) mma_gemm(const float* __restrict__ A,
                                                const float* __restrict__ W,
                                                const float* __restrict__ bias1,
                                                const float* __restrict__ bias2,
                                                int K) {
    __shared__ __align__(16) uint32_t As[BM * SPAD];
    __shared__ __align__(16) uint32_t Bs[BN * SPAD];

    const int tid = threadIdx.x;
    const int lane = tid & 31;
    const int warp = tid >> 5;
    const int warpM = warp & 3;       // 0..3
    const int warpN = warp >> 2;      // 0..1
    const int gr = lane >> 2;         // group id 0..7
    const int tg = lane & 3;          // thread in group

    const int m0 = blockIdx.y * BM;
    const int n0 = blockIdx.x * BN;

    const float* Asrc;
    if (MODE == 0) Asrc = A;
    else if (MODE == 1) Asrc = g_attnout;
    else if (MODE == 2) Asrc = g_x1;
    else Asrc = g_hmid;

    // A global pointers: 2 rows/thread (row = idx>>2, col4 = tid&3, same both halves)
    const int acol4 = tid & 3;
    const float* aptr[2];
    int arowv[2];
#pragma unroll
    for (int i = 0; i < 2; ++i) {
        int idx = tid + i * 256;
        int arow = idx >> 2;
        arowv[i] = arow;
        int rho = m0 + arow;
        const float* p;
        if (MODE == 0) {
            int b_ = rho / 343, n = rho - b_ * 343;
            int bb = b_ >> 6, win = b_ & 63;
            int wa = win >> 4, wb = (win >> 2) & 3, wc = win & 3;
            int ii = n / 49, jj = (n / 7) % 7, kk = n % 7;
            int hs = (wa * 7 + ii + 3) % 28;
            int ws = (wb * 7 + jj + 3) % 28;
            int ds = (wc * 7 + kk + 3) % 28;
            p = Asrc + ((size_t)bb * LTOT + (hs * 784 + ws * 28 + ds)) * CDIM;
        } else {
            p = Asrc + (size_t)rho * K;
        }
        aptr[i] = p + acol4 * 4;
    }

    float acc[2][6][4];
#pragma unroll
    for (int mi = 0; mi < 2; ++mi)
#pragma unroll
        for (int ni = 0; ni < 6; ++ni)
#pragma unroll
            for (int e = 0; e < 4; ++e) acc[mi][ni][e] = 0.f;

    for (int kt = 0; kt < K; kt += BK) {
        float4 av[2];
#pragma unroll
        for (int i = 0; i < 2; ++i) av[i] = *(const float4*)(aptr[i] + kt);
        float4 bv[2];
        int bcnt = 0;
        for (int i = tid; i < BN * 4; i += 256) {
            int brow = i >> 2, bc4 = i & 3;
            bv[bcnt++] = *(const float4*)(W + (size_t)(n0 + brow) * K + kt + bc4 * 4);
        }
        __syncthreads();
#pragma unroll
        for (int i = 0; i < 2; ++i) {
            uint4 u;
            u.x = f2tf32(av[i].x);
            u.y = f2tf32(av[i].y);
            u.z = f2tf32(av[i].z);
            u.w = f2tf32(av[i].w);
            *(uint4*)&As[arowv[i] * SPAD + acol4 * 4] = u;
        }
        bcnt = 0;
        for (int i = tid; i < BN * 4; i += 256) {
            int brow = i >> 2, bc4 = i & 3;
            uint4 u;
            u.x = f2tf32(bv[bcnt].x);
            u.y = f2tf32(bv[bcnt].y);
            u.z = f2tf32(bv[bcnt].z);
            u.w = f2tf32(bv[bcnt].w);
            bcnt++;
            *(uint4*)&Bs[brow * SPAD + bc4 * 4] = u;
        }
        __syncthreads();

#pragma unroll
        for (int kk = 0; kk < 16; kk += 8) {
            uint32_t afr[2][4];
#pragma unroll
            for (int mi = 0; mi < 2; ++mi) {
                int rb = warpM * 32 + mi * 16;
                afr[mi][0] = As[(rb + gr) * SPAD + kk + tg];
                afr[mi][1] = As[(rb + gr + 8) * SPAD + kk + tg];
                afr[mi][2] = As[(rb + gr) * SPAD + kk + tg + 4];
                afr[mi][3] = As[(rb + gr + 8) * SPAD + kk + tg + 4];
            }
            uint32_t bfr[6][2];
#pragma unroll
            for (int ni = 0; ni < 6; ++ni) {
                int nb = warpN * 48 + ni * 8 + gr;
                bfr[ni][0] = Bs[nb * SPAD + kk + tg];
                bfr[ni][1] = Bs[nb * SPAD + kk + tg + 4];
            }
#pragma unroll
            for (int mi = 0; mi < 2; ++mi)
#pragma unroll
                for (int ni = 0; ni < 6; ++ni)
                    mma_tf32(acc[mi][ni], afr[mi], bfr[ni]);
        }
    }

    // ---------------- epilogue ----------------------------------------------------
#pragma unroll
    for (int mi = 0; mi < 2; ++mi) {
        int rows[2];
        rows[0] = m0 + warpM * 32 + mi * 16 + gr;
        rows[1] = rows[0] + 8;
#pragma unroll
        for (int half = 0; half < 2; ++half) {
            const int r = rows[half];
            int b_ = 0, n = 0;
            size_t scat = 0;
            if (MODE == 0 || MODE == 1) {
                b_ = r / 343;
                n = r - b_ * 343;
            }
            if (MODE == 1) {
                int bb2 = b_ >> 6, win = b_ & 63;
                int wa = win >> 4, wb = (win >> 2) & 3, wc = win & 3;
                int i3 = n / 49, j3 = (n / 7) % 7, k3 = n % 7;
                int hd_ = (wa * 7 + i3 + 3) % 28;
                int wd_ = (wb * 7 + j3 + 3) % 28;
                int dd_ = (wc * 7 + k3 + 3) % 28;
                scat = ((size_t)bb2 * LTOT + (hd_ * 784 + wd_ * 28 + dd_)) * CDIM;
            }
#pragma unroll
            for (int ni = 0; ni < 6; ++ni) {
                int c = n0 + warpN * 48 + ni * 8 + tg * 2;
                float v0 = acc[mi][ni][half * 2 + 0];
                float v1 = acc[mi][ni][half * 2 + 1];
                if (MODE == 0) {
                    int sct = c / 192;
                    int remc = c - sct * 192;
                    int hh = remc >> 5, dd = remc & 31;
                    float* dst = (sct == 0 ? g_q : (sct == 1 ? g_k : g_v)) +
                                 ((size_t)(b_ * 6 + hh) * NTOK + n) * HD + dd;
                    float e0 = 0.f, e1 = 0.f;
                    if (sct == 0) { e0 = bias1[remc]; e1 = bias1[remc + 1]; }
                    else if (sct == 2) { e0 = bias2[remc]; e1 = bias2[remc + 1]; }
                    *(float2*)dst = make_float2(v0 + e0, v1 + e1);
                } else if (MODE == 1) {
                    *(float2*)(g_xa + scat + c) =
                        make_float2(v0 + bias1[c], v1 + bias1[c + 1]);
                } else if (MODE == 2) {
                    float x0 = v0 + bias1[c], x1 = v1 + bias1[c + 1];
                    float g0 = 0.5f * x0 * (1.f + erff(x0 * 0.70710678118654752f));
                    float g1 = 0.5f * x1 * (1.f + erff(x1 * 0.70710678118654752f));
                    *(float2*)(g_hmid + (size_t)r * 768 + c) = make_float2(g0, g1);
                } else {
                    *(float2*)(g_m + (size_t)r * 192 + c) =
                        make_float2(v0 + bias1[c], v1 + bias1[c + 1]);
                }
            }
        }
    }
}

// ---------------- attention (round-1, known correct) -----------------------------
#define ATTN_SMEM_FLOATS (343 * 33 + 343 * 32 + 8 * 4 * 344)
#define ATTN_SMEM_BYTES (ATTN_SMEM_FLOATS * 4 + 384)

__global__ void __launch_bounds__(256) attn_kernel(const float* __restrict__ logit_scale) {
    extern __shared__ float sm[];
    float* Ks = sm;
    float* Vs = Ks + 343 * 33;
    float* Ps = Vs + 343 * 32;
    unsigned char* region = (unsigned char*)(Ps + 8 * 4 * 344);

    const int bh = blockIdx.x;
    const int b_ = bh / 6, h = bh - (bh / 6) * 6;
    const int tid = threadIdx.x;
    const int lane = tid & 31, w = tid >> 5;

    const size_t kvbase = (size_t)bh * (NTOK * HD);
    const float* kg = g_k + kvbase;
    const float* vg = g_v + kvbase;

    for (int idx = tid; idx < NTOK * HD; idx += 256) {
        int r = idx >> 5, d = idx & 31;
        Ks[r * 33 + d] = kg[idx];
        Vs[idx] = vg[idx];
    }
    {
        int win = b_ & 63;
        int wa = win >> 4, wb = (win >> 2) & 3, wc = win & 3;
        for (int t = tid; t < NTOK; t += 256) {
            int ih = t / 49, iw = (t / 7) % 7, id = t % 7;
            int rH = (wa < 3) ? 0 : ((ih < 4) ? 1 : 2);
            int rW = (wb < 3) ? 0 : ((iw < 4) ? 1 : 2);
            int rD = (wc < 3) ? 0 : ((id < 4) ? 1 : 2);
            region[t] = (unsigned char)(rH * 9 + rW * 3 + rD);
        }
    }
    __syncthreads();
    for (int r = tid; r < NTOK; r += 256) {
        float s = 0.f;
#pragma unroll
        for (int d = 0; d < 32; ++d) { float vv = Ks[r * 33 + d]; s += vv * vv; }
        float inv = 1.f / fmaxf(sqrtf(s), 1e-12f);
#pragma unroll
        for (int d = 0; d < 32; ++d) Ks[r * 33 + d] *= inv;
    }
    __syncthreads();

    const float scale = __expf(fminf(logit_scale[h], 4.6051701859880914f));
    const float* rpbh = g_rpb + (size_t)h * 343 * 343;
    float* Pw = Ps + w * 4 * 344;

    for (int g = w; g * 4 < NTOK; g += 8) {
        const int r0 = g * 4;
        float qv[4];
#pragma unroll
        for (int u = 0; u < 4; ++u) {
            int r = r0 + u;
            qv[u] = (r < NTOK) ? g_q[kvbase + (size_t)r * HD + lane] : 0.f;
        }
#pragma unroll
        for (int u = 0; u < 4; ++u) {
            float s = qv[u] * qv[u];
#pragma unroll
            for (int off = 16; off; off >>= 1) s += __shfl_xor_sync(FULLMASK, s, off);
            float inv = scale / fmaxf(sqrtf(s), 1e-12f);
            qv[u] *= inv;
        }
        unsigned char regq[4];
#pragma unroll
        for (int u = 0; u < 4; ++u) {
            int r = r0 + u;
            regq[u] = region[(r < NTOK) ? r : (NTOK - 1)];
        }
        float mx[4] = {-1e30f, -1e30f, -1e30f, -1e30f};

        for (int t = 0; t < 11; ++t) {
            int jj = t * 32 + lane;
            bool valid = jj < NTOK;
            const float* kp = Ks + (valid ? jj : (NTOK - 1)) * 33;
            float a0 = 0.f, a1 = 0.f, a2 = 0.f, a3 = 0.f;
#pragma unroll
            for (int d = 0; d < 32; ++d) {
                float kd = kp[d];
                a0 += __shfl_sync(FULLMASK, qv[0], d) * kd;
                a1 += __shfl_sync(FULLMASK, qv[1], d) * kd;
                a2 += __shfl_sync(FULLMASK, qv[2], d) * kd;
                a3 += __shfl_sync(FULLMASK, qv[3], d) * kd;
            }
            float accs[4] = {a0, a1, a2, a3};
            unsigned char regk = region[valid ? jj : 0];
#pragma unroll
            for (int u = 0; u < 4; ++u) {
                int r = r0 + u;
                if (valid && r < NTOK) {
                    float s = accs[u] + rpbh[(size_t)r * 343 + jj];
                    if (regq[u] != regk) s -= 100.f;
                    Pw[u * 344 + jj] = s;
                    mx[u] = fmaxf(mx[u], s);
                }
            }
        }
#pragma unroll
        for (int u = 0; u < 4; ++u)
#pragma unroll
            for (int off = 16; off; off >>= 1)
                mx[u] = fmaxf(mx[u], __shfl_xor_sync(FULLMASK, mx[u], off));

        float sums[4] = {0.f, 0.f, 0.f, 0.f};
        for (int t = 0; t < 11; ++t) {
            int jj = t * 32 + lane;
            if (jj < NTOK) {
#pragma unroll
                for (int u = 0; u < 4; ++u) {
                    int r = r0 + u;
                    if (r < NTOK) {
                        float p = __expf(Pw[u * 344 + jj] - mx[u]);
                        Pw[u * 344 + jj] = p;
                        sums[u] += p;
                    }
                }
            }
        }
#pragma unroll
        for (int u = 0; u < 4; ++u)
#pragma unroll
            for (int off = 16; off; off >>= 1)
                sums[u] += __shfl_xor_sync(FULLMASK, sums[u], off);

        __syncwarp();
        float o0 = 0.f, o1 = 0.f, o2 = 0.f, o3 = 0.f;
        for (int j = 0; j < NTOK; ++j) {
            float vv = Vs[j * 32 + lane];
            o0 += Pw[0 * 344 + j] * vv;
            o1 += Pw[1 * 344 + j] * vv;
            o2 += Pw[2 * 344 + j] * vv;
            o3 += Pw[3 * 344 + j] * vv;
        }
        float outs[4] = {o0, o1, o2, o3};
#pragma unroll
        for (int u = 0; u < 4; ++u) {
            int r = r0 + u;
            if (r < NTOK) {
                g_attnout[((size_t)b_ * NTOK + r) * CDIM + h * HD + lane] =
                    outs[u] * (1.f / sums[u]);
            }
        }
        __syncwarp();
    }
}

// ---------------- layernorm + residual ------------------------------------------
template <int WHICH>
__global__ void __launch_bounds__(256) ln_kernel(const float* __restrict__ base_p,
                                                 const float* __restrict__ gw,
                                                 const float* __restrict__ bw,
                                                 float* __restrict__ out_p) {
    int gid = blockIdx.x * blockDim.x + threadIdx.x;
    int row = gid >> 5;
    int lane = gid & 31;
    if (row >= NROWS) return;
    const float* a = ((WHICH == 0) ? g_xa : g_m) + (size_t)row * CDIM;
    const float* bs = ((WHICH == 0) ? base_p : g_x1) + (size_t)row * CDIM;
    float* o = ((WHICH == 0) ? g_x1 : out_p) + (size_t)row * CDIM;
    float v[6];
    float s = 0.f, sq = 0.f;
#pragma unroll
    for (int u = 0; u < 6; ++u) {
        float t = a[lane + u * 32];
        v[u] = t;
        s += t;
        sq += t * t;
    }
#pragma unroll
    for (int off = 16; off; off >>= 1) {
        s += __shfl_xor_sync(FULLMASK, s, off);
        sq += __shfl_xor_sync(FULLMASK, sq, off);
    }
    float mean = s * (1.f / 192.f);
    float var = sq * (1.f / 192.f) - mean * mean;
    float inv = rsqrtf(var + 1e-5f);
#pragma unroll
    for (int u = 0; u < 6; ++u) {
        int c = lane + u * 32;
        o[c] = bs[c] + (v[u] - mean) * inv * gw[c] + bw[c];
    }
}

// ---------------- launch ---------------------------------------------------------
extern "C" void kernel_launch(void* const* d_in, const int* in_sizes, int n_in,
                              void* d_out, int out_size) {
    (void)in_sizes; (void)n_in; (void)out_size;
    const float* x = (const float*)d_in[0];
    const float* qkv_w = (const float*)d_in[1];
    const float* q_bias = (const float*)d_in[2];
    const float* v_bias = (const float*)d_in[3];
    const float* logit_scale = (const float*)d_in[4];
    const float* cpb_w1 = (const float*)d_in[5];
    const float* cpb_b1 = (const float*)d_in[6];
    const float* cpb_w2 = (const float*)d_in[7];
    const float* proj_w = (const float*)d_in[8];
    const float* proj_b = (const float*)d_in[9];
    const float* norm1_g = (const float*)d_in[10];
    const float* norm1_b = (const float*)d_in[11];
    const float* fc1_w = (const float*)d_in[12];
    const float* fc1_b = (const float*)d_in[13];
    const float* fc2_w = (const float*)d_in[14];
    const float* fc2_b = (const float*)d_in[15];
    const float* norm2_g = (const float*)d_in[16];
    const float* norm2_b = (const float*)d_in[17];
    float* out = (float*)d_out;

    static bool attr_done = false;
    if (!attr_done) {
        cudaFuncSetAttribute(attn_kernel, cudaFuncAttributeMaxDynamicSharedMemorySize,
                             ATTN_SMEM_BYTES);
        attr_done = true;
    }

    // constants
    cpb_kernel<<<2197, 256>>>(cpb_w1, cpb_b1, cpb_w2);
    rpb_kernel<<<864, 256>>>();

    // qkv (fused shift + window gather): M=43904, N=576, K=192
    mma_gemm<0><<<dim3(6, 343), 256>>>(x, qkv_w, q_bias, v_bias, 192);

    // attention
    attn_kernel<<<768, 256, ATTN_SMEM_BYTES>>>(logit_scale);

    // proj (fused window reverse + roll scatter): N=192, K=192
    mma_gemm<1><<<dim3(2, 343), 256>>>(nullptr, proj_w, proj_b, nullptr, 192);

    // x1 = x + LN(xa)
    ln_kernel<0><<<5488, 256>>>(x, norm1_g, norm1_b, nullptr);

    // MLP: fc1 N=768 K=192 (GELU), fc2 N=192 K=768
    mma_gemm<2><<<dim3(8, 343), 256>>>(nullptr, fc1_w, fc1_b, nullptr, 192);
    mma_gemm<3><<<dim3(2, 343), 256>>>(nullptr, fc2_w, fc2_b, nullptr, 768);

    // out = x1 + LN(m)
    ln_kernel<1><<<5488, 256>>>(nullptr, norm2_g, norm2_b, out);
}

// round 4
// speedup vs baseline: 1.8578x; 1.2365x over previous
#include <cuda_runtime.h>
#include <math.h>
#include <stdint.h>

#define FULLMASK 0xffffffffu

// problem dims
#define NTOK   343
#define NHEAD  6
#define HD     32
#define CDIM   192
#define LTOT   21952   // 28^3
#define NWIN   128     // 2 batches * 64 windows
#define NROWS  43904   // 128*343 = 2*21952

// ---------------- device scratch ------------------------------------------------
__device__ float g_hb[2197 * 6];
__device__ float g_rpb[6 * 343 * 343];
__device__ float g_q[(size_t)NWIN * NHEAD * NTOK * HD];
__device__ float g_k[(size_t)NWIN * NHEAD * NTOK * HD];
__device__ float g_v[(size_t)NWIN * NHEAD * NTOK * HD];
__device__ float g_attnout[(size_t)NWIN * NTOK * CDIM];
__device__ float g_xa[(size_t)2 * LTOT * CDIM];
__device__ float g_x1[(size_t)2 * LTOT * CDIM];
__device__ float g_m[(size_t)2 * LTOT * CDIM];
__device__ float g_hmid[(size_t)NROWS * 768];

// ---------------- helpers -------------------------------------------------------
__device__ __forceinline__ uint32_t f2tf32(float x) {
    uint32_t r;
    asm("cvt.rna.tf32.f32 %0, %1;" : "=r"(r) : "f"(x));
    return r;
}

__device__ __forceinline__ void mma_tf32(float* c, const uint32_t* a, const uint32_t* b) {
    asm volatile(
        "mma.sync.aligned.m16n8k8.row.col.f32.tf32.tf32.f32 "
        "{%0,%1,%2,%3}, {%4,%5,%6,%7}, {%8,%9}, {%0,%1,%2,%3};"
        : "+f"(c[0]), "+f"(c[1]), "+f"(c[2]), "+f"(c[3])
        : "r"(a[0]), "r"(a[1]), "r"(a[2]), "r"(a[3]), "r"(b[0]), "r"(b[1]));
}

// ---------------- CPB MLP -------------------------------------------------------
__device__ __forceinline__ float cpb_coord(int i) {
    float v = (float)(i - 6) * (8.0f / 6.0f);
    float av = fabsf(v);
    float r = log2f(av + 1.0f) * (1.0f / 3.0f);
    return (v < 0.f) ? -r : r;
}

__global__ void __launch_bounds__(256) cpb_kernel(const float* __restrict__ w1,
                                                  const float* __restrict__ b1,
                                                  const float* __restrict__ w2) {
    __shared__ float hid[512];
    int t = blockIdx.x;
    int a = t / 169;
    int rem = t - a * 169;
    int b = rem / 13;
    int c = rem - b * 13;
    float c0 = cpb_coord(a), c1 = cpb_coord(b), c2 = cpb_coord(c);
    for (int j = threadIdx.x; j < 512; j += blockDim.x) {
        float hv = c0 * w1[j * 3 + 0] + c1 * w1[j * 3 + 1] + c2 * w1[j * 3 + 2] + b1[j];
        hid[j] = fmaxf(hv, 0.f);
    }
    __syncthreads();
    if (threadIdx.x < 192) {
        int hh = threadIdx.x >> 5, lane = threadIdx.x & 31;
        float s = 0.f;
        for (int j = lane; j < 512; j += 32) s += hid[j] * w2[hh * 512 + j];
#pragma unroll
        for (int off = 16; off; off >>= 1) s += __shfl_xor_sync(FULLMASK, s, off);
        if (lane == 0) g_hb[t * 6 + hh] = s;
    }
}

__global__ void rpb_kernel() {
    const int total = 6 * 343 * 343;
    for (int idx = blockIdx.x * blockDim.x + threadIdx.x; idx < total;
         idx += gridDim.x * blockDim.x) {
        int hh = idx / 117649;
        int rem = idx - hh * 117649;
        int i = rem / 343;
        int j = rem - i * 343;
        int dh = i / 49 - j / 49 + 6;
        int dw = (i / 7) % 7 - (j / 7) % 7 + 6;
        int dd = i % 7 - j % 7 + 6;
        int tix = (dh * 13 + dw) * 13 + dd;
        float v = g_hb[tix * 6 + hh];
        g_rpb[idx] = 16.f / (1.f + __expf(-v));
    }
}

// ---------------- tf32 mma.sync GEMM with register prefetch ----------------------
#define BM 128
#define BN 96
#define BK 16
#define SPAD 20

template <int MODE>
__global__ void __launch_bounds__(256) mma_gemm(const float* __restrict__ A,
                                                const float* __restrict__ W,
                                                const float* __restrict__ bias1,
                                                const float* __restrict__ bias2,
                                                int K) {
    __shared__ __align__(16) uint32_t As[BM * SPAD];
    __shared__ __align__(16) uint32_t Bs[BN * SPAD];

    const int tid = threadIdx.x;
    const int lane = tid & 31;
    const int warp = tid >> 5;
    const int warpM = warp & 3;
    const int warpN = warp >> 2;
    const int gr = lane >> 2;
    const int tg = lane & 3;

    const int m0 = blockIdx.y * BM;
    const int n0 = blockIdx.x * BN;

    const float* Asrc;
    if (MODE == 0) Asrc = A;
    else if (MODE == 1) Asrc = g_attnout;
    else if (MODE == 2) Asrc = g_x1;
    else Asrc = g_hmid;

    const int acol4 = tid & 3;
    const float* aptr[2];
    int arowv[2];
#pragma unroll
    for (int i = 0; i < 2; ++i) {
        int idx = tid + i * 256;
        int arow = idx >> 2;
        arowv[i] = arow;
        int rho = m0 + arow;
        const float* p;
        if (MODE == 0) {
            int b_ = rho / 343, n = rho - b_ * 343;
            int bb = b_ >> 6, win = b_ & 63;
            int wa = win >> 4, wb = (win >> 2) & 3, wc = win & 3;
            int ii = n / 49, jj = (n / 7) % 7, kk = n % 7;
            int hs = (wa * 7 + ii + 3) % 28;
            int ws = (wb * 7 + jj + 3) % 28;
            int ds = (wc * 7 + kk + 3) % 28;
            p = Asrc + ((size_t)bb * LTOT + (hs * 784 + ws * 28 + ds)) * CDIM;
        } else {
            p = Asrc + (size_t)rho * K;
        }
        aptr[i] = p + acol4 * 4;
    }
    // B: slot0 = tid (<384), slot1 = tid+256 (valid iff tid<128)
    const int brow0 = tid >> 2, bc40 = tid & 3;
    const int brow1 = (tid + 256) >> 2, bc41 = tid & 3;
    const float* bptr0 = W + (size_t)(n0 + brow0) * K + bc40 * 4;
    const float* bptr1 = W + (size_t)(n0 + brow1) * K + bc41 * 4;
    const bool bhas1 = (tid < 128);

    float acc[2][6][4];
#pragma unroll
    for (int mi = 0; mi < 2; ++mi)
#pragma unroll
        for (int ni = 0; ni < 6; ++ni)
#pragma unroll
            for (int e = 0; e < 4; ++e) acc[mi][ni][e] = 0.f;

    float4 av[2], bv[2];
    av[0] = *(const float4*)(aptr[0]);
    av[1] = *(const float4*)(aptr[1]);
    bv[0] = *(const float4*)(bptr0);
    if (bhas1) bv[1] = *(const float4*)(bptr1);

    for (int kt = 0; kt < K; kt += BK) {
        __syncthreads();
#pragma unroll
        for (int i = 0; i < 2; ++i) {
            uint4 u;
            u.x = f2tf32(av[i].x);
            u.y = f2tf32(av[i].y);
            u.z = f2tf32(av[i].z);
            u.w = f2tf32(av[i].w);
            *(uint4*)&As[arowv[i] * SPAD + acol4 * 4] = u;
        }
        {
            uint4 u;
            u.x = f2tf32(bv[0].x);
            u.y = f2tf32(bv[0].y);
            u.z = f2tf32(bv[0].z);
            u.w = f2tf32(bv[0].w);
            *(uint4*)&Bs[brow0 * SPAD + bc40 * 4] = u;
            if (bhas1) {
                uint4 v;
                v.x = f2tf32(bv[1].x);
                v.y = f2tf32(bv[1].y);
                v.z = f2tf32(bv[1].z);
                v.w = f2tf32(bv[1].w);
                *(uint4*)&Bs[brow1 * SPAD + bc41 * 4] = v;
            }
        }
        __syncthreads();
        // prefetch next tile (overlaps with mma below)
        if (kt + BK < K) {
            av[0] = *(const float4*)(aptr[0] + kt + BK);
            av[1] = *(const float4*)(aptr[1] + kt + BK);
            bv[0] = *(const float4*)(bptr0 + kt + BK);
            if (bhas1) bv[1] = *(const float4*)(bptr1 + kt + BK);
        }

#pragma unroll
        for (int kk = 0; kk < 16; kk += 8) {
            uint32_t afr[2][4];
#pragma unroll
            for (int mi = 0; mi < 2; ++mi) {
                int rb = warpM * 32 + mi * 16;
                afr[mi][0] = As[(rb + gr) * SPAD + kk + tg];
                afr[mi][1] = As[(rb + gr + 8) * SPAD + kk + tg];
                afr[mi][2] = As[(rb + gr) * SPAD + kk + tg + 4];
                afr[mi][3] = As[(rb + gr + 8) * SPAD + kk + tg + 4];
            }
            uint32_t bfr[6][2];
#pragma unroll
            for (int ni = 0; ni < 6; ++ni) {
                int nb = warpN * 48 + ni * 8 + gr;
                bfr[ni][0] = Bs[nb * SPAD + kk + tg];
                bfr[ni][1] = Bs[nb * SPAD + kk + tg + 4];
            }
#pragma unroll
            for (int mi = 0; mi < 2; ++mi)
#pragma unroll
                for (int ni = 0; ni < 6; ++ni)
                    mma_tf32(acc[mi][ni], afr[mi], bfr[ni]);
        }
    }

    // ---------------- epilogue ----------------------------------------------------
#pragma unroll
    for (int mi = 0; mi < 2; ++mi) {
        int rows[2];
        rows[0] = m0 + warpM * 32 + mi * 16 + gr;
        rows[1] = rows[0] + 8;
#pragma unroll
        for (int half = 0; half < 2; ++half) {
            const int r = rows[half];
            int b_ = 0, n = 0;
            size_t scat = 0;
            if (MODE == 0 || MODE == 1) {
                b_ = r / 343;
                n = r - b_ * 343;
            }
            if (MODE == 1) {
                int bb2 = b_ >> 6, win = b_ & 63;
                int wa = win >> 4, wb = (win >> 2) & 3, wc = win & 3;
                int i3 = n / 49, j3 = (n / 7) % 7, k3 = n % 7;
                int hd_ = (wa * 7 + i3 + 3) % 28;
                int wd_ = (wb * 7 + j3 + 3) % 28;
                int dd_ = (wc * 7 + k3 + 3) % 28;
                scat = ((size_t)bb2 * LTOT + (hd_ * 784 + wd_ * 28 + dd_)) * CDIM;
            }
#pragma unroll
            for (int ni = 0; ni < 6; ++ni) {
                int c = n0 + warpN * 48 + ni * 8 + tg * 2;
                float v0 = acc[mi][ni][half * 2 + 0];
                float v1 = acc[mi][ni][half * 2 + 1];
                if (MODE == 0) {
                    int sct = c / 192;
                    int remc = c - sct * 192;
                    int hh = remc >> 5, dd = remc & 31;
                    float* dst = (sct == 0 ? g_q : (sct == 1 ? g_k : g_v)) +
                                 ((size_t)(b_ * 6 + hh) * NTOK + n) * HD + dd;
                    float e0 = 0.f, e1 = 0.f;
                    if (sct == 0) { e0 = bias1[remc]; e1 = bias1[remc + 1]; }
                    else if (sct == 2) { e0 = bias2[remc]; e1 = bias2[remc + 1]; }
                    *(float2*)dst = make_float2(v0 + e0, v1 + e1);
                } else if (MODE == 1) {
                    *(float2*)(g_xa + scat + c) =
                        make_float2(v0 + bias1[c], v1 + bias1[c + 1]);
                } else if (MODE == 2) {
                    float x0 = v0 + bias1[c], x1 = v1 + bias1[c + 1];
                    float g0 = 0.5f * x0 * (1.f + erff(x0 * 0.70710678118654752f));
                    float g1 = 0.5f * x1 * (1.f + erff(x1 * 0.70710678118654752f));
                    *(float2*)(g_hmid + (size_t)r * 768 + c) = make_float2(g0, g1);
                } else {
                    *(float2*)(g_m + (size_t)r * 192 + c) =
                        make_float2(v0 + bias1[c], v1 + bias1[c + 1]);
                }
            }
        }
    }
}

// ---------------- tensor-core flash attention ------------------------------------
// one block per (window, head). 256 threads = 8 warps. rows: 3 row-blocks x 8 warps
// x 16 rows = 384 (343 valid). KV chunks of 64 (6 chunks over 384, 343 valid).
#define KS_WORDS (384 * 36)
#define VT_WORDS (32 * 388)
#define PS_WORDS (8 * 16 * 68)
#define ATTN2_SMEM ((KS_WORDS + VT_WORDS + PS_WORDS) * 4 + 512)

__global__ void __launch_bounds__(256) attn2_kernel(const float* __restrict__ logit_scale) {
    extern __shared__ uint32_t asmem[];
    uint32_t* Ks = asmem;                       // [384][36] tf32 normalized K
    uint32_t* Vt = asmem + KS_WORDS;            // [32][388] tf32 V transposed
    uint32_t* Ps = Vt + VT_WORDS;               // per-warp [16][68]
    unsigned char* region = (unsigned char*)(Ps + PS_WORDS);

    const int bh = blockIdx.x;
    const int b_ = bh / 6, h = bh - (bh / 6) * 6;
    const int tid = threadIdx.x;
    const int lane = tid & 31, warp = tid >> 5;
    const int gr = lane >> 2, tg = lane & 3;

    const size_t kvbase = (size_t)bh * (NTOK * HD);
    const float* kg = g_k + kvbase;
    const float* vg = g_v + kvbase;
    const float* qg = g_q + kvbase;

    // K: normalize rows -> tf32 smem (warp per row)
    for (int r = warp; r < 384; r += 8) {
        if (r < NTOK) {
            float v = kg[r * 32 + lane];
            float s = v * v;
#pragma unroll
            for (int o = 16; o; o >>= 1) s += __shfl_xor_sync(FULLMASK, s, o);
            float inv = 1.f / fmaxf(sqrtf(s), 1e-12f);
            Ks[r * 36 + lane] = f2tf32(v * inv);
        } else {
            Ks[r * 36 + lane] = 0u;
        }
    }
    // V transposed -> tf32 smem
    for (int idx = tid; idx < NTOK * 32; idx += 256) {
        int j = idx >> 5, d = idx & 31;
        Vt[d * 388 + j] = f2tf32(vg[idx]);
    }
    for (int idx = tid; idx < 32 * 45; idx += 256) {   // zero cols 343..387
        int d = idx / 45, j = NTOK + idx - (idx / 45) * 45;
        Vt[d * 388 + j] = 0u;
    }
    // region ids
    {
        int win = b_ & 63;
        int wa = win >> 4, wb = (win >> 2) & 3, wc = win & 3;
        for (int t = tid; t < NTOK; t += 256) {
            int ih = t / 49, iw = (t / 7) % 7, id = t % 7;
            int rH = (wa < 3) ? 0 : ((ih < 4) ? 1 : 2);
            int rW = (wb < 3) ? 0 : ((iw < 4) ? 1 : 2);
            int rD = (wc < 3) ? 0 : ((id < 4) ? 1 : 2);
            region[t] = (unsigned char)(rH * 9 + rW * 3 + rD);
        }
    }
    __syncthreads();

    const float scale = __expf(fminf(logit_scale[h], 4.6051701859880914f));
    const float* rpbh = g_rpb + (size_t)h * (343 * 343);
    uint32_t* Pw = Ps + warp * (16 * 68);
    float* Qst = (float*)Pw;   // staging area (reused by P later)

    for (int rb = 0; rb < 3; ++rb) {
        const int r0 = rb * 128 + warp * 16;
        if (r0 >= NTOK) continue;   // whole warp-tile invalid (no barriers below)

        // stage Q rows r0..r0+15 (fp32), coalesced
        for (int i = lane; i < 16 * 32; i += 32) {
            int r = i >> 5, d = i & 31;
            int grow = r0 + r;
            Qst[r * 33 + d] = (grow < NTOK) ? qg[(size_t)grow * 32 + d] : 0.f;
        }
        __syncwarp();
        // per-row 1/norm * scale
        {
            int r = lane >> 1, hf = lane & 1;
            float s = 0.f;
#pragma unroll
            for (int d = 0; d < 16; ++d) {
                float v = Qst[r * 33 + hf * 16 + d];
                s += v * v;
            }
            s += __shfl_xor_sync(FULLMASK, s, 1);
            if (hf == 0) Qst[r * 33 + 32] = scale / fmaxf(sqrtf(s), 1e-12f);
        }
        __syncwarp();
        // build Q A-frags in registers
        uint32_t aQ[4][4];
        {
            float i0 = Qst[gr * 33 + 32], i1 = Qst[(gr + 8) * 33 + 32];
#pragma unroll
            for (int kk = 0; kk < 4; ++kk) {
                aQ[kk][0] = f2tf32(Qst[gr * 33 + kk * 8 + tg] * i0);
                aQ[kk][1] = f2tf32(Qst[(gr + 8) * 33 + kk * 8 + tg] * i1);
                aQ[kk][2] = f2tf32(Qst[gr * 33 + kk * 8 + tg + 4] * i0);
                aQ[kk][3] = f2tf32(Qst[(gr + 8) * 33 + kk * 8 + tg + 4] * i1);
            }
        }
        const int r_lo = r0 + gr, r_hi = r0 + gr + 8;
        const bool v_lo = r_lo < NTOK, v_hi = r_hi < NTOK;
        const unsigned char rq0 = region[v_lo ? r_lo : (NTOK - 1)];
        const unsigned char rq1 = region[v_hi ? r_hi : (NTOK - 1)];
        __syncwarp();

        float m0 = -1e30f, m1 = -1e30f, l0 = 0.f, l1 = 0.f;
        float o[4][4];
#pragma unroll
        for (int nt = 0; nt < 4; ++nt)
#pragma unroll
            for (int e = 0; e < 4; ++e) o[nt][e] = 0.f;

        for (int ch = 0; ch < 6; ++ch) {
            const int j0 = ch * 64;
            float s[8][4];
#pragma unroll
            for (int nt = 0; nt < 8; ++nt)
#pragma unroll
                for (int e = 0; e < 4; ++e) s[nt][e] = 0.f;
#pragma unroll
            for (int kk = 0; kk < 4; ++kk) {
#pragma unroll
                for (int nt = 0; nt < 8; ++nt) {
                    uint32_t bb[2];
                    bb[0] = Ks[(j0 + nt * 8 + gr) * 36 + kk * 8 + tg];
                    bb[1] = Ks[(j0 + nt * 8 + gr) * 36 + kk * 8 + tg + 4];
                    mma_tf32(s[nt], aQ[kk], bb);
                }
            }
            // bias + mask + row max
            float rm0 = v_lo ? -1e30f : 0.f;
            float rm1 = v_hi ? -1e30f : 0.f;
#pragma unroll
            for (int nt = 0; nt < 8; ++nt) {
                int jc = j0 + nt * 8 + tg * 2;
                bool jv0 = (jc < NTOK), jv1 = (jc + 1 < NTOK);
                unsigned char rk0 = region[jv0 ? jc : 0];
                unsigned char rk1 = region[jv1 ? jc + 1 : 0];
                if (v_lo) {
                    float t0 = jv0 ? (s[nt][0] + rpbh[(size_t)r_lo * 343 + jc] -
                                      ((rk0 != rq0) ? 100.f : 0.f))
                                   : -1e30f;
                    float t1 = jv1 ? (s[nt][1] + rpbh[(size_t)r_lo * 343 + jc + 1] -
                                      ((rk1 != rq0) ? 100.f : 0.f))
                                   : -1e30f;
                    s[nt][0] = t0;
                    s[nt][1] = t1;
                    rm0 = fmaxf(rm0, fmaxf(t0, t1));
                }
                if (v_hi) {
                    float t2 = jv0 ? (s[nt][2] + rpbh[(size_t)r_hi * 343 + jc] -
                                      ((rk0 != rq1) ? 100.f : 0.f))
                                   : -1e30f;
                    float t3 = jv1 ? (s[nt][3] + rpbh[(size_t)r_hi * 343 + jc + 1] -
                                      ((rk1 != rq1) ? 100.f : 0.f))
                                   : -1e30f;
                    s[nt][2] = t2;
                    s[nt][3] = t3;
                    rm1 = fmaxf(rm1, fmaxf(t2, t3));
                }
            }
            rm0 = fmaxf(rm0, __shfl_xor_sync(FULLMASK, rm0, 1));
            rm0 = fmaxf(rm0, __shfl_xor_sync(FULLMASK, rm0, 2));
            rm1 = fmaxf(rm1, __shfl_xor_sync(FULLMASK, rm1, 1));
            rm1 = fmaxf(rm1, __shfl_xor_sync(FULLMASK, rm1, 2));
            float mn0 = fmaxf(m0, rm0), mn1 = fmaxf(m1, rm1);
            float sf0 = __expf(m0 - mn0), sf1 = __expf(m1 - mn1);
            m0 = mn0;
            m1 = mn1;
            float rs0 = 0.f, rs1 = 0.f;
#pragma unroll
            for (int nt = 0; nt < 8; ++nt) {
                float p0 = __expf(s[nt][0] - mn0);
                float p1 = __expf(s[nt][1] - mn0);
                float p2 = __expf(s[nt][2] - mn1);
                float p3 = __expf(s[nt][3] - mn1);
                rs0 += p0 + p1;
                rs1 += p2 + p3;
                uint2 lo = make_uint2(f2tf32(p0), f2tf32(p1));
                uint2 hi = make_uint2(f2tf32(p2), f2tf32(p3));
                *(uint2*)&Pw[gr * 68 + nt * 8 + tg * 2] = lo;
                *(uint2*)&Pw[(gr + 8) * 68 + nt * 8 + tg * 2] = hi;
            }
            rs0 += __shfl_xor_sync(FULLMASK, rs0, 1);
            rs0 += __shfl_xor_sync(FULLMASK, rs0, 2);
            rs1 += __shfl_xor_sync(FULLMASK, rs1, 1);
            rs1 += __shfl_xor_sync(FULLMASK, rs1, 2);
            l0 = l0 * sf0 + rs0;
            l1 = l1 * sf1 + rs1;
#pragma unroll
            for (int nt = 0; nt < 4; ++nt) {
                o[nt][0] *= sf0;
                o[nt][1] *= sf0;
                o[nt][2] *= sf1;
                o[nt][3] *= sf1;
            }
            __syncwarp();
            // O += P * V
#pragma unroll
            for (int kk = 0; kk < 8; ++kk) {
                uint32_t aP[4];
                aP[0] = Pw[gr * 68 + kk * 8 + tg];
                aP[1] = Pw[(gr + 8) * 68 + kk * 8 + tg];
                aP[2] = Pw[gr * 68 + kk * 8 + tg + 4];
                aP[3] = Pw[(gr + 8) * 68 + kk * 8 + tg + 4];
#pragma unroll
                for (int nt = 0; nt < 4; ++nt) {
                    uint32_t bb[2];
                    bb[0] = Vt[(nt * 8 + gr) * 388 + j0 + kk * 8 + tg];
                    bb[1] = Vt[(nt * 8 + gr) * 388 + j0 + kk * 8 + tg + 4];
                    mma_tf32(o[nt], aP, bb);
                }
            }
            __syncwarp();
        }

        // write out
        float il0 = 1.f / l0, il1 = 1.f / l1;
        if (v_lo) {
            float* dst = g_attnout + ((size_t)b_ * NTOK + r_lo) * CDIM + h * HD;
#pragma unroll
            for (int nt = 0; nt < 4; ++nt)
                *(float2*)(dst + nt * 8 + tg * 2) =
                    make_float2(o[nt][0] * il0, o[nt][1] * il0);
        }
        if (v_hi) {
            float* dst = g_attnout + ((size_t)b_ * NTOK + r_hi) * CDIM + h * HD;
#pragma unroll
            for (int nt = 0; nt < 4; ++nt)
                *(float2*)(dst + nt * 8 + tg * 2) =
                    make_float2(o[nt][2] * il1, o[nt][3] * il1);
        }
        __syncwarp();
    }
}

// ---------------- layernorm + residual ------------------------------------------
template <int WHICH>
__global__ void __launch_bounds__(256) ln_kernel(const float* __restrict__ base_p,
                                                 const float* __restrict__ gw,
                                                 const float* __restrict__ bw,
                                                 float* __restrict__ out_p) {
    int gid = blockIdx.x * blockDim.x + threadIdx.x;
    int row = gid >> 5;
    int lane = gid & 31;
    if (row >= NROWS) return;
    const float* a = ((WHICH == 0) ? g_xa : g_m) + (size_t)row * CDIM;
    const float* bs = ((WHICH == 0) ? base_p : g_x1) + (size_t)row * CDIM;
    float* o = ((WHICH == 0) ? g_x1 : out_p) + (size_t)row * CDIM;
    float v[6];
    float s = 0.f, sq = 0.f;
#pragma unroll
    for (int u = 0; u < 6; ++u) {
        float t = a[lane + u * 32];
        v[u] = t;
        s += t;
        sq += t * t;
    }
#pragma unroll
    for (int off = 16; off; off >>= 1) {
        s += __shfl_xor_sync(FULLMASK, s, off);
        sq += __shfl_xor_sync(FULLMASK, sq, off);
    }
    float mean = s * (1.f / 192.f);
    float var = sq * (1.f / 192.f) - mean * mean;
    float inv = rsqrtf(var + 1e-5f);
#pragma unroll
    for (int u = 0; u < 6; ++u) {
        int c = lane + u * 32;
        o[c] = bs[c] + (v[u] - mean) * inv * gw[c] + bw[c];
    }
}

// ---------------- launch ---------------------------------------------------------
extern "C" void kernel_launch(void* const* d_in, const int* in_sizes, int n_in,
                              void* d_out, int out_size) {
    (void)in_sizes; (void)n_in; (void)out_size;
    const float* x = (const float*)d_in[0];
    const float* qkv_w = (const float*)d_in[1];
    const float* q_bias = (const float*)d_in[2];
    const float* v_bias = (const float*)d_in[3];
    const float* logit_scale = (const float*)d_in[4];
    const float* cpb_w1 = (const float*)d_in[5];
    const float* cpb_b1 = (const float*)d_in[6];
    const float* cpb_w2 = (const float*)d_in[7];
    const float* proj_w = (const float*)d_in[8];
    const float* proj_b = (const float*)d_in[9];
    const float* norm1_g = (const float*)d_in[10];
    const float* norm1_b = (const float*)d_in[11];
    const float* fc1_w = (const float*)d_in[12];
    const float* fc1_b = (const float*)d_in[13];
    const float* fc2_w = (const float*)d_in[14];
    const float* fc2_b = (const float*)d_in[15];
    const float* norm2_g = (const float*)d_in[16];
    const float* norm2_b = (const float*)d_in[17];
    float* out = (float*)d_out;

    static bool attr_done = false;
    if (!attr_done) {
        cudaFuncSetAttribute(attn2_kernel, cudaFuncAttributeMaxDynamicSharedMemorySize,
                             ATTN2_SMEM);
        attr_done = true;
    }

    // constants
    cpb_kernel<<<2197, 256>>>(cpb_w1, cpb_b1, cpb_w2);
    rpb_kernel<<<864, 256>>>();

    // qkv (fused shift + window gather): M=43904, N=576, K=192
    mma_gemm<0><<<dim3(6, 343), 256>>>(x, qkv_w, q_bias, v_bias, 192);

    // attention (tensor-core flash)
    attn2_kernel<<<768, 256, ATTN2_SMEM>>>(logit_scale);

    // proj (fused window reverse + roll scatter): N=192, K=192
    mma_gemm<1><<<dim3(2, 343), 256>>>(nullptr, proj_w, proj_b, nullptr, 192);

    // x1 = x + LN(xa)
    ln_kernel<0><<<5488, 256>>>(x, norm1_g, norm1_b, nullptr);

    // MLP: fc1 N=768 K=192 (GELU), fc2 N=192 K=768
    mma_gemm<2><<<dim3(8, 343), 256>>>(nullptr, fc1_w, fc1_b, nullptr, 192);
    mma_gemm<3><<<dim3(2, 343), 256>>>(nullptr, fc2_w, fc2_b, nullptr, 768);

    // out = x1 + LN(m)
    ln_kernel<1><<<5488, 256>>>(nullptr, norm2_g, norm2_b, out);
}

// round 5
// speedup vs baseline: 3.0595x; 1.6468x over previous
#include <cuda_runtime.h>
#include <math.h>
#include <stdint.h>

#define FULLMASK 0xffffffffu

// problem dims
#define NTOK   343
#define NHEAD  6
#define HD     32
#define CDIM   192
#define LTOT   21952   // 28^3
#define NWIN   128     // 2 batches * 64 windows
#define NROWS  43904   // 128*343 = 2*21952
#define RPBS   344     // padded rpb row stride (8B-aligned float2 loads)

// ---------------- device scratch ------------------------------------------------
__device__ float g_hb[2197 * 6];
__device__ __align__(16) float g_rpb[6 * 343 * RPBS];
__device__ float g_q[(size_t)NWIN * NHEAD * NTOK * HD];
__device__ float g_k[(size_t)NWIN * NHEAD * NTOK * HD];
__device__ float g_v[(size_t)NWIN * NHEAD * NTOK * HD];
__device__ float g_attnout[(size_t)NWIN * NTOK * CDIM];
__device__ float g_xa[(size_t)2 * LTOT * CDIM];
__device__ float g_x1[(size_t)2 * LTOT * CDIM];
__device__ float g_m[(size_t)2 * LTOT * CDIM];
__device__ float g_hmid[(size_t)NROWS * 768];

// ---------------- helpers -------------------------------------------------------
__device__ __forceinline__ uint32_t f2tf32(float x) {
    uint32_t r;
    asm("cvt.rna.tf32.f32 %0, %1;" : "=r"(r) : "f"(x));
    return r;
}

__device__ __forceinline__ void mma_tf32(float* c, const uint32_t* a, const uint32_t* b) {
    asm volatile(
        "mma.sync.aligned.m16n8k8.row.col.f32.tf32.tf32.f32 "
        "{%0,%1,%2,%3}, {%4,%5,%6,%7}, {%8,%9}, {%0,%1,%2,%3};"
        : "+f"(c[0]), "+f"(c[1]), "+f"(c[2]), "+f"(c[3])
        : "r"(a[0]), "r"(a[1]), "r"(a[2]), "r"(a[3]), "r"(b[0]), "r"(b[1]));
}

// ---------------- CPB MLP -------------------------------------------------------
__device__ __forceinline__ float cpb_coord(int i) {
    float v = (float)(i - 6) * (8.0f / 6.0f);
    float av = fabsf(v);
    float r = log2f(av + 1.0f) * (1.0f / 3.0f);
    return (v < 0.f) ? -r : r;
}

__global__ void __launch_bounds__(256) cpb_kernel(const float* __restrict__ w1,
                                                  const float* __restrict__ b1,
                                                  const float* __restrict__ w2) {
    __shared__ float hid[512];
    int t = blockIdx.x;
    int a = t / 169;
    int rem = t - a * 169;
    int b = rem / 13;
    int c = rem - b * 13;
    float c0 = cpb_coord(a), c1 = cpb_coord(b), c2 = cpb_coord(c);
    for (int j = threadIdx.x; j < 512; j += blockDim.x) {
        float hv = c0 * w1[j * 3 + 0] + c1 * w1[j * 3 + 1] + c2 * w1[j * 3 + 2] + b1[j];
        hid[j] = fmaxf(hv, 0.f);
    }
    __syncthreads();
    if (threadIdx.x < 192) {
        int hh = threadIdx.x >> 5, lane = threadIdx.x & 31;
        float s = 0.f;
        for (int j = lane; j < 512; j += 32) s += hid[j] * w2[hh * 512 + j];
#pragma unroll
        for (int off = 16; off; off >>= 1) s += __shfl_xor_sync(FULLMASK, s, off);
        if (lane == 0) g_hb[t * 6 + hh] = s;
    }
}

__global__ void rpb_kernel() {
    const int total = 6 * 343 * RPBS;
    for (int idx = blockIdx.x * blockDim.x + threadIdx.x; idx < total;
         idx += gridDim.x * blockDim.x) {
        int hh = idx / (343 * RPBS);
        int rem = idx - hh * (343 * RPBS);
        int i = rem / RPBS;
        int j = rem - i * RPBS;
        if (j >= 343) {
            g_rpb[idx] = 0.f;
            continue;
        }
        int dh = i / 49 - j / 49 + 6;
        int dw = (i / 7) % 7 - (j / 7) % 7 + 6;
        int dd = i % 7 - j % 7 + 6;
        int tix = (dh * 13 + dw) * 13 + dd;
        float v = g_hb[tix * 6 + hh];
        g_rpb[idx] = 16.f / (1.f + __expf(-v));
    }
}

// ---------------- tf32 mma.sync GEMM with register prefetch ----------------------
#define BM 128
#define BN 96
#define BK 16
#define SPAD 20

template <int MODE>
__global__ void __launch_bounds__(256) mma_gemm(const float* __restrict__ A,
                                                const float* __restrict__ W,
                                                const float* __restrict__ bias1,
                                                const float* __restrict__ bias2,
                                                int K) {
    __shared__ __align__(16) uint32_t As[BM * SPAD];
    __shared__ __align__(16) uint32_t Bs[BN * SPAD];

    const int tid = threadIdx.x;
    const int lane = tid & 31;
    const int warp = tid >> 5;
    const int warpM = warp & 3;
    const int warpN = warp >> 2;
    const int gr = lane >> 2;
    const int tg = lane & 3;

    const int m0 = blockIdx.y * BM;
    const int n0 = blockIdx.x * BN;

    const float* Asrc;
    if (MODE == 0) Asrc = A;
    else if (MODE == 1) Asrc = g_attnout;
    else if (MODE == 2) Asrc = g_x1;
    else Asrc = g_hmid;

    const int acol4 = tid & 3;
    const float* aptr[2];
    int arowv[2];
#pragma unroll
    for (int i = 0; i < 2; ++i) {
        int idx = tid + i * 256;
        int arow = idx >> 2;
        arowv[i] = arow;
        int rho = m0 + arow;
        const float* p;
        if (MODE == 0) {
            int b_ = rho / 343, n = rho - b_ * 343;
            int bb = b_ >> 6, win = b_ & 63;
            int wa = win >> 4, wb = (win >> 2) & 3, wc = win & 3;
            int ii = n / 49, jj = (n / 7) % 7, kk = n % 7;
            int hs = (wa * 7 + ii + 3) % 28;
            int ws = (wb * 7 + jj + 3) % 28;
            int ds = (wc * 7 + kk + 3) % 28;
            p = Asrc + ((size_t)bb * LTOT + (hs * 784 + ws * 28 + ds)) * CDIM;
        } else {
            p = Asrc + (size_t)rho * K;
        }
        aptr[i] = p + acol4 * 4;
    }
    const int brow0 = tid >> 2, bc40 = tid & 3;
    const int brow1 = (tid + 256) >> 2, bc41 = tid & 3;
    const float* bptr0 = W + (size_t)(n0 + brow0) * K + bc40 * 4;
    const float* bptr1 = W + (size_t)(n0 + brow1) * K + bc41 * 4;
    const bool bhas1 = (tid < 128);

    float acc[2][6][4];
#pragma unroll
    for (int mi = 0; mi < 2; ++mi)
#pragma unroll
        for (int ni = 0; ni < 6; ++ni)
#pragma unroll
            for (int e = 0; e < 4; ++e) acc[mi][ni][e] = 0.f;

    float4 av[2], bv[2];
    av[0] = *(const float4*)(aptr[0]);
    av[1] = *(const float4*)(aptr[1]);
    bv[0] = *(const float4*)(bptr0);
    if (bhas1) bv[1] = *(const float4*)(bptr1);

    for (int kt = 0; kt < K; kt += BK) {
        __syncthreads();
#pragma unroll
        for (int i = 0; i < 2; ++i) {
            uint4 u;
            u.x = f2tf32(av[i].x);
            u.y = f2tf32(av[i].y);
            u.z = f2tf32(av[i].z);
            u.w = f2tf32(av[i].w);
            *(uint4*)&As[arowv[i] * SPAD + acol4 * 4] = u;
        }
        {
            uint4 u;
            u.x = f2tf32(bv[0].x);
            u.y = f2tf32(bv[0].y);
            u.z = f2tf32(bv[0].z);
            u.w = f2tf32(bv[0].w);
            *(uint4*)&Bs[brow0 * SPAD + bc40 * 4] = u;
            if (bhas1) {
                uint4 v;
                v.x = f2tf32(bv[1].x);
                v.y = f2tf32(bv[1].y);
                v.z = f2tf32(bv[1].z);
                v.w = f2tf32(bv[1].w);
                *(uint4*)&Bs[brow1 * SPAD + bc41 * 4] = v;
            }
        }
        __syncthreads();
        if (kt + BK < K) {
            av[0] = *(const float4*)(aptr[0] + kt + BK);
            av[1] = *(const float4*)(aptr[1] + kt + BK);
            bv[0] = *(const float4*)(bptr0 + kt + BK);
            if (bhas1) bv[1] = *(const float4*)(bptr1 + kt + BK);
        }

#pragma unroll
        for (int kk = 0; kk < 16; kk += 8) {
            uint32_t afr[2][4];
#pragma unroll
            for (int mi = 0; mi < 2; ++mi) {
                int rb = warpM * 32 + mi * 16;
                afr[mi][0] = As[(rb + gr) * SPAD + kk + tg];
                afr[mi][1] = As[(rb + gr + 8) * SPAD + kk + tg];
                afr[mi][2] = As[(rb + gr) * SPAD + kk + tg + 4];
                afr[mi][3] = As[(rb + gr + 8) * SPAD + kk + tg + 4];
            }
            uint32_t bfr[6][2];
#pragma unroll
            for (int ni = 0; ni < 6; ++ni) {
                int nb = warpN * 48 + ni * 8 + gr;
                bfr[ni][0] = Bs[nb * SPAD + kk + tg];
                bfr[ni][1] = Bs[nb * SPAD + kk + tg + 4];
            }
#pragma unroll
            for (int mi = 0; mi < 2; ++mi)
#pragma unroll
                for (int ni = 0; ni < 6; ++ni)
                    mma_tf32(acc[mi][ni], afr[mi], bfr[ni]);
        }
    }

    // ---------------- epilogue ----------------------------------------------------
#pragma unroll
    for (int mi = 0; mi < 2; ++mi) {
        int rows[2];
        rows[0] = m0 + warpM * 32 + mi * 16 + gr;
        rows[1] = rows[0] + 8;
#pragma unroll
        for (int half = 0; half < 2; ++half) {
            const int r = rows[half];
            int b_ = 0, n = 0;
            size_t scat = 0;
            if (MODE == 0 || MODE == 1) {
                b_ = r / 343;
                n = r - b_ * 343;
            }
            if (MODE == 1) {
                int bb2 = b_ >> 6, win = b_ & 63;
                int wa = win >> 4, wb = (win >> 2) & 3, wc = win & 3;
                int i3 = n / 49, j3 = (n / 7) % 7, k3 = n % 7;
                int hd_ = (wa * 7 + i3 + 3) % 28;
                int wd_ = (wb * 7 + j3 + 3) % 28;
                int dd_ = (wc * 7 + k3 + 3) % 28;
                scat = ((size_t)bb2 * LTOT + (hd_ * 784 + wd_ * 28 + dd_)) * CDIM;
            }
#pragma unroll
            for (int ni = 0; ni < 6; ++ni) {
                int c = n0 + warpN * 48 + ni * 8 + tg * 2;
                float v0 = acc[mi][ni][half * 2 + 0];
                float v1 = acc[mi][ni][half * 2 + 1];
                if (MODE == 0) {
                    int sct = c / 192;
                    int remc = c - sct * 192;
                    int hh = remc >> 5, dd = remc & 31;
                    float* dst = (sct == 0 ? g_q : (sct == 1 ? g_k : g_v)) +
                                 ((size_t)(b_ * 6 + hh) * NTOK + n) * HD + dd;
                    float e0 = 0.f, e1 = 0.f;
                    if (sct == 0) { e0 = bias1[remc]; e1 = bias1[remc + 1]; }
                    else if (sct == 2) { e0 = bias2[remc]; e1 = bias2[remc + 1]; }
                    *(float2*)dst = make_float2(v0 + e0, v1 + e1);
                } else if (MODE == 1) {
                    *(float2*)(g_xa + scat + c) =
                        make_float2(v0 + bias1[c], v1 + bias1[c + 1]);
                } else if (MODE == 2) {
                    float x0 = v0 + bias1[c], x1 = v1 + bias1[c + 1];
                    float g0 = 0.5f * x0 * (1.f + erff(x0 * 0.70710678118654752f));
                    float g1 = 0.5f * x1 * (1.f + erff(x1 * 0.70710678118654752f));
                    *(float2*)(g_hmid + (size_t)r * 768 + c) = make_float2(g0, g1);
                } else {
                    *(float2*)(g_m + (size_t)r * 192 + c) =
                        make_float2(v0 + bias1[c], v1 + bias1[c + 1]);
                }
            }
        }
    }
}

// ---------------- tensor-core flash attention v3 ---------------------------------
// one block per (window, head). 256 threads = 8 warps, 2 CTAs/SM.
// K normalized tf32 in smem [384][36]; V^T tf32 [32][388]; NO P staging (register
// shuffles); NO Q staging (direct LDG + quad reduction).
#define KS_WORDS (384 * 36)
#define VT_WORDS (32 * 388)
#define ATTN3_SMEM ((KS_WORDS + VT_WORDS) * 4 + 512)

__global__ void __launch_bounds__(256, 2) attn3_kernel(const float* __restrict__ logit_scale) {
    extern __shared__ uint32_t asmem[];
    uint32_t* Ks = asmem;                       // [384][36]
    uint32_t* Vt = asmem + KS_WORDS;            // [32][388]
    unsigned char* region = (unsigned char*)(Vt + VT_WORDS);

    const int bh = blockIdx.x;
    const int b_ = bh / 6, h = bh - (bh / 6) * 6;
    const int tid = threadIdx.x;
    const int lane = tid & 31, warp = tid >> 5;
    const int gr = lane >> 2, tg = lane & 3;

    const size_t kvbase = (size_t)bh * (NTOK * HD);
    const float* kg = g_k + kvbase;
    const float* vg = g_v + kvbase;
    const float* qg = g_q + kvbase;

    // K: normalize rows -> tf32 smem (warp per row)
    for (int r = warp; r < 384; r += 8) {
        if (r < NTOK) {
            float v = kg[r * 32 + lane];
            float s = v * v;
#pragma unroll
            for (int o = 16; o; o >>= 1) s += __shfl_xor_sync(FULLMASK, s, o);
            float inv = 1.f / fmaxf(sqrtf(s), 1e-12f);
            Ks[r * 36 + lane] = f2tf32(v * inv);
        } else {
            Ks[r * 36 + lane] = 0u;
        }
    }
    // V transposed -> tf32 smem
    for (int idx = tid; idx < NTOK * 32; idx += 256) {
        int j = idx >> 5, d = idx & 31;
        Vt[d * 388 + j] = f2tf32(vg[idx]);
    }
    for (int idx = tid; idx < 32 * 45; idx += 256) {
        int d = idx / 45, j = NTOK + idx - (idx / 45) * 45;
        Vt[d * 388 + j] = 0u;
    }
    // region ids (only for shift-boundary windows)
    const int win = b_ & 63;
    const int wa = win >> 4, wb = (win >> 2) & 3, wc = win & 3;
    const bool maskedw = (wa == 3) || (wb == 3) || (wc == 3);
    if (maskedw) {
        for (int t = tid; t < 384; t += 256) {
            if (t < NTOK) {
                int ih = t / 49, iw = (t / 7) % 7, id = t % 7;
                int rH = (wa < 3) ? 0 : ((ih < 4) ? 1 : 2);
                int rW = (wb < 3) ? 0 : ((iw < 4) ? 1 : 2);
                int rD = (wc < 3) ? 0 : ((id < 4) ? 1 : 2);
                region[t] = (unsigned char)(rH * 9 + rW * 3 + rD);
            } else {
                region[t] = 0;
            }
        }
    }
    __syncthreads();

    const float scale = __expf(fminf(logit_scale[h], 4.6051701859880914f));
    const float* rpbh = g_rpb + (size_t)h * (343 * RPBS);

    for (int rb = 0; rb < 3; ++rb) {
        const int r0 = rb * 128 + warp * 16;
        if (r0 >= NTOK) continue;   // warp-uniform

        const int r_lo = r0 + gr, r_hi = r0 + gr + 8;
        const bool v_lo = r_lo < NTOK, v_hi = r_hi < NTOK;

        // Q fragments direct from gmem
        float qf[4][4];
        const float* qlo = qg + (size_t)(v_lo ? r_lo : 0) * 32;
        const float* qhi = qg + (size_t)(v_hi ? r_hi : 0) * 32;
#pragma unroll
        for (int kk = 0; kk < 4; ++kk) {
            qf[kk][0] = v_lo ? qlo[kk * 8 + tg] : 0.f;
            qf[kk][1] = v_hi ? qhi[kk * 8 + tg] : 0.f;
            qf[kk][2] = v_lo ? qlo[kk * 8 + tg + 4] : 0.f;
            qf[kk][3] = v_hi ? qhi[kk * 8 + tg + 4] : 0.f;
        }
        // row norms via quad reduction
        float s0 = 0.f, s1 = 0.f;
#pragma unroll
        for (int kk = 0; kk < 4; ++kk) {
            s0 += qf[kk][0] * qf[kk][0] + qf[kk][2] * qf[kk][2];
            s1 += qf[kk][1] * qf[kk][1] + qf[kk][3] * qf[kk][3];
        }
        s0 += __shfl_xor_sync(FULLMASK, s0, 1);
        s0 += __shfl_xor_sync(FULLMASK, s0, 2);
        s1 += __shfl_xor_sync(FULLMASK, s1, 1);
        s1 += __shfl_xor_sync(FULLMASK, s1, 2);
        const float i0 = scale / fmaxf(sqrtf(s0), 1e-12f);
        const float i1 = scale / fmaxf(sqrtf(s1), 1e-12f);
        uint32_t aQ[4][4];
#pragma unroll
        for (int kk = 0; kk < 4; ++kk) {
            aQ[kk][0] = f2tf32(qf[kk][0] * i0);
            aQ[kk][1] = f2tf32(qf[kk][1] * i1);
            aQ[kk][2] = f2tf32(qf[kk][2] * i0);
            aQ[kk][3] = f2tf32(qf[kk][3] * i1);
        }

        unsigned char rq0 = 0, rq1 = 0;
        if (maskedw) {
            rq0 = region[v_lo ? r_lo : (NTOK - 1)];
            rq1 = region[v_hi ? r_hi : (NTOK - 1)];
        }
        const float* rpr_lo = rpbh + (size_t)(v_lo ? r_lo : 0) * RPBS;
        const float* rpr_hi = rpbh + (size_t)(v_hi ? r_hi : 0) * RPBS;

        float m0 = -1e30f, m1 = -1e30f, l0 = 0.f, l1 = 0.f;
        float o[4][4];
#pragma unroll
        for (int nt = 0; nt < 4; ++nt)
#pragma unroll
            for (int e = 0; e < 4; ++e) o[nt][e] = 0.f;

        for (int ch = 0; ch < 6; ++ch) {
            const int j0 = ch * 64;
            float s[8][4];
#pragma unroll
            for (int nt = 0; nt < 8; ++nt)
#pragma unroll
                for (int e = 0; e < 4; ++e) s[nt][e] = 0.f;
#pragma unroll
            for (int kk = 0; kk < 4; ++kk) {
#pragma unroll
                for (int nt = 0; nt < 8; ++nt) {
                    uint32_t bb[2];
                    bb[0] = Ks[(j0 + nt * 8 + gr) * 36 + kk * 8 + tg];
                    bb[1] = Ks[(j0 + nt * 8 + gr) * 36 + kk * 8 + tg + 4];
                    mma_tf32(s[nt], aQ[kk], bb);
                }
            }
            // bias + mask + row max
            float rm0 = -1e30f, rm1 = -1e30f;
#pragma unroll
            for (int nt = 0; nt < 8; ++nt) {
                const int jc = j0 + nt * 8 + tg * 2;
                float2 blo = *(const float2*)(rpr_lo + jc);
                float2 bhi = *(const float2*)(rpr_hi + jc);
                float t0 = s[nt][0] + blo.x;
                float t1 = s[nt][1] + blo.y;
                float t2 = s[nt][2] + bhi.x;
                float t3 = s[nt][3] + bhi.y;
                if (maskedw) {
                    unsigned char rk0 = region[jc];
                    unsigned char rk1 = region[jc + 1];
                    if (rk0 != rq0) t0 -= 100.f;
                    if (rk1 != rq0) t1 -= 100.f;
                    if (rk0 != rq1) t2 -= 100.f;
                    if (rk1 != rq1) t3 -= 100.f;
                }
                if (ch == 5) {
                    if (jc >= NTOK) { t0 = t2 = -1e30f; }
                    if (jc + 1 >= NTOK) { t1 = t3 = -1e30f; }
                }
                if (!v_lo) { t0 = t1 = -1e30f; }
                if (!v_hi) { t2 = t3 = -1e30f; }
                s[nt][0] = t0;
                s[nt][1] = t1;
                s[nt][2] = t2;
                s[nt][3] = t3;
                rm0 = fmaxf(rm0, fmaxf(t0, t1));
                rm1 = fmaxf(rm1, fmaxf(t2, t3));
            }
            rm0 = fmaxf(rm0, __shfl_xor_sync(FULLMASK, rm0, 1));
            rm0 = fmaxf(rm0, __shfl_xor_sync(FULLMASK, rm0, 2));
            rm1 = fmaxf(rm1, __shfl_xor_sync(FULLMASK, rm1, 1));
            rm1 = fmaxf(rm1, __shfl_xor_sync(FULLMASK, rm1, 2));
            const float mn0 = fmaxf(m0, rm0), mn1 = fmaxf(m1, rm1);
            const float sf0 = __expf(m0 - mn0), sf1 = __expf(m1 - mn1);
            m0 = mn0;
            m1 = mn1;
            float rs0 = 0.f, rs1 = 0.f;
#pragma unroll
            for (int nt = 0; nt < 8; ++nt) {
                float p0 = __expf(s[nt][0] - mn0);
                float p1 = __expf(s[nt][1] - mn0);
                float p2 = __expf(s[nt][2] - mn1);
                float p3 = __expf(s[nt][3] - mn1);
                rs0 += p0 + p1;
                rs1 += p2 + p3;
                s[nt][0] = p0;
                s[nt][1] = p1;
                s[nt][2] = p2;
                s[nt][3] = p3;
            }
            rs0 += __shfl_xor_sync(FULLMASK, rs0, 1);
            rs0 += __shfl_xor_sync(FULLMASK, rs0, 2);
            rs1 += __shfl_xor_sync(FULLMASK, rs1, 1);
            rs1 += __shfl_xor_sync(FULLMASK, rs1, 2);
            l0 = l0 * sf0 + rs0;
            l1 = l1 * sf1 + rs1;
#pragma unroll
            for (int nt = 0; nt < 4; ++nt) {
                o[nt][0] *= sf0;
                o[nt][1] *= sf0;
                o[nt][2] *= sf1;
                o[nt][3] *= sf1;
            }
            // O += P * V : acc-frag -> A-frag via intra-quad shuffles
            const int src0 = (lane & ~3) | (tg >> 1);
            const int src2 = src0 + 2;
            const bool odd = (tg & 1);
#pragma unroll
            for (int kk = 0; kk < 8; ++kk) {
                float v00 = __shfl_sync(FULLMASK, s[kk][0], src0);
                float v01 = __shfl_sync(FULLMASK, s[kk][1], src0);
                float v20 = __shfl_sync(FULLMASK, s[kk][0], src2);
                float v21 = __shfl_sync(FULLMASK, s[kk][1], src2);
                float v10 = __shfl_sync(FULLMASK, s[kk][2], src0);
                float v11 = __shfl_sync(FULLMASK, s[kk][3], src0);
                float v30 = __shfl_sync(FULLMASK, s[kk][2], src2);
                float v31 = __shfl_sync(FULLMASK, s[kk][3], src2);
                uint32_t aP[4];
                aP[0] = f2tf32(odd ? v01 : v00);
                aP[1] = f2tf32(odd ? v11 : v10);
                aP[2] = f2tf32(odd ? v21 : v20);
                aP[3] = f2tf32(odd ? v31 : v30);
#pragma unroll
                for (int nt = 0; nt < 4; ++nt) {
                    uint32_t bb[2];
                    bb[0] = Vt[(nt * 8 + gr) * 388 + j0 + kk * 8 + tg];
                    bb[1] = Vt[(nt * 8 + gr) * 388 + j0 + kk * 8 + tg + 4];
                    mma_tf32(o[nt], aP, bb);
                }
            }
        }

        // write out
        if (v_lo) {
            const float il0 = 1.f / l0;
            float* dst = g_attnout + ((size_t)b_ * NTOK + r_lo) * CDIM + h * HD;
#pragma unroll
            for (int nt = 0; nt < 4; ++nt)
                *(float2*)(dst + nt * 8 + tg * 2) =
                    make_float2(o[nt][0] * il0, o[nt][1] * il0);
        }
        if (v_hi) {
            const float il1 = 1.f / l1;
            float* dst = g_attnout + ((size_t)b_ * NTOK + r_hi) * CDIM + h * HD;
#pragma unroll
            for (int nt = 0; nt < 4; ++nt)
                *(float2*)(dst + nt * 8 + tg * 2) =
                    make_float2(o[nt][2] * il1, o[nt][3] * il1);
        }
    }
}

// ---------------- layernorm + residual ------------------------------------------
template <int WHICH>
__global__ void __launch_bounds__(256) ln_kernel(const float* __restrict__ base_p,
                                                 const float* __restrict__ gw,
                                                 const float* __restrict__ bw,
                                                 float* __restrict__ out_p) {
    int gid = blockIdx.x * blockDim.x + threadIdx.x;
    int row = gid >> 5;
    int lane = gid & 31;
    if (row >= NROWS) return;
    const float* a = ((WHICH == 0) ? g_xa : g_m) + (size_t)row * CDIM;
    const float* bs = ((WHICH == 0) ? base_p : g_x1) + (size_t)row * CDIM;
    float* o = ((WHICH == 0) ? g_x1 : out_p) + (size_t)row * CDIM;
    float v[6];
    float s = 0.f, sq = 0.f;
#pragma unroll
    for (int u = 0; u < 6; ++u) {
        float t = a[lane + u * 32];
        v[u] = t;
        s += t;
        sq += t * t;
    }
#pragma unroll
    for (int off = 16; off; off >>= 1) {
        s += __shfl_xor_sync(FULLMASK, s, off);
        sq += __shfl_xor_sync(FULLMASK, sq, off);
    }
    float mean = s * (1.f / 192.f);
    float var = sq * (1.f / 192.f) - mean * mean;
    float inv = rsqrtf(var + 1e-5f);
#pragma unroll
    for (int u = 0; u < 6; ++u) {
        int c = lane + u * 32;
        o[c] = bs[c] + (v[u] - mean) * inv * gw[c] + bw[c];
    }
}

// ---------------- launch ---------------------------------------------------------
extern "C" void kernel_launch(void* const* d_in, const int* in_sizes, int n_in,
                              void* d_out, int out_size) {
    (void)in_sizes; (void)n_in; (void)out_size;
    const float* x = (const float*)d_in[0];
    const float* qkv_w = (const float*)d_in[1];
    const float* q_bias = (const float*)d_in[2];
    const float* v_bias = (const float*)d_in[3];
    const float* logit_scale = (const float*)d_in[4];
    const float* cpb_w1 = (const float*)d_in[5];
    const float* cpb_b1 = (const float*)d_in[6];
    const float* cpb_w2 = (const float*)d_in[7];
    const float* proj_w = (const float*)d_in[8];
    const float* proj_b = (const float*)d_in[9];
    const float* norm1_g = (const float*)d_in[10];
    const float* norm1_b = (const float*)d_in[11];
    const float* fc1_w = (const float*)d_in[12];
    const float* fc1_b = (const float*)d_in[13];
    const float* fc2_w = (const float*)d_in[14];
    const float* fc2_b = (const float*)d_in[15];
    const float* norm2_g = (const float*)d_in[16];
    const float* norm2_b = (const float*)d_in[17];
    float* out = (float*)d_out;

    static bool attr_done = false;
    if (!attr_done) {
        cudaFuncSetAttribute(attn3_kernel, cudaFuncAttributeMaxDynamicSharedMemorySize,
                             ATTN3_SMEM);
        attr_done = true;
    }

    // constants
    cpb_kernel<<<2197, 256>>>(cpb_w1, cpb_b1, cpb_w2);
    rpb_kernel<<<888, 256>>>();

    // qkv (fused shift + window gather): M=43904, N=576, K=192
    mma_gemm<0><<<dim3(6, 343), 256>>>(x, qkv_w, q_bias, v_bias, 192);

    // attention (tensor-core flash, register P)
    attn3_kernel<<<768, 256, ATTN3_SMEM>>>(logit_scale);

    // proj (fused window reverse + roll scatter): N=192, K=192
    mma_gemm<1><<<dim3(2, 343), 256>>>(nullptr, proj_w, proj_b, nullptr, 192);

    // x1 = x + LN(xa)
    ln_kernel<0><<<5488, 256>>>(x, norm1_g, norm1_b, nullptr);

    // MLP: fc1 N=768 K=192 (GELU), fc2 N=192 K=768
    mma_gemm<2><<<dim3(8, 343), 256>>>(nullptr, fc1_w, fc1_b, nullptr, 192);
    mma_gemm<3><<<dim3(2, 343), 256>>>(nullptr, fc2_w, fc2_b, nullptr, 768);

    // out = x1 + LN(m)
    ln_kernel<1><<<5488, 256>>>(nullptr, norm2_g, norm2_b, out);
}

// round 6
// speedup vs baseline: 3.0847x; 1.0082x over previous
#include <cuda_runtime.h>
#include <math.h>
#include <stdint.h>

#define FULLMASK 0xffffffffu

// problem dims
#define NTOK   343
#define NHEAD  6
#define HD     32
#define CDIM   192
#define LTOT   21952   // 28^3
#define NWIN   128     // 2 batches * 64 windows
#define NROWS  43904   // 128*343 = 2*21952
#define RPBS   344     // padded rpb row stride (8B-aligned float2 loads)

// ---------------- device scratch ------------------------------------------------
__device__ float g_hb[2197 * 6];
__device__ __align__(16) float g_rpb[6 * 343 * RPBS];
__device__ float g_q[(size_t)NWIN * NHEAD * NTOK * HD];
__device__ float g_k[(size_t)NWIN * NHEAD * NTOK * HD];
__device__ float g_v[(size_t)NWIN * NHEAD * NTOK * HD];
__device__ float g_attnout[(size_t)NWIN * NTOK * CDIM];
__device__ float g_x1[(size_t)2 * LTOT * CDIM];
__device__ float g_hmid[(size_t)NROWS * 768];

// ---------------- helpers -------------------------------------------------------
__device__ __forceinline__ uint32_t f2tf32(float x) {
    uint32_t r;
    asm("cvt.rna.tf32.f32 %0, %1;" : "=r"(r) : "f"(x));
    return r;
}

__device__ __forceinline__ void mma_tf32(float* c, const uint32_t* a, const uint32_t* b) {
    asm volatile(
        "mma.sync.aligned.m16n8k8.row.col.f32.tf32.tf32.f32 "
        "{%0,%1,%2,%3}, {%4,%5,%6,%7}, {%8,%9}, {%0,%1,%2,%3};"
        : "+f"(c[0]), "+f"(c[1]), "+f"(c[2]), "+f"(c[3])
        : "r"(a[0]), "r"(a[1]), "r"(a[2]), "r"(a[3]), "r"(b[0]), "r"(b[1]));
}

// ---------------- CPB MLP -------------------------------------------------------
__device__ __forceinline__ float cpb_coord(int i) {
    float v = (float)(i - 6) * (8.0f / 6.0f);
    float av = fabsf(v);
    float r = log2f(av + 1.0f) * (1.0f / 3.0f);
    return (v < 0.f) ? -r : r;
}

__global__ void __launch_bounds__(256) cpb_kernel(const float* __restrict__ w1,
                                                  const float* __restrict__ b1,
                                                  const float* __restrict__ w2) {
    __shared__ float hid[512];
    int t = blockIdx.x;
    int a = t / 169;
    int rem = t - a * 169;
    int b = rem / 13;
    int c = rem - b * 13;
    float c0 = cpb_coord(a), c1 = cpb_coord(b), c2 = cpb_coord(c);
    for (int j = threadIdx.x; j < 512; j += blockDim.x) {
        float hv = c0 * w1[j * 3 + 0] + c1 * w1[j * 3 + 1] + c2 * w1[j * 3 + 2] + b1[j];
        hid[j] = fmaxf(hv, 0.f);
    }
    __syncthreads();
    if (threadIdx.x < 192) {
        int hh = threadIdx.x >> 5, lane = threadIdx.x & 31;
        float s = 0.f;
        for (int j = lane; j < 512; j += 32) s += hid[j] * w2[hh * 512 + j];
#pragma unroll
        for (int off = 16; off; off >>= 1) s += __shfl_xor_sync(FULLMASK, s, off);
        if (lane == 0) g_hb[t * 6 + hh] = s;
    }
}

__global__ void rpb_kernel() {
    const int total = 6 * 343 * RPBS;
    for (int idx = blockIdx.x * blockDim.x + threadIdx.x; idx < total;
         idx += gridDim.x * blockDim.x) {
        int hh = idx / (343 * RPBS);
        int rem = idx - hh * (343 * RPBS);
        int i = rem / RPBS;
        int j = rem - i * RPBS;
        if (j >= 343) {
            g_rpb[idx] = 0.f;
            continue;
        }
        int dh = i / 49 - j / 49 + 6;
        int dw = (i / 7) % 7 - (j / 7) % 7 + 6;
        int dd = i % 7 - j % 7 + 6;
        int tix = (dh * 13 + dw) * 13 + dd;
        float v = g_hb[tix * 6 + hh];
        g_rpb[idx] = 16.f / (1.f + __expf(-v));
    }
}

// ---------------- tf32 mma.sync GEMM, double-buffered smem, 1 sync/tile ----------
// MODE 0: QKV (A gathered from x via shift+window; out -> g_q/g_k/g_v + biases)
// MODE 2: FC1 (A=g_x1 -> g_hmid with exact GELU)
#define BM 128
#define BN 96
#define BK 16
#define SPAD 20

template <int MODE>
__global__ void __launch_bounds__(256) mma_gemm(const float* __restrict__ A,
                                                const float* __restrict__ W,
                                                const float* __restrict__ bias1,
                                                const float* __restrict__ bias2,
                                                int K) {
    __shared__ __align__(16) uint32_t As[2][BM * SPAD];
    __shared__ __align__(16) uint32_t Bs[2][BN * SPAD];

    const int tid = threadIdx.x;
    const int lane = tid & 31;
    const int warp = tid >> 5;
    const int warpM = warp & 3;
    const int warpN = warp >> 2;
    const int gr = lane >> 2;
    const int tg = lane & 3;

    const int m0 = blockIdx.y * BM;
    const int n0 = blockIdx.x * BN;

    const float* Asrc = (MODE == 0) ? A : g_x1;

    const int acol4 = tid & 3;
    const float* aptr[2];
    int arowv[2];
#pragma unroll
    for (int i = 0; i < 2; ++i) {
        int idx = tid + i * 256;
        int arow = idx >> 2;
        arowv[i] = arow;
        int rho = m0 + arow;
        const float* p;
        if (MODE == 0) {
            int b_ = rho / 343, n = rho - b_ * 343;
            int bb = b_ >> 6, win = b_ & 63;
            int wa = win >> 4, wb = (win >> 2) & 3, wc = win & 3;
            int ii = n / 49, jj = (n / 7) % 7, kk = n % 7;
            int hs = (wa * 7 + ii + 3) % 28;
            int ws = (wb * 7 + jj + 3) % 28;
            int ds = (wc * 7 + kk + 3) % 28;
            p = Asrc + ((size_t)bb * LTOT + (hs * 784 + ws * 28 + ds)) * CDIM;
        } else {
            p = Asrc + (size_t)rho * K;
        }
        aptr[i] = p + acol4 * 4;
    }
    const int brow0 = tid >> 2;
    const int brow1 = (tid + 256) >> 2;
    const float* bptr0 = W + (size_t)(n0 + brow0) * K + (tid & 3) * 4;
    const float* bptr1 = W + (size_t)(n0 + brow1) * K + (tid & 3) * 4;
    const bool bhas1 = (tid < 128);

    float acc[2][6][4];
#pragma unroll
    for (int mi = 0; mi < 2; ++mi)
#pragma unroll
        for (int ni = 0; ni < 6; ++ni)
#pragma unroll
            for (int e = 0; e < 4; ++e) acc[mi][ni][e] = 0.f;

    float4 av[2], bv[2];
    av[0] = *(const float4*)(aptr[0]);
    av[1] = *(const float4*)(aptr[1]);
    bv[0] = *(const float4*)(bptr0);
    if (bhas1) bv[1] = *(const float4*)(bptr1);

    int buf = 0;
    for (int kt = 0; kt < K; kt += BK) {
#pragma unroll
        for (int i = 0; i < 2; ++i) {
            uint4 u;
            u.x = f2tf32(av[i].x);
            u.y = f2tf32(av[i].y);
            u.z = f2tf32(av[i].z);
            u.w = f2tf32(av[i].w);
            *(uint4*)&As[buf][arowv[i] * SPAD + acol4 * 4] = u;
        }
        {
            uint4 u;
            u.x = f2tf32(bv[0].x);
            u.y = f2tf32(bv[0].y);
            u.z = f2tf32(bv[0].z);
            u.w = f2tf32(bv[0].w);
            *(uint4*)&Bs[buf][brow0 * SPAD + (tid & 3) * 4] = u;
            if (bhas1) {
                uint4 v;
                v.x = f2tf32(bv[1].x);
                v.y = f2tf32(bv[1].y);
                v.z = f2tf32(bv[1].z);
                v.w = f2tf32(bv[1].w);
                *(uint4*)&Bs[buf][brow1 * SPAD + (tid & 3) * 4] = v;
            }
        }
        __syncthreads();
        if (kt + BK < K) {
            av[0] = *(const float4*)(aptr[0] + kt + BK);
            av[1] = *(const float4*)(aptr[1] + kt + BK);
            bv[0] = *(const float4*)(bptr0 + kt + BK);
            if (bhas1) bv[1] = *(const float4*)(bptr1 + kt + BK);
        }

#pragma unroll
        for (int kk = 0; kk < 16; kk += 8) {
            uint32_t afr[2][4];
#pragma unroll
            for (int mi = 0; mi < 2; ++mi) {
                int rb = warpM * 32 + mi * 16;
                afr[mi][0] = As[buf][(rb + gr) * SPAD + kk + tg];
                afr[mi][1] = As[buf][(rb + gr + 8) * SPAD + kk + tg];
                afr[mi][2] = As[buf][(rb + gr) * SPAD + kk + tg + 4];
                afr[mi][3] = As[buf][(rb + gr + 8) * SPAD + kk + tg + 4];
            }
            uint32_t bfr[6][2];
#pragma unroll
            for (int ni = 0; ni < 6; ++ni) {
                int nb = warpN * 48 + ni * 8 + gr;
                bfr[ni][0] = Bs[buf][nb * SPAD + kk + tg];
                bfr[ni][1] = Bs[buf][nb * SPAD + kk + tg + 4];
            }
#pragma unroll
            for (int mi = 0; mi < 2; ++mi)
#pragma unroll
                for (int ni = 0; ni < 6; ++ni)
                    mma_tf32(acc[mi][ni], afr[mi], bfr[ni]);
        }
        buf ^= 1;
    }

    // ---------------- epilogue ----------------------------------------------------
#pragma unroll
    for (int mi = 0; mi < 2; ++mi) {
        int rows[2];
        rows[0] = m0 + warpM * 32 + mi * 16 + gr;
        rows[1] = rows[0] + 8;
#pragma unroll
        for (int half = 0; half < 2; ++half) {
            const int r = rows[half];
            int b_ = 0, n = 0;
            if (MODE == 0) {
                b_ = r / 343;
                n = r - b_ * 343;
            }
#pragma unroll
            for (int ni = 0; ni < 6; ++ni) {
                int c = n0 + warpN * 48 + ni * 8 + tg * 2;
                float v0 = acc[mi][ni][half * 2 + 0];
                float v1 = acc[mi][ni][half * 2 + 1];
                if (MODE == 0) {
                    int sct = c / 192;
                    int remc = c - sct * 192;
                    int hh = remc >> 5, dd = remc & 31;
                    float* dst = (sct == 0 ? g_q : (sct == 1 ? g_k : g_v)) +
                                 ((size_t)(b_ * 6 + hh) * NTOK + n) * HD + dd;
                    float e0 = 0.f, e1 = 0.f;
                    if (sct == 0) { e0 = bias1[remc]; e1 = bias1[remc + 1]; }
                    else if (sct == 2) { e0 = bias2[remc]; e1 = bias2[remc + 1]; }
                    *(float2*)dst = make_float2(v0 + e0, v1 + e1);
                } else {
                    float x0 = v0 + bias1[c], x1 = v1 + bias1[c + 1];
                    float g0 = 0.5f * x0 * (1.f + erff(x0 * 0.70710678118654752f));
                    float g1 = 0.5f * x1 * (1.f + erff(x1 * 0.70710678118654752f));
                    *(float2*)(g_hmid + (size_t)r * 768 + c) = make_float2(g0, g1);
                }
            }
        }
    }
}

// ---------------- GEMM (BN=192 full width) + fused LayerNorm + residual ----------
// MODE 0: PROJ  out_pos = window-reverse scatter; g_x1[pos] = x[pos] + LN(acc+bias)
// MODE 1: FC2   out[row] = g_x1[row] + LN(acc+bias)
// 512 threads = 16 warps (4M x 4N), BM=128, BN=192, double-buffered smem.
#define LN_ASZ (BM * SPAD)
#define LN_BSZ (192 * SPAD)
#define LN_SMEM ((2 * LN_ASZ + 2 * LN_BSZ + 128 * 4 * 2) * 4)

template <int MODE>
__global__ void __launch_bounds__(512) gemm_ln(const float* __restrict__ W,
                                               const float* __restrict__ bias,
                                               const float* __restrict__ basex,
                                               const float* __restrict__ gw,
                                               const float* __restrict__ bw,
                                               float* __restrict__ outp,
                                               int K) {
    extern __shared__ uint32_t sm[];
    uint32_t* Asm = sm;                         // 2 x LN_ASZ
    uint32_t* Bsm = sm + 2 * LN_ASZ;            // 2 x LN_BSZ
    float* part = (float*)(sm + 2 * LN_ASZ + 2 * LN_BSZ);  // [128][4][2]

    const int tid = threadIdx.x;
    const int lane = tid & 31;
    const int warp = tid >> 5;      // 0..15
    const int warpM = warp & 3;
    const int warpN = warp >> 2;    // 0..3
    const int gr = lane >> 2;
    const int tg = lane & 3;

    const int m0 = blockIdx.x * BM;

    const float* Asrc = (MODE == 0) ? g_attnout : g_hmid;
    const int arow = tid >> 2, acol4 = tid & 3;
    const float* aptr = Asrc + (size_t)(m0 + arow) * K + acol4 * 4;
    const int br0 = tid >> 2;
    const int br1 = (tid + 512) >> 2;
    const float* bptr0 = W + (size_t)br0 * K + (tid & 3) * 4;
    const float* bptr1 = W + (size_t)br1 * K + (tid & 3) * 4;
    const bool bhas1 = (tid < 256);

    float acc[2][6][4];
#pragma unroll
    for (int mi = 0; mi < 2; ++mi)
#pragma unroll
        for (int ni = 0; ni < 6; ++ni)
#pragma unroll
            for (int e = 0; e < 4; ++e) acc[mi][ni][e] = 0.f;

    float4 av, bv0, bv1;
    av = *(const float4*)(aptr);
    bv0 = *(const float4*)(bptr0);
    if (bhas1) bv1 = *(const float4*)(bptr1);

    int buf = 0;
    for (int kt = 0; kt < K; kt += BK) {
        {
            uint4 u;
            u.x = f2tf32(av.x);
            u.y = f2tf32(av.y);
            u.z = f2tf32(av.z);
            u.w = f2tf32(av.w);
            *(uint4*)&Asm[buf * LN_ASZ + arow * SPAD + acol4 * 4] = u;
            uint4 b0;
            b0.x = f2tf32(bv0.x);
            b0.y = f2tf32(bv0.y);
            b0.z = f2tf32(bv0.z);
            b0.w = f2tf32(bv0.w);
            *(uint4*)&Bsm[buf * LN_BSZ + br0 * SPAD + (tid & 3) * 4] = b0;
            if (bhas1) {
                uint4 b1;
                b1.x = f2tf32(bv1.x);
                b1.y = f2tf32(bv1.y);
                b1.z = f2tf32(bv1.z);
                b1.w = f2tf32(bv1.w);
                *(uint4*)&Bsm[buf * LN_BSZ + br1 * SPAD + (tid & 3) * 4] = b1;
            }
        }
        __syncthreads();
        if (kt + BK < K) {
            av = *(const float4*)(aptr + kt + BK);
            bv0 = *(const float4*)(bptr0 + kt + BK);
            if (bhas1) bv1 = *(const float4*)(bptr1 + kt + BK);
        }

#pragma unroll
        for (int kk = 0; kk < 16; kk += 8) {
            uint32_t afr[2][4];
#pragma unroll
            for (int mi = 0; mi < 2; ++mi) {
                int rb = warpM * 32 + mi * 16;
                afr[mi][0] = Asm[buf * LN_ASZ + (rb + gr) * SPAD + kk + tg];
                afr[mi][1] = Asm[buf * LN_ASZ + (rb + gr + 8) * SPAD + kk + tg];
                afr[mi][2] = Asm[buf * LN_ASZ + (rb + gr) * SPAD + kk + tg + 4];
                afr[mi][3] = Asm[buf * LN_ASZ + (rb + gr + 8) * SPAD + kk + tg + 4];
            }
            uint32_t bfr[6][2];
#pragma unroll
            for (int ni = 0; ni < 6; ++ni) {
                int nb = warpN * 48 + ni * 8 + gr;
                bfr[ni][0] = Bsm[buf * LN_BSZ + nb * SPAD + kk + tg];
                bfr[ni][1] = Bsm[buf * LN_BSZ + nb * SPAD + kk + tg + 4];
            }
#pragma unroll
            for (int mi = 0; mi < 2; ++mi)
#pragma unroll
                for (int ni = 0; ni < 6; ++ni)
                    mma_tf32(acc[mi][ni], afr[mi], bfr[ni]);
        }
        buf ^= 1;
    }

    // ---------------- fused bias + LN partials -------------------------------------
#pragma unroll
    for (int mi = 0; mi < 2; ++mi) {
#pragma unroll
        for (int half = 0; half < 2; ++half) {
            const int rl = warpM * 32 + mi * 16 + gr + half * 8;
            float s = 0.f, sq = 0.f;
#pragma unroll
            for (int ni = 0; ni < 6; ++ni) {
                int c = warpN * 48 + ni * 8 + tg * 2;
                float v0 = acc[mi][ni][half * 2 + 0] + bias[c];
                float v1 = acc[mi][ni][half * 2 + 1] + bias[c + 1];
                acc[mi][ni][half * 2 + 0] = v0;
                acc[mi][ni][half * 2 + 1] = v1;
                s += v0 + v1;
                sq += v0 * v0 + v1 * v1;
            }
            s += __shfl_xor_sync(FULLMASK, s, 1);
            s += __shfl_xor_sync(FULLMASK, s, 2);
            sq += __shfl_xor_sync(FULLMASK, sq, 1);
            sq += __shfl_xor_sync(FULLMASK, sq, 2);
            if (tg == 0) {
                part[(rl * 4 + warpN) * 2 + 0] = s;
                part[(rl * 4 + warpN) * 2 + 1] = sq;
            }
        }
    }
    __syncthreads();

#pragma unroll
    for (int mi = 0; mi < 2; ++mi) {
#pragma unroll
        for (int half = 0; half < 2; ++half) {
            const int rl = warpM * 32 + mi * 16 + gr + half * 8;
            const int r = m0 + rl;
            float s = 0.f, sq = 0.f;
#pragma unroll
            for (int g2 = 0; g2 < 4; ++g2) {
                s += part[(rl * 4 + g2) * 2 + 0];
                sq += part[(rl * 4 + g2) * 2 + 1];
            }
            float mean = s * (1.f / 192.f);
            float var = sq * (1.f / 192.f) - mean * mean;
            float inv = rsqrtf(var + 1e-5f);

            const float* bsrow;
            float* orow;
            if (MODE == 0) {
                int b_ = r / 343, n = r - b_ * 343;
                int bb2 = b_ >> 6, win = b_ & 63;
                int wa = win >> 4, wb = (win >> 2) & 3, wc = win & 3;
                int i3 = n / 49, j3 = (n / 7) % 7, k3 = n % 7;
                int hd_ = (wa * 7 + i3 + 3) % 28;
                int wd_ = (wb * 7 + j3 + 3) % 28;
                int dd_ = (wc * 7 + k3 + 3) % 28;
                size_t pos = ((size_t)bb2 * LTOT + (hd_ * 784 + wd_ * 28 + dd_)) * CDIM;
                bsrow = basex + pos;
                orow = g_x1 + pos;
            } else {
                bsrow = g_x1 + (size_t)r * CDIM;
                orow = outp + (size_t)r * CDIM;
            }
#pragma unroll
            for (int ni = 0; ni < 6; ++ni) {
                int c = warpN * 48 + ni * 8 + tg * 2;
                float v0 = acc[mi][ni][half * 2 + 0];
                float v1 = acc[mi][ni][half * 2 + 1];
                float2 bse = *(const float2*)(bsrow + c);
                float2 gg = *(const float2*)(gw + c);
                float2 bb = *(const float2*)(bw + c);
                float o0 = bse.x + (v0 - mean) * inv * gg.x + bb.x;
                float o1 = bse.y + (v1 - mean) * inv * gg.y + bb.y;
                *(float2*)(orow + c) = make_float2(o0, o1);
            }
        }
    }
}

// ---------------- tensor-core flash attention v3 ---------------------------------
#define KS_WORDS (384 * 36)
#define VT_WORDS (32 * 388)
#define ATTN3_SMEM ((KS_WORDS + VT_WORDS) * 4 + 512)

__global__ void __launch_bounds__(256, 2) attn3_kernel(const float* __restrict__ logit_scale) {
    extern __shared__ uint32_t asmem[];
    uint32_t* Ks = asmem;                       // [384][36]
    uint32_t* Vt = asmem + KS_WORDS;            // [32][388]
    unsigned char* region = (unsigned char*)(Vt + VT_WORDS);

    const int bh = blockIdx.x;
    const int b_ = bh / 6, h = bh - (bh / 6) * 6;
    const int tid = threadIdx.x;
    const int lane = tid & 31, warp = tid >> 5;
    const int gr = lane >> 2, tg = lane & 3;

    const size_t kvbase = (size_t)bh * (NTOK * HD);
    const float* kg = g_k + kvbase;
    const float* vg = g_v + kvbase;
    const float* qg = g_q + kvbase;

    for (int r = warp; r < 384; r += 8) {
        if (r < NTOK) {
            float v = kg[r * 32 + lane];
            float s = v * v;
#pragma unroll
            for (int o = 16; o; o >>= 1) s += __shfl_xor_sync(FULLMASK, s, o);
            float inv = 1.f / fmaxf(sqrtf(s), 1e-12f);
            Ks[r * 36 + lane] = f2tf32(v * inv);
        } else {
            Ks[r * 36 + lane] = 0u;
        }
    }
    for (int idx = tid; idx < NTOK * 32; idx += 256) {
        int j = idx >> 5, d = idx & 31;
        Vt[d * 388 + j] = f2tf32(vg[idx]);
    }
    for (int idx = tid; idx < 32 * 45; idx += 256) {
        int d = idx / 45, j = NTOK + idx - (idx / 45) * 45;
        Vt[d * 388 + j] = 0u;
    }
    const int win = b_ & 63;
    const int wa = win >> 4, wb = (win >> 2) & 3, wc = win & 3;
    const bool maskedw = (wa == 3) || (wb == 3) || (wc == 3);
    if (maskedw) {
        for (int t = tid; t < 384; t += 256) {
            if (t < NTOK) {
                int ih = t / 49, iw = (t / 7) % 7, id = t % 7;
                int rH = (wa < 3) ? 0 : ((ih < 4) ? 1 : 2);
                int rW = (wb < 3) ? 0 : ((iw < 4) ? 1 : 2);
                int rD = (wc < 3) ? 0 : ((id < 4) ? 1 : 2);
                region[t] = (unsigned char)(rH * 9 + rW * 3 + rD);
            } else {
                region[t] = 0;
            }
        }
    }
    __syncthreads();

    const float scale = __expf(fminf(logit_scale[h], 4.6051701859880914f));
    const float* rpbh = g_rpb + (size_t)h * (343 * RPBS);

    for (int rb = 0; rb < 3; ++rb) {
        const int r0 = rb * 128 + warp * 16;
        if (r0 >= NTOK) continue;

        const int r_lo = r0 + gr, r_hi = r0 + gr + 8;
        const bool v_lo = r_lo < NTOK, v_hi = r_hi < NTOK;

        float qf[4][4];
        const float* qlo = qg + (size_t)(v_lo ? r_lo : 0) * 32;
        const float* qhi = qg + (size_t)(v_hi ? r_hi : 0) * 32;
#pragma unroll
        for (int kk = 0; kk < 4; ++kk) {
            qf[kk][0] = v_lo ? qlo[kk * 8 + tg] : 0.f;
            qf[kk][1] = v_hi ? qhi[kk * 8 + tg] : 0.f;
            qf[kk][2] = v_lo ? qlo[kk * 8 + tg + 4] : 0.f;
            qf[kk][3] = v_hi ? qhi[kk * 8 + tg + 4] : 0.f;
        }
        float s0 = 0.f, s1 = 0.f;
#pragma unroll
        for (int kk = 0; kk < 4; ++kk) {
            s0 += qf[kk][0] * qf[kk][0] + qf[kk][2] * qf[kk][2];
            s1 += qf[kk][1] * qf[kk][1] + qf[kk][3] * qf[kk][3];
        }
        s0 += __shfl_xor_sync(FULLMASK, s0, 1);
        s0 += __shfl_xor_sync(FULLMASK, s0, 2);
        s1 += __shfl_xor_sync(FULLMASK, s1, 1);
        s1 += __shfl_xor_sync(FULLMASK, s1, 2);
        const float i0 = scale / fmaxf(sqrtf(s0), 1e-12f);
        const float i1 = scale / fmaxf(sqrtf(s1), 1e-12f);
        uint32_t aQ[4][4];
#pragma unroll
        for (int kk = 0; kk < 4; ++kk) {
            aQ[kk][0] = f2tf32(qf[kk][0] * i0);
            aQ[kk][1] = f2tf32(qf[kk][1] * i1);
            aQ[kk][2] = f2tf32(qf[kk][2] * i0);
            aQ[kk][3] = f2tf32(qf[kk][3] * i1);
        }

        unsigned char rq0 = 0, rq1 = 0;
        if (maskedw) {
            rq0 = region[v_lo ? r_lo : (NTOK - 1)];
            rq1 = region[v_hi ? r_hi : (NTOK - 1)];
        }
        const float* rpr_lo = rpbh + (size_t)(v_lo ? r_lo : 0) * RPBS;
        const float* rpr_hi = rpbh + (size_t)(v_hi ? r_hi : 0) * RPBS;

        float m0 = -1e30f, m1 = -1e30f, l0 = 0.f, l1 = 0.f;
        float o[4][4];
#pragma unroll
        for (int nt = 0; nt < 4; ++nt)
#pragma unroll
            for (int e = 0; e < 4; ++e) o[nt][e] = 0.f;

        for (int ch = 0; ch < 6; ++ch) {
            const int j0 = ch * 64;
            float s[8][4];
#pragma unroll
            for (int nt = 0; nt < 8; ++nt)
#pragma unroll
                for (int e = 0; e < 4; ++e) s[nt][e] = 0.f;
#pragma unroll
            for (int kk = 0; kk < 4; ++kk) {
#pragma unroll
                for (int nt = 0; nt < 8; ++nt) {
                    uint32_t bb[2];
                    bb[0] = Ks[(j0 + nt * 8 + gr) * 36 + kk * 8 + tg];
                    bb[1] = Ks[(j0 + nt * 8 + gr) * 36 + kk * 8 + tg + 4];
                    mma_tf32(s[nt], aQ[kk], bb);
                }
            }
            float rm0 = -1e30f, rm1 = -1e30f;
#pragma unroll
            for (int nt = 0; nt < 8; ++nt) {
                const int jc = j0 + nt * 8 + tg * 2;
                float2 blo = *(const float2*)(rpr_lo + jc);
                float2 bhi = *(const float2*)(rpr_hi + jc);
                float t0 = s[nt][0] + blo.x;
                float t1 = s[nt][1] + blo.y;
                float t2 = s[nt][2] + bhi.x;
                float t3 = s[nt][3] + bhi.y;
                if (maskedw) {
                    unsigned char rk0 = region[jc];
                    unsigned char rk1 = region[jc + 1];
                    if (rk0 != rq0) t0 -= 100.f;
                    if (rk1 != rq0) t1 -= 100.f;
                    if (rk0 != rq1) t2 -= 100.f;
                    if (rk1 != rq1) t3 -= 100.f;
                }
                if (ch == 5) {
                    if (jc >= NTOK) { t0 = t2 = -1e30f; }
                    if (jc + 1 >= NTOK) { t1 = t3 = -1e30f; }
                }
                if (!v_lo) { t0 = t1 = -1e30f; }
                if (!v_hi) { t2 = t3 = -1e30f; }
                s[nt][0] = t0;
                s[nt][1] = t1;
                s[nt][2] = t2;
                s[nt][3] = t3;
                rm0 = fmaxf(rm0, fmaxf(t0, t1));
                rm1 = fmaxf(rm1, fmaxf(t2, t3));
            }
            rm0 = fmaxf(rm0, __shfl_xor_sync(FULLMASK, rm0, 1));
            rm0 = fmaxf(rm0, __shfl_xor_sync(FULLMASK, rm0, 2));
            rm1 = fmaxf(rm1, __shfl_xor_sync(FULLMASK, rm1, 1));
            rm1 = fmaxf(rm1, __shfl_xor_sync(FULLMASK, rm1, 2));
            const float mn0 = fmaxf(m0, rm0), mn1 = fmaxf(m1, rm1);
            const float sf0 = __expf(m0 - mn0), sf1 = __expf(m1 - mn1);
            m0 = mn0;
            m1 = mn1;
            float rs0 = 0.f, rs1 = 0.f;
#pragma unroll
            for (int nt = 0; nt < 8; ++nt) {
                float p0 = __expf(s[nt][0] - mn0);
                float p1 = __expf(s[nt][1] - mn0);
                float p2 = __expf(s[nt][2] - mn1);
                float p3 = __expf(s[nt][3] - mn1);
                rs0 += p0 + p1;
                rs1 += p2 + p3;
                s[nt][0] = p0;
                s[nt][1] = p1;
                s[nt][2] = p2;
                s[nt][3] = p3;
            }
            rs0 += __shfl_xor_sync(FULLMASK, rs0, 1);
            rs0 += __shfl_xor_sync(FULLMASK, rs0, 2);
            rs1 += __shfl_xor_sync(FULLMASK, rs1, 1);
            rs1 += __shfl_xor_sync(FULLMASK, rs1, 2);
            l0 = l0 * sf0 + rs0;
            l1 = l1 * sf1 + rs1;
#pragma unroll
            for (int nt = 0; nt < 4; ++nt) {
                o[nt][0] *= sf0;
                o[nt][1] *= sf0;
                o[nt][2] *= sf1;
                o[nt][3] *= sf1;
            }
            const int src0 = (lane & ~3) | (tg >> 1);
            const int src2 = src0 + 2;
            const bool odd = (tg & 1);
#pragma unroll
            for (int kk = 0; kk < 8; ++kk) {
                float v00 = __shfl_sync(FULLMASK, s[kk][0], src0);
                float v01 = __shfl_sync(FULLMASK, s[kk][1], src0);
                float v20 = __shfl_sync(FULLMASK, s[kk][0], src2);
                float v21 = __shfl_sync(FULLMASK, s[kk][1], src2);
                float v10 = __shfl_sync(FULLMASK, s[kk][2], src0);
                float v11 = __shfl_sync(FULLMASK, s[kk][3], src0);
                float v30 = __shfl_sync(FULLMASK, s[kk][2], src2);
                float v31 = __shfl_sync(FULLMASK, s[kk][3], src2);
                uint32_t aP[4];
                aP[0] = f2tf32(odd ? v01 : v00);
                aP[1] = f2tf32(odd ? v11 : v10);
                aP[2] = f2tf32(odd ? v21 : v20);
                aP[3] = f2tf32(odd ? v31 : v30);
#pragma unroll
                for (int nt = 0; nt < 4; ++nt) {
                    uint32_t bb[2];
                    bb[0] = Vt[(nt * 8 + gr) * 388 + j0 + kk * 8 + tg];
                    bb[1] = Vt[(nt * 8 + gr) * 388 + j0 + kk * 8 + tg + 4];
                    mma_tf32(o[nt], aP, bb);
                }
            }
        }

        if (v_lo) {
            const float il0 = 1.f / l0;
            float* dst = g_attnout + ((size_t)b_ * NTOK + r_lo) * CDIM + h * HD;
#pragma unroll
            for (int nt = 0; nt < 4; ++nt)
                *(float2*)(dst + nt * 8 + tg * 2) =
                    make_float2(o[nt][0] * il0, o[nt][1] * il0);
        }
        if (v_hi) {
            const float il1 = 1.f / l1;
            float* dst = g_attnout + ((size_t)b_ * NTOK + r_hi) * CDIM + h * HD;
#pragma unroll
            for (int nt = 0; nt < 4; ++nt)
                *(float2*)(dst + nt * 8 + tg * 2) =
                    make_float2(o[nt][2] * il1, o[nt][3] * il1);
        }
    }
}

// ---------------- launch ---------------------------------------------------------
extern "C" void kernel_launch(void* const* d_in, const int* in_sizes, int n_in,
                              void* d_out, int out_size) {
    (void)in_sizes; (void)n_in; (void)out_size;
    const float* x = (const float*)d_in[0];
    const float* qkv_w = (const float*)d_in[1];
    const float* q_bias = (const float*)d_in[2];
    const float* v_bias = (const float*)d_in[3];
    const float* logit_scale = (const float*)d_in[4];
    const float* cpb_w1 = (const float*)d_in[5];
    const float* cpb_b1 = (const float*)d_in[6];
    const float* cpb_w2 = (const float*)d_in[7];
    const float* proj_w = (const float*)d_in[8];
    const float* proj_b = (const float*)d_in[9];
    const float* norm1_g = (const float*)d_in[10];
    const float* norm1_b = (const float*)d_in[11];
    const float* fc1_w = (const float*)d_in[12];
    const float* fc1_b = (const float*)d_in[13];
    const float* fc2_w = (const float*)d_in[14];
    const float* fc2_b = (const float*)d_in[15];
    const float* norm2_g = (const float*)d_in[16];
    const float* norm2_b = (const float*)d_in[17];
    float* out = (float*)d_out;

    static bool attr_done = false;
    if (!attr_done) {
        cudaFuncSetAttribute(attn3_kernel, cudaFuncAttributeMaxDynamicSharedMemorySize,
                             ATTN3_SMEM);
        cudaFuncSetAttribute(gemm_ln<0>, cudaFuncAttributeMaxDynamicSharedMemorySize,
                             LN_SMEM);
        cudaFuncSetAttribute(gemm_ln<1>, cudaFuncAttributeMaxDynamicSharedMemorySize,
                             LN_SMEM);
        attr_done = true;
    }

    // constants
    cpb_kernel<<<2197, 256>>>(cpb_w1, cpb_b1, cpb_w2);
    rpb_kernel<<<888, 256>>>();

    // qkv (fused shift + window gather): M=43904, N=576, K=192
    mma_gemm<0><<<dim3(6, 343), 256>>>(x, qkv_w, q_bias, v_bias, 192);

    // attention (tensor-core flash, register P)
    attn3_kernel<<<768, 256, ATTN3_SMEM>>>(logit_scale);

    // proj + LN + residual (fused window reverse + roll scatter): N=192, K=192
    gemm_ln<0><<<343, 512, LN_SMEM>>>(proj_w, proj_b, x, norm1_g, norm1_b, nullptr, 192);

    // fc1: N=768, K=192 (GELU)
    mma_gemm<2><<<dim3(8, 343), 256>>>(nullptr, fc1_w, fc1_b, nullptr, 192);

    // fc2 + LN + residual: N=192, K=768
    gemm_ln<1><<<343, 512, LN_SMEM>>>(fc2_w, fc2_b, nullptr, norm2_g, norm2_b, out, 768);
}

// round 7
// speedup vs baseline: 3.2841x; 1.0647x over previous
#include <cuda_runtime.h>
#include <math.h>
#include <stdint.h>

#define FULLMASK 0xffffffffu

// problem dims
#define NTOK   343
#define NHEAD  6
#define HD     32
#define CDIM   192
#define LTOT   21952   // 28^3
#define NWIN   128     // 2 batches * 64 windows
#define NROWS  43904   // 128*343 = 2*21952
#define RPBS   344     // padded rpb row stride (8B-aligned float2 loads)

// ---------------- device scratch ------------------------------------------------
__device__ float g_hb[2197 * 6];
__device__ __align__(16) float g_rpb[6 * 343 * RPBS];
__device__ __align__(16) float g_q[(size_t)NWIN * NHEAD * NTOK * HD];
__device__ __align__(16) float g_k[(size_t)NWIN * NHEAD * NTOK * HD];
__device__ __align__(16) float g_v[(size_t)NWIN * NHEAD * NTOK * HD];
__device__ __align__(16) float g_attnout[(size_t)NWIN * NTOK * CDIM];   // tf32-rounded
__device__ __align__(16) float g_x1[(size_t)2 * LTOT * CDIM];           // fp32
__device__ __align__(16) float g_x1t[(size_t)2 * LTOT * CDIM];          // tf32-rounded
__device__ __align__(16) float g_xt[(size_t)2 * LTOT * CDIM];           // tf32-rounded
__device__ __align__(16) float g_hmid[(size_t)NROWS * 768];             // tf32-rounded
__device__ __align__(16) float g_wq[576 * 192];
__device__ __align__(16) float g_wp[192 * 192];
__device__ __align__(16) float g_w1[768 * 192];
__device__ __align__(16) float g_w2[192 * 768];

// ---------------- helpers -------------------------------------------------------
__device__ __forceinline__ uint32_t f2tf32(float x) {
    uint32_t r;
    asm("cvt.rna.tf32.f32 %0, %1;" : "=r"(r) : "f"(x));
    return r;
}

__device__ __forceinline__ void mma_tf32(float* c, const uint32_t* a, const uint32_t* b) {
    asm volatile(
        "mma.sync.aligned.m16n8k8.row.col.f32.tf32.tf32.f32 "
        "{%0,%1,%2,%3}, {%4,%5,%6,%7}, {%8,%9}, {%0,%1,%2,%3};"
        : "+f"(c[0]), "+f"(c[1]), "+f"(c[2]), "+f"(c[3])
        : "r"(a[0]), "r"(a[1]), "r"(a[2]), "r"(a[3]), "r"(b[0]), "r"(b[1]));
}

__device__ __forceinline__ uint32_t smem_u32(const void* p) {
    uint32_t a;
    asm("{ .reg .u64 t; cvta.to.shared.u64 t, %1; cvt.u32.u64 %0, t; }" : "=r"(a) : "l"(p));
    return a;
}

__device__ __forceinline__ void cp16(uint32_t dst, const void* src) {
    asm volatile("cp.async.ca.shared.global [%0], [%1], 16;" :: "r"(dst), "l"(src));
}
#define CP_COMMIT() asm volatile("cp.async.commit_group;" ::: "memory")
#define CP_WAIT1()  asm volatile("cp.async.wait_group 1;" ::: "memory")

// ---------------- tf32 convert kernel --------------------------------------------
__global__ void __launch_bounds__(256) cvt_kernel(const float* __restrict__ src,
                                                  int which, int n4) {
    float* d;
    if (which == 0) d = g_xt;
    else if (which == 1) d = g_wq;
    else if (which == 2) d = g_wp;
    else if (which == 3) d = g_w1;
    else d = g_w2;
    for (int i = blockIdx.x * blockDim.x + threadIdx.x; i < n4;
         i += gridDim.x * blockDim.x) {
        float4 v = ((const float4*)src)[i];
        uint4 u;
        u.x = f2tf32(v.x);
        u.y = f2tf32(v.y);
        u.z = f2tf32(v.z);
        u.w = f2tf32(v.w);
        ((uint4*)d)[i] = u;
    }
}

// ---------------- CPB MLP -------------------------------------------------------
__device__ __forceinline__ float cpb_coord(int i) {
    float v = (float)(i - 6) * (8.0f / 6.0f);
    float av = fabsf(v);
    float r = log2f(av + 1.0f) * (1.0f / 3.0f);
    return (v < 0.f) ? -r : r;
}

__global__ void __launch_bounds__(256) cpb_kernel(const float* __restrict__ w1,
                                                  const float* __restrict__ b1,
                                                  const float* __restrict__ w2) {
    __shared__ float hid[512];
    int t = blockIdx.x;
    int a = t / 169;
    int rem = t - a * 169;
    int b = rem / 13;
    int c = rem - b * 13;
    float c0 = cpb_coord(a), c1 = cpb_coord(b), c2 = cpb_coord(c);
    for (int j = threadIdx.x; j < 512; j += blockDim.x) {
        float hv = c0 * w1[j * 3 + 0] + c1 * w1[j * 3 + 1] + c2 * w1[j * 3 + 2] + b1[j];
        hid[j] = fmaxf(hv, 0.f);
    }
    __syncthreads();
    if (threadIdx.x < 192) {
        int hh = threadIdx.x >> 5, lane = threadIdx.x & 31;
        float s = 0.f;
        for (int j = lane; j < 512; j += 32) s += hid[j] * w2[hh * 512 + j];
#pragma unroll
        for (int off = 16; off; off >>= 1) s += __shfl_xor_sync(FULLMASK, s, off);
        if (lane == 0) g_hb[t * 6 + hh] = s;
    }
}

__global__ void rpb_kernel() {
    const int total = 6 * 343 * RPBS;
    for (int idx = blockIdx.x * blockDim.x + threadIdx.x; idx < total;
         idx += gridDim.x * blockDim.x) {
        int hh = idx / (343 * RPBS);
        int rem = idx - hh * (343 * RPBS);
        int i = rem / RPBS;
        int j = rem - i * RPBS;
        if (j >= 343) {
            g_rpb[idx] = 0.f;
            continue;
        }
        int dh = i / 49 - j / 49 + 6;
        int dw = (i / 7) % 7 - (j / 7) % 7 + 6;
        int dd = i % 7 - j % 7 + 6;
        int tix = (dh * 13 + dw) * 13 + dd;
        float v = g_hb[tix * 6 + hh];
        g_rpb[idx] = 16.f / (1.f + __expf(-v));
    }
}

// ---------------- tf32 mma GEMM, cp.async 3-stage pipeline -----------------------
// MODE 0: QKV (A = g_xt gathered; W = g_wq; out -> g_q/g_k/g_v + biases)
// MODE 2: FC1 (A = g_x1t; W = g_w1; out -> g_hmid tf32-rounded with GELU)
#define BM 128
#define BN 96
#define BK 16
#define SPAD 20
#define A_WORDS (BM * SPAD)
#define B_WORDS (BN * SPAD)
#define GT_SMEM (3 * (A_WORDS + B_WORDS) * 4)

template <int MODE>
__global__ void __launch_bounds__(256) mma_gemm(const float* __restrict__ bias1,
                                                const float* __restrict__ bias2,
                                                int K) {
    extern __shared__ uint32_t sh[];
    uint32_t* As = sh;                    // 3 stages of A
    uint32_t* Bs = sh + 3 * A_WORDS;      // 3 stages of B
    const uint32_t sbA = smem_u32(As);
    const uint32_t sbB = smem_u32(Bs);

    const int tid = threadIdx.x;
    const int lane = tid & 31;
    const int warp = tid >> 5;
    const int warpM = warp & 3;
    const int warpN = warp >> 2;
    const int gr = lane >> 2;
    const int tg = lane & 3;

    const int m0 = blockIdx.y * BM;
    const int n0 = blockIdx.x * BN;

    const float* Asrc = (MODE == 0) ? g_xt : g_x1t;
    const float* W = (MODE == 0) ? g_wq : g_w1;

    const int acol4 = tid & 3;
    const float* aptr[2];
    uint32_t aoffB[2];
#pragma unroll
    for (int i = 0; i < 2; ++i) {
        int idx = tid + i * 256;
        int arow = idx >> 2;
        int rho = m0 + arow;
        const float* p;
        if (MODE == 0) {
            int b_ = rho / 343, n = rho - b_ * 343;
            int bb = b_ >> 6, win = b_ & 63;
            int wa = win >> 4, wb = (win >> 2) & 3, wc = win & 3;
            int ii = n / 49, jj = (n / 7) % 7, kk = n % 7;
            int hs = (wa * 7 + ii + 3) % 28;
            int ws = (wb * 7 + jj + 3) % 28;
            int ds = (wc * 7 + kk + 3) % 28;
            p = Asrc + ((size_t)bb * LTOT + (hs * 784 + ws * 28 + ds)) * CDIM;
        } else {
            p = Asrc + (size_t)rho * K;
        }
        aptr[i] = p + acol4 * 4;
        aoffB[i] = (arow * SPAD + acol4 * 4) * 4;
    }
    const int brow0 = tid >> 2;
    const int brow1 = (tid + 256) >> 2;
    const float* bptr0 = W + (size_t)(n0 + brow0) * K + (tid & 3) * 4;
    const float* bptr1 = W + (size_t)(n0 + brow1) * K + (tid & 3) * 4;
    const uint32_t boff0 = (brow0 * SPAD + (tid & 3) * 4) * 4;
    const uint32_t boff1 = (brow1 * SPAD + (tid & 3) * 4) * 4;
    const bool bhas1 = (tid < 128);

    float acc[2][6][4];
#pragma unroll
    for (int mi = 0; mi < 2; ++mi)
#pragma unroll
        for (int ni = 0; ni < 6; ++ni)
#pragma unroll
            for (int e = 0; e < 4; ++e) acc[mi][ni][e] = 0.f;

    const int ntiles = K >> 4;
    // prologue: tiles 0,1
#pragma unroll
    for (int s = 0; s < 2; ++s) {
        const int kt = s * BK;
        cp16(sbA + s * (A_WORDS * 4) + aoffB[0], aptr[0] + kt);
        cp16(sbA + s * (A_WORDS * 4) + aoffB[1], aptr[1] + kt);
        cp16(sbB + s * (B_WORDS * 4) + boff0, bptr0 + kt);
        if (bhas1) cp16(sbB + s * (B_WORDS * 4) + boff1, bptr1 + kt);
        CP_COMMIT();
    }

    for (int t = 0; t < ntiles; ++t) {
        const int buf = t % 3;
        CP_WAIT1();
        __syncthreads();

        const uint32_t* Ab = As + buf * A_WORDS;
        const uint32_t* Bb = Bs + buf * B_WORDS;
#pragma unroll
        for (int kk = 0; kk < 16; kk += 8) {
            uint32_t afr[2][4];
#pragma unroll
            for (int mi = 0; mi < 2; ++mi) {
                int rb = warpM * 32 + mi * 16;
                afr[mi][0] = Ab[(rb + gr) * SPAD + kk + tg];
                afr[mi][1] = Ab[(rb + gr + 8) * SPAD + kk + tg];
                afr[mi][2] = Ab[(rb + gr) * SPAD + kk + tg + 4];
                afr[mi][3] = Ab[(rb + gr + 8) * SPAD + kk + tg + 4];
            }
            uint32_t bfr[6][2];
#pragma unroll
            for (int ni = 0; ni < 6; ++ni) {
                int nb = warpN * 48 + ni * 8 + gr;
                bfr[ni][0] = Bb[nb * SPAD + kk + tg];
                bfr[ni][1] = Bb[nb * SPAD + kk + tg + 4];
            }
#pragma unroll
            for (int mi = 0; mi < 2; ++mi)
#pragma unroll
                for (int ni = 0; ni < 6; ++ni)
                    mma_tf32(acc[mi][ni], afr[mi], bfr[ni]);
        }

        const int tn = t + 2;
        if (tn < ntiles) {
            const int s = tn % 3;
            const int kt = tn * BK;
            cp16(sbA + s * (A_WORDS * 4) + aoffB[0], aptr[0] + kt);
            cp16(sbA + s * (A_WORDS * 4) + aoffB[1], aptr[1] + kt);
            cp16(sbB + s * (B_WORDS * 4) + boff0, bptr0 + kt);
            if (bhas1) cp16(sbB + s * (B_WORDS * 4) + boff1, bptr1 + kt);
        }
        CP_COMMIT();
    }

    // ---------------- epilogue ----------------------------------------------------
#pragma unroll
    for (int mi = 0; mi < 2; ++mi) {
        int rows[2];
        rows[0] = m0 + warpM * 32 + mi * 16 + gr;
        rows[1] = rows[0] + 8;
#pragma unroll
        for (int half = 0; half < 2; ++half) {
            const int r = rows[half];
            int b_ = 0, n = 0;
            if (MODE == 0) {
                b_ = r / 343;
                n = r - b_ * 343;
            }
#pragma unroll
            for (int ni = 0; ni < 6; ++ni) {
                int c = n0 + warpN * 48 + ni * 8 + tg * 2;
                float v0 = acc[mi][ni][half * 2 + 0];
                float v1 = acc[mi][ni][half * 2 + 1];
                if (MODE == 0) {
                    int sct = c / 192;
                    int remc = c - sct * 192;
                    int hh = remc >> 5, dd = remc & 31;
                    float* dst = (sct == 0 ? g_q : (sct == 1 ? g_k : g_v)) +
                                 ((size_t)(b_ * 6 + hh) * NTOK + n) * HD + dd;
                    float e0 = 0.f, e1 = 0.f;
                    if (sct == 0) { e0 = bias1[remc]; e1 = bias1[remc + 1]; }
                    else if (sct == 2) { e0 = bias2[remc]; e1 = bias2[remc + 1]; }
                    *(float2*)dst = make_float2(v0 + e0, v1 + e1);
                } else {
                    float x0 = v0 + bias1[c], x1 = v1 + bias1[c + 1];
                    float g0 = 0.5f * x0 * (1.f + erff(x0 * 0.70710678118654752f));
                    float g1 = 0.5f * x1 * (1.f + erff(x1 * 0.70710678118654752f));
                    *(float2*)(g_hmid + (size_t)r * 768 + c) =
                        make_float2(__uint_as_float(f2tf32(g0)),
                                    __uint_as_float(f2tf32(g1)));
                }
            }
        }
    }
}

// ---------------- GEMM (BN=192) + fused LayerNorm + residual, cp.async -----------
// MODE 0: PROJ  g_x1[pos] = x[pos] + LN(acc+bias) (window-reverse scatter); also g_x1t
// MODE 1: FC2   out[row] = g_x1[row] + LN(acc+bias)
#define LNB_WORDS (192 * SPAD)
#define LN_SMEM ((3 * (A_WORDS + LNB_WORDS) + 128 * 4 * 2) * 4)

template <int MODE>
__global__ void __launch_bounds__(512) gemm_ln(const float* __restrict__ bias,
                                               const float* __restrict__ basex,
                                               const float* __restrict__ gw,
                                               const float* __restrict__ bw,
                                               float* __restrict__ outp,
                                               int K) {
    extern __shared__ uint32_t sh[];
    uint32_t* Asm = sh;
    uint32_t* Bsm = sh + 3 * A_WORDS;
    float* part = (float*)(sh + 3 * A_WORDS + 3 * LNB_WORDS);  // [128][4][2]
    const uint32_t sbA = smem_u32(Asm);
    const uint32_t sbB = smem_u32(Bsm);

    const int tid = threadIdx.x;
    const int lane = tid & 31;
    const int warp = tid >> 5;
    const int warpM = warp & 3;
    const int warpN = warp >> 2;
    const int gr = lane >> 2;
    const int tg = lane & 3;

    const int m0 = blockIdx.x * BM;

    const float* Asrc = (MODE == 0) ? g_attnout : g_hmid;
    const float* W = (MODE == 0) ? g_wp : g_w2;

    const int arow = tid >> 2, acol4 = tid & 3;
    const float* aptr = Asrc + (size_t)(m0 + arow) * K + acol4 * 4;
    const uint32_t aoff = (arow * SPAD + acol4 * 4) * 4;
    const int br0 = tid >> 2;
    const int br1 = (tid + 512) >> 2;
    const float* bptr0 = W + (size_t)br0 * K + (tid & 3) * 4;
    const float* bptr1 = W + (size_t)br1 * K + (tid & 3) * 4;
    const uint32_t boff0 = (br0 * SPAD + (tid & 3) * 4) * 4;
    const uint32_t boff1 = (br1 * SPAD + (tid & 3) * 4) * 4;
    const bool bhas1 = (tid < 256);

    float acc[2][6][4];
#pragma unroll
    for (int mi = 0; mi < 2; ++mi)
#pragma unroll
        for (int ni = 0; ni < 6; ++ni)
#pragma unroll
            for (int e = 0; e < 4; ++e) acc[mi][ni][e] = 0.f;

    const int ntiles = K >> 4;
#pragma unroll
    for (int s = 0; s < 2; ++s) {
        const int kt = s * BK;
        cp16(sbA + s * (A_WORDS * 4) + aoff, aptr + kt);
        cp16(sbB + s * (LNB_WORDS * 4) + boff0, bptr0 + kt);
        if (bhas1) cp16(sbB + s * (LNB_WORDS * 4) + boff1, bptr1 + kt);
        CP_COMMIT();
    }

    for (int t = 0; t < ntiles; ++t) {
        const int buf = t % 3;
        CP_WAIT1();
        __syncthreads();

        const uint32_t* Ab = Asm + buf * A_WORDS;
        const uint32_t* Bb = Bsm + buf * LNB_WORDS;
#pragma unroll
        for (int kk = 0; kk < 16; kk += 8) {
            uint32_t afr[2][4];
#pragma unroll
            for (int mi = 0; mi < 2; ++mi) {
                int rb = warpM * 32 + mi * 16;
                afr[mi][0] = Ab[(rb + gr) * SPAD + kk + tg];
                afr[mi][1] = Ab[(rb + gr + 8) * SPAD + kk + tg];
                afr[mi][2] = Ab[(rb + gr) * SPAD + kk + tg + 4];
                afr[mi][3] = Ab[(rb + gr + 8) * SPAD + kk + tg + 4];
            }
            uint32_t bfr[6][2];
#pragma unroll
            for (int ni = 0; ni < 6; ++ni) {
                int nb = warpN * 48 + ni * 8 + gr;
                bfr[ni][0] = Bb[nb * SPAD + kk + tg];
                bfr[ni][1] = Bb[nb * SPAD + kk + tg + 4];
            }
#pragma unroll
            for (int mi = 0; mi < 2; ++mi)
#pragma unroll
                for (int ni = 0; ni < 6; ++ni)
                    mma_tf32(acc[mi][ni], afr[mi], bfr[ni]);
        }

        const int tn = t + 2;
        if (tn < ntiles) {
            const int s = tn % 3;
            const int kt = tn * BK;
            cp16(sbA + s * (A_WORDS * 4) + aoff, aptr + kt);
            cp16(sbB + s * (LNB_WORDS * 4) + boff0, bptr0 + kt);
            if (bhas1) cp16(sbB + s * (LNB_WORDS * 4) + boff1, bptr1 + kt);
        }
        CP_COMMIT();
    }
    __syncthreads();

    // ---------------- fused bias + LN partials -------------------------------------
#pragma unroll
    for (int mi = 0; mi < 2; ++mi) {
#pragma unroll
        for (int half = 0; half < 2; ++half) {
            const int rl = warpM * 32 + mi * 16 + gr + half * 8;
            float s = 0.f, sq = 0.f;
#pragma unroll
            for (int ni = 0; ni < 6; ++ni) {
                int c = warpN * 48 + ni * 8 + tg * 2;
                float v0 = acc[mi][ni][half * 2 + 0] + bias[c];
                float v1 = acc[mi][ni][half * 2 + 1] + bias[c + 1];
                acc[mi][ni][half * 2 + 0] = v0;
                acc[mi][ni][half * 2 + 1] = v1;
                s += v0 + v1;
                sq += v0 * v0 + v1 * v1;
            }
            s += __shfl_xor_sync(FULLMASK, s, 1);
            s += __shfl_xor_sync(FULLMASK, s, 2);
            sq += __shfl_xor_sync(FULLMASK, sq, 1);
            sq += __shfl_xor_sync(FULLMASK, sq, 2);
            if (tg == 0) {
                part[(rl * 4 + warpN) * 2 + 0] = s;
                part[(rl * 4 + warpN) * 2 + 1] = sq;
            }
        }
    }
    __syncthreads();

#pragma unroll
    for (int mi = 0; mi < 2; ++mi) {
#pragma unroll
        for (int half = 0; half < 2; ++half) {
            const int rl = warpM * 32 + mi * 16 + gr + half * 8;
            const int r = m0 + rl;
            float s = 0.f, sq = 0.f;
#pragma unroll
            for (int g2 = 0; g2 < 4; ++g2) {
                s += part[(rl * 4 + g2) * 2 + 0];
                sq += part[(rl * 4 + g2) * 2 + 1];
            }
            float mean = s * (1.f / 192.f);
            float var = sq * (1.f / 192.f) - mean * mean;
            float inv = rsqrtf(var + 1e-5f);

            const float* bsrow;
            float* orow;
            float* orow2 = nullptr;
            if (MODE == 0) {
                int b_ = r / 343, n = r - b_ * 343;
                int bb2 = b_ >> 6, win = b_ & 63;
                int wa = win >> 4, wb = (win >> 2) & 3, wc = win & 3;
                int i3 = n / 49, j3 = (n / 7) % 7, k3 = n % 7;
                int hd_ = (wa * 7 + i3 + 3) % 28;
                int wd_ = (wb * 7 + j3 + 3) % 28;
                int dd_ = (wc * 7 + k3 + 3) % 28;
                size_t pos = ((size_t)bb2 * LTOT + (hd_ * 784 + wd_ * 28 + dd_)) * CDIM;
                bsrow = basex + pos;
                orow = g_x1 + pos;
                orow2 = g_x1t + pos;
            } else {
                bsrow = g_x1 + (size_t)r * CDIM;
                orow = outp + (size_t)r * CDIM;
            }
#pragma unroll
            for (int ni = 0; ni < 6; ++ni) {
                int c = warpN * 48 + ni * 8 + tg * 2;
                float v0 = acc[mi][ni][half * 2 + 0];
                float v1 = acc[mi][ni][half * 2 + 1];
                float2 bse = *(const float2*)(bsrow + c);
                float2 gg = *(const float2*)(gw + c);
                float2 bb = *(const float2*)(bw + c);
                float o0 = bse.x + (v0 - mean) * inv * gg.x + bb.x;
                float o1 = bse.y + (v1 - mean) * inv * gg.y + bb.y;
                *(float2*)(orow + c) = make_float2(o0, o1);
                if (MODE == 0)
                    *(float2*)(orow2 + c) =
                        make_float2(__uint_as_float(f2tf32(o0)),
                                    __uint_as_float(f2tf32(o1)));
            }
        }
    }
}

// ---------------- tensor-core flash attention v3 ---------------------------------
#define KS_WORDS (384 * 36)
#define VT_WORDS (32 * 388)
#define ATTN3_SMEM ((KS_WORDS + VT_WORDS) * 4 + 512)

__global__ void __launch_bounds__(256, 2) attn3_kernel(const float* __restrict__ logit_scale) {
    extern __shared__ uint32_t asmem[];
    uint32_t* Ks = asmem;                       // [384][36]
    uint32_t* Vt = asmem + KS_WORDS;            // [32][388]
    unsigned char* region = (unsigned char*)(Vt + VT_WORDS);

    const int bh = blockIdx.x;
    const int b_ = bh / 6, h = bh - (bh / 6) * 6;
    const int tid = threadIdx.x;
    const int lane = tid & 31, warp = tid >> 5;
    const int gr = lane >> 2, tg = lane & 3;

    const size_t kvbase = (size_t)bh * (NTOK * HD);
    const float* kg = g_k + kvbase;
    const float* vg = g_v + kvbase;
    const float* qg = g_q + kvbase;

    for (int r = warp; r < 384; r += 8) {
        if (r < NTOK) {
            float v = kg[r * 32 + lane];
            float s = v * v;
#pragma unroll
            for (int o = 16; o; o >>= 1) s += __shfl_xor_sync(FULLMASK, s, o);
            float inv = 1.f / fmaxf(sqrtf(s), 1e-12f);
            Ks[r * 36 + lane] = f2tf32(v * inv);
        } else {
            Ks[r * 36 + lane] = 0u;
        }
    }
    for (int idx = tid; idx < NTOK * 32; idx += 256) {
        int j = idx >> 5, d = idx & 31;
        Vt[d * 388 + j] = f2tf32(vg[idx]);
    }
    for (int idx = tid; idx < 32 * 45; idx += 256) {
        int d = idx / 45, j = NTOK + idx - (idx / 45) * 45;
        Vt[d * 388 + j] = 0u;
    }
    const int win = b_ & 63;
    const int wa = win >> 4, wb = (win >> 2) & 3, wc = win & 3;
    const bool maskedw = (wa == 3) || (wb == 3) || (wc == 3);
    if (maskedw) {
        for (int t = tid; t < 384; t += 256) {
            if (t < NTOK) {
                int ih = t / 49, iw = (t / 7) % 7, id = t % 7;
                int rH = (wa < 3) ? 0 : ((ih < 4) ? 1 : 2);
                int rW = (wb < 3) ? 0 : ((iw < 4) ? 1 : 2);
                int rD = (wc < 3) ? 0 : ((id < 4) ? 1 : 2);
                region[t] = (unsigned char)(rH * 9 + rW * 3 + rD);
            } else {
                region[t] = 0;
            }
        }
    }
    __syncthreads();

    const float scale = __expf(fminf(logit_scale[h], 4.6051701859880914f));
    const float* rpbh = g_rpb + (size_t)h * (343 * RPBS);

    for (int rb = 0; rb < 3; ++rb) {
        const int r0 = rb * 128 + warp * 16;
        if (r0 >= NTOK) continue;

        const int r_lo = r0 + gr, r_hi = r0 + gr + 8;
        const bool v_lo = r_lo < NTOK, v_hi = r_hi < NTOK;

        float qf[4][4];
        const float* qlo = qg + (size_t)(v_lo ? r_lo : 0) * 32;
        const float* qhi = qg + (size_t)(v_hi ? r_hi : 0) * 32;
#pragma unroll
        for (int kk = 0; kk < 4; ++kk) {
            qf[kk][0] = v_lo ? qlo[kk * 8 + tg] : 0.f;
            qf[kk][1] = v_hi ? qhi[kk * 8 + tg] : 0.f;
            qf[kk][2] = v_lo ? qlo[kk * 8 + tg + 4] : 0.f;
            qf[kk][3] = v_hi ? qhi[kk * 8 + tg + 4] : 0.f;
        }
        float s0 = 0.f, s1 = 0.f;
#pragma unroll
        for (int kk = 0; kk < 4; ++kk) {
            s0 += qf[kk][0] * qf[kk][0] + qf[kk][2] * qf[kk][2];
            s1 += qf[kk][1] * qf[kk][1] + qf[kk][3] * qf[kk][3];
        }
        s0 += __shfl_xor_sync(FULLMASK, s0, 1);
        s0 += __shfl_xor_sync(FULLMASK, s0, 2);
        s1 += __shfl_xor_sync(FULLMASK, s1, 1);
        s1 += __shfl_xor_sync(FULLMASK, s1, 2);
        const float i0 = scale / fmaxf(sqrtf(s0), 1e-12f);
        const float i1 = scale / fmaxf(sqrtf(s1), 1e-12f);
        uint32_t aQ[4][4];
#pragma unroll
        for (int kk = 0; kk < 4; ++kk) {
            aQ[kk][0] = f2tf32(qf[kk][0] * i0);
            aQ[kk][1] = f2tf32(qf[kk][1] * i1);
            aQ[kk][2] = f2tf32(qf[kk][2] * i0);
            aQ[kk][3] = f2tf32(qf[kk][3] * i1);
        }

        unsigned char rq0 = 0, rq1 = 0;
        if (maskedw) {
            rq0 = region[v_lo ? r_lo : (NTOK - 1)];
            rq1 = region[v_hi ? r_hi : (NTOK - 1)];
        }
        const float* rpr_lo = rpbh + (size_t)(v_lo ? r_lo : 0) * RPBS;
        const float* rpr_hi = rpbh + (size_t)(v_hi ? r_hi : 0) * RPBS;

        float m0 = -1e30f, m1 = -1e30f, l0 = 0.f, l1 = 0.f;
        float o[4][4];
#pragma unroll
        for (int nt = 0; nt < 4; ++nt)
#pragma unroll
            for (int e = 0; e < 4; ++e) o[nt][e] = 0.f;

        for (int ch = 0; ch < 6; ++ch) {
            const int j0 = ch * 64;
            float s[8][4];
#pragma unroll
            for (int nt = 0; nt < 8; ++nt)
#pragma unroll
                for (int e = 0; e < 4; ++e) s[nt][e] = 0.f;
#pragma unroll
            for (int kk = 0; kk < 4; ++kk) {
#pragma unroll
                for (int nt = 0; nt < 8; ++nt) {
                    uint32_t bb[2];
                    bb[0] = Ks[(j0 + nt * 8 + gr) * 36 + kk * 8 + tg];
                    bb[1] = Ks[(j0 + nt * 8 + gr) * 36 + kk * 8 + tg + 4];
                    mma_tf32(s[nt], aQ[kk], bb);
                }
            }
            float rm0 = -1e30f, rm1 = -1e30f;
#pragma unroll
            for (int nt = 0; nt < 8; ++nt) {
                const int jc = j0 + nt * 8 + tg * 2;
                float2 blo = *(const float2*)(rpr_lo + jc);
                float2 bhi = *(const float2*)(rpr_hi + jc);
                float t0 = s[nt][0] + blo.x;
                float t1 = s[nt][1] + blo.y;
                float t2 = s[nt][2] + bhi.x;
                float t3 = s[nt][3] + bhi.y;
                if (maskedw) {
                    unsigned char rk0 = region[jc];
                    unsigned char rk1 = region[jc + 1];
                    if (rk0 != rq0) t0 -= 100.f;
                    if (rk1 != rq0) t1 -= 100.f;
                    if (rk0 != rq1) t2 -= 100.f;
                    if (rk1 != rq1) t3 -= 100.f;
                }
                if (ch == 5) {
                    if (jc >= NTOK) { t0 = t2 = -1e30f; }
                    if (jc + 1 >= NTOK) { t1 = t3 = -1e30f; }
                }
                if (!v_lo) { t0 = t1 = -1e30f; }
                if (!v_hi) { t2 = t3 = -1e30f; }
                s[nt][0] = t0;
                s[nt][1] = t1;
                s[nt][2] = t2;
                s[nt][3] = t3;
                rm0 = fmaxf(rm0, fmaxf(t0, t1));
                rm1 = fmaxf(rm1, fmaxf(t2, t3));
            }
            rm0 = fmaxf(rm0, __shfl_xor_sync(FULLMASK, rm0, 1));
            rm0 = fmaxf(rm0, __shfl_xor_sync(FULLMASK, rm0, 2));
            rm1 = fmaxf(rm1, __shfl_xor_sync(FULLMASK, rm1, 1));
            rm1 = fmaxf(rm1, __shfl_xor_sync(FULLMASK, rm1, 2));
            const float mn0 = fmaxf(m0, rm0), mn1 = fmaxf(m1, rm1);
            const float sf0 = __expf(m0 - mn0), sf1 = __expf(m1 - mn1);
            m0 = mn0;
            m1 = mn1;
            float rs0 = 0.f, rs1 = 0.f;
#pragma unroll
            for (int nt = 0; nt < 8; ++nt) {
                float p0 = __expf(s[nt][0] - mn0);
                float p1 = __expf(s[nt][1] - mn0);
                float p2 = __expf(s[nt][2] - mn1);
                float p3 = __expf(s[nt][3] - mn1);
                rs0 += p0 + p1;
                rs1 += p2 + p3;
                s[nt][0] = p0;
                s[nt][1] = p1;
                s[nt][2] = p2;
                s[nt][3] = p3;
            }
            rs0 += __shfl_xor_sync(FULLMASK, rs0, 1);
            rs0 += __shfl_xor_sync(FULLMASK, rs0, 2);
            rs1 += __shfl_xor_sync(FULLMASK, rs1, 1);
            rs1 += __shfl_xor_sync(FULLMASK, rs1, 2);
            l0 = l0 * sf0 + rs0;
            l1 = l1 * sf1 + rs1;
#pragma unroll
            for (int nt = 0; nt < 4; ++nt) {
                o[nt][0] *= sf0;
                o[nt][1] *= sf0;
                o[nt][2] *= sf1;
                o[nt][3] *= sf1;
            }
            const int src0 = (lane & ~3) | (tg >> 1);
            const int src2 = src0 + 2;
            const bool odd = (tg & 1);
#pragma unroll
            for (int kk = 0; kk < 8; ++kk) {
                float v00 = __shfl_sync(FULLMASK, s[kk][0], src0);
                float v01 = __shfl_sync(FULLMASK, s[kk][1], src0);
                float v20 = __shfl_sync(FULLMASK, s[kk][0], src2);
                float v21 = __shfl_sync(FULLMASK, s[kk][1], src2);
                float v10 = __shfl_sync(FULLMASK, s[kk][2], src0);
                float v11 = __shfl_sync(FULLMASK, s[kk][3], src0);
                float v30 = __shfl_sync(FULLMASK, s[kk][2], src2);
                float v31 = __shfl_sync(FULLMASK, s[kk][3], src2);
                uint32_t aP[4];
                aP[0] = f2tf32(odd ? v01 : v00);
                aP[1] = f2tf32(odd ? v11 : v10);
                aP[2] = f2tf32(odd ? v21 : v20);
                aP[3] = f2tf32(odd ? v31 : v30);
#pragma unroll
                for (int nt = 0; nt < 4; ++nt) {
                    uint32_t bb[2];
                    bb[0] = Vt[(nt * 8 + gr) * 388 + j0 + kk * 8 + tg];
                    bb[1] = Vt[(nt * 8 + gr) * 388 + j0 + kk * 8 + tg + 4];
                    mma_tf32(o[nt], aP, bb);
                }
            }
        }

        if (v_lo) {
            const float il0 = 1.f / l0;
            float* dst = g_attnout + ((size_t)b_ * NTOK + r_lo) * CDIM + h * HD;
#pragma unroll
            for (int nt = 0; nt < 4; ++nt)
                *(float2*)(dst + nt * 8 + tg * 2) =
                    make_float2(__uint_as_float(f2tf32(o[nt][0] * il0)),
                                __uint_as_float(f2tf32(o[nt][1] * il0)));
        }
        if (v_hi) {
            const float il1 = 1.f / l1;
            float* dst = g_attnout + ((size_t)b_ * NTOK + r_hi) * CDIM + h * HD;
#pragma unroll
            for (int nt = 0; nt < 4; ++nt)
                *(float2*)(dst + nt * 8 + tg * 2) =
                    make_float2(__uint_as_float(f2tf32(o[nt][2] * il1)),
                                __uint_as_float(f2tf32(o[nt][3] * il1)));
        }
    }
}

// ---------------- launch ---------------------------------------------------------
extern "C" void kernel_launch(void* const* d_in, const int* in_sizes, int n_in,
                              void* d_out, int out_size) {
    (void)in_sizes; (void)n_in; (void)out_size;
    const float* x = (const float*)d_in[0];
    const float* qkv_w = (const float*)d_in[1];
    const float* q_bias = (const float*)d_in[2];
    const float* v_bias = (const float*)d_in[3];
    const float* logit_scale = (const float*)d_in[4];
    const float* cpb_w1 = (const float*)d_in[5];
    const float* cpb_b1 = (const float*)d_in[6];
    const float* cpb_w2 = (const float*)d_in[7];
    const float* proj_w = (const float*)d_in[8];
    const float* proj_b = (const float*)d_in[9];
    const float* norm1_g = (const float*)d_in[10];
    const float* norm1_b = (const float*)d_in[11];
    const float* fc1_w = (const float*)d_in[12];
    const float* fc1_b = (const float*)d_in[13];
    const float* fc2_w = (const float*)d_in[14];
    const float* fc2_b = (const float*)d_in[15];
    const float* norm2_g = (const float*)d_in[16];
    const float* norm2_b = (const float*)d_in[17];
    float* out = (float*)d_out;

    static bool attr_done = false;
    if (!attr_done) {
        cudaFuncSetAttribute(attn3_kernel, cudaFuncAttributeMaxDynamicSharedMemorySize,
                             ATTN3_SMEM);
        cudaFuncSetAttribute(mma_gemm<0>, cudaFuncAttributeMaxDynamicSharedMemorySize,
                             GT_SMEM);
        cudaFuncSetAttribute(mma_gemm<2>, cudaFuncAttributeMaxDynamicSharedMemorySize,
                             GT_SMEM);
        cudaFuncSetAttribute(gemm_ln<0>, cudaFuncAttributeMaxDynamicSharedMemorySize,
                             LN_SMEM);
        cudaFuncSetAttribute(gemm_ln<1>, cudaFuncAttributeMaxDynamicSharedMemorySize,
                             LN_SMEM);
        attr_done = true;
    }

    // tf32 pre-conversion of GEMM operands
    cvt_kernel<<<1024, 256>>>(x, 0, (2 * LTOT * CDIM) / 4);
    cvt_kernel<<<108, 256>>>(qkv_w, 1, (576 * 192) / 4);
    cvt_kernel<<<36, 256>>>(proj_w, 2, (192 * 192) / 4);
    cvt_kernel<<<144, 256>>>(fc1_w, 3, (768 * 192) / 4);
    cvt_kernel<<<144, 256>>>(fc2_w, 4, (192 * 768) / 4);

    // constants
    cpb_kernel<<<2197, 256>>>(cpb_w1, cpb_b1, cpb_w2);
    rpb_kernel<<<888, 256>>>();

    // qkv (fused shift + window gather): M=43904, N=576, K=192
    mma_gemm<0><<<dim3(6, 343), 256, GT_SMEM>>>(q_bias, v_bias, 192);

    // attention (tensor-core flash, register P)
    attn3_kernel<<<768, 256, ATTN3_SMEM>>>(logit_scale);

    // proj + LN + residual (fused window reverse + roll scatter): N=192, K=192
    gemm_ln<0><<<343, 512, LN_SMEM>>>(proj_b, x, norm1_g, norm1_b, nullptr, 192);

    // fc1: N=768, K=192 (GELU)
    mma_gemm<2><<<dim3(8, 343), 256, GT_SMEM>>>(fc1_b, nullptr, 192);

    // fc2 + LN + residual: N=192, K=768
    gemm_ln<1><<<343, 512, LN_SMEM>>>(fc2_b, nullptr, norm2_g, norm2_b, out, 768);
}

// round 8
// speedup vs baseline: 3.6050x; 1.0977x over previous
#include <cuda_runtime.h>
#include <math.h>
#include <stdint.h>

#define FULLMASK 0xffffffffu

// problem dims
#define NTOK   343
#define NHEAD  6
#define HD     32
#define CDIM   192
#define LTOT   21952   // 28^3
#define NWIN   128     // 2 batches * 64 windows
#define NROWS  43904   // 128*343 = 2*21952
#define RPBS   344     // padded rpb row stride (8B-aligned float2 loads)

// ---------------- device scratch ------------------------------------------------
__device__ float g_hb[2197 * 6];
__device__ __align__(16) float g_rpb[6 * 343 * RPBS];
__device__ __align__(16) float g_q[(size_t)NWIN * NHEAD * NTOK * HD];
__device__ __align__(16) float g_k[(size_t)NWIN * NHEAD * NTOK * HD];
__device__ __align__(16) float g_v[(size_t)NWIN * NHEAD * NTOK * HD];
__device__ __align__(16) float g_attnout[(size_t)NWIN * NTOK * CDIM];   // tf32-rounded
__device__ __align__(16) float g_x1[(size_t)2 * LTOT * CDIM];           // fp32
__device__ __align__(16) float g_x1t[(size_t)2 * LTOT * CDIM];          // tf32-rounded
__device__ __align__(16) float g_xt[(size_t)2 * LTOT * CDIM];           // tf32-rounded
__device__ __align__(16) float g_hmid[(size_t)NROWS * 768];             // tf32-rounded
__device__ __align__(16) float g_wq[576 * 192];
__device__ __align__(16) float g_wp[192 * 192];
__device__ __align__(16) float g_w1[768 * 192];
__device__ __align__(16) float g_w2[192 * 768];

// ---------------- helpers -------------------------------------------------------
__device__ __forceinline__ uint32_t f2tf32(float x) {
    uint32_t r;
    asm("cvt.rna.tf32.f32 %0, %1;" : "=r"(r) : "f"(x));
    return r;
}

__device__ __forceinline__ void mma_tf32(float* c, const uint32_t* a, const uint32_t* b) {
    asm volatile(
        "mma.sync.aligned.m16n8k8.row.col.f32.tf32.tf32.f32 "
        "{%0,%1,%2,%3}, {%4,%5,%6,%7}, {%8,%9}, {%0,%1,%2,%3};"
        : "+f"(c[0]), "+f"(c[1]), "+f"(c[2]), "+f"(c[3])
        : "r"(a[0]), "r"(a[1]), "r"(a[2]), "r"(a[3]), "r"(b[0]), "r"(b[1]));
}

__device__ __forceinline__ uint32_t smem_u32(const void* p) {
    uint32_t a;
    asm("{ .reg .u64 t; cvta.to.shared.u64 t, %1; cvt.u32.u64 %0, t; }" : "=r"(a) : "l"(p));
    return a;
}

__device__ __forceinline__ void cp16(uint32_t dst, const void* src) {
    asm volatile("cp.async.ca.shared.global [%0], [%1], 16;" :: "r"(dst), "l"(src));
}
#define CP_COMMIT() asm volatile("cp.async.commit_group;" ::: "memory")
#define CP_WAIT1()  asm volatile("cp.async.wait_group 1;" ::: "memory")

// ---------------- fused tf32 convert kernel --------------------------------------
__global__ void __launch_bounds__(256) cvt_all(const float* __restrict__ x,
                                               const float* __restrict__ wq,
                                               const float* __restrict__ wp,
                                               const float* __restrict__ w1,
                                               const float* __restrict__ w2) {
    const int N0 = 2107392;            // x: 2*LTOT*CDIM/4
    const int N1 = N0 + 27648;         // wq
    const int N2 = N1 + 9216;          // wp
    const int N3 = N2 + 36864;         // w1
    const int N4 = N3 + 36864;         // w2
    for (int i = blockIdx.x * blockDim.x + threadIdx.x; i < N4;
         i += gridDim.x * blockDim.x) {
        const float4* s;
        uint4* d;
        int off;
        if (i < N0) { s = (const float4*)x; d = (uint4*)g_xt; off = i; }
        else if (i < N1) { s = (const float4*)wq; d = (uint4*)g_wq; off = i - N0; }
        else if (i < N2) { s = (const float4*)wp; d = (uint4*)g_wp; off = i - N1; }
        else if (i < N3) { s = (const float4*)w1; d = (uint4*)g_w1; off = i - N2; }
        else { s = (const float4*)w2; d = (uint4*)g_w2; off = i - N3; }
        float4 v = s[off];
        uint4 u;
        u.x = f2tf32(v.x);
        u.y = f2tf32(v.y);
        u.z = f2tf32(v.z);
        u.w = f2tf32(v.w);
        d[off] = u;
    }
}

// ---------------- CPB MLP -------------------------------------------------------
__device__ __forceinline__ float cpb_coord(int i) {
    float v = (float)(i - 6) * (8.0f / 6.0f);
    float av = fabsf(v);
    float r = log2f(av + 1.0f) * (1.0f / 3.0f);
    return (v < 0.f) ? -r : r;
}

__global__ void __launch_bounds__(256) cpb_kernel(const float* __restrict__ w1,
                                                  const float* __restrict__ b1,
                                                  const float* __restrict__ w2) {
    __shared__ float hid[512];
    int t = blockIdx.x;
    int a = t / 169;
    int rem = t - a * 169;
    int b = rem / 13;
    int c = rem - b * 13;
    float c0 = cpb_coord(a), c1 = cpb_coord(b), c2 = cpb_coord(c);
    for (int j = threadIdx.x; j < 512; j += blockDim.x) {
        float hv = c0 * w1[j * 3 + 0] + c1 * w1[j * 3 + 1] + c2 * w1[j * 3 + 2] + b1[j];
        hid[j] = fmaxf(hv, 0.f);
    }
    __syncthreads();
    if (threadIdx.x < 192) {
        int hh = threadIdx.x >> 5, lane = threadIdx.x & 31;
        float s = 0.f;
        for (int j = lane; j < 512; j += 32) s += hid[j] * w2[hh * 512 + j];
#pragma unroll
        for (int off = 16; off; off >>= 1) s += __shfl_xor_sync(FULLMASK, s, off);
        if (lane == 0) g_hb[t * 6 + hh] = s;
    }
}

__global__ void rpb_kernel() {
    const int total = 6 * 343 * RPBS;
    for (int idx = blockIdx.x * blockDim.x + threadIdx.x; idx < total;
         idx += gridDim.x * blockDim.x) {
        int hh = idx / (343 * RPBS);
        int rem = idx - hh * (343 * RPBS);
        int i = rem / RPBS;
        int j = rem - i * RPBS;
        if (j >= 343) {
            g_rpb[idx] = 0.f;
            continue;
        }
        int dh = i / 49 - j / 49 + 6;
        int dw = (i / 7) % 7 - (j / 7) % 7 + 6;
        int dd = i % 7 - j % 7 + 6;
        int tix = (dh * 13 + dw) * 13 + dd;
        float v = g_hb[tix * 6 + hh];
        g_rpb[idx] = 16.f / (1.f + __expf(-v));
    }
}

// ---------------- tf32 mma GEMM, BK=32, cp.async 3-stage pipeline ----------------
// MODE 0: QKV (A = g_xt gathered; W = g_wq; out -> g_q/g_k/g_v + biases)
// MODE 2: FC1 (A = g_x1t; W = g_w1; out -> g_hmid tf32-rounded with GELU)
#define BM 128
#define BN 96
#define BK2 32
#define SPAD2 36
#define A2_WORDS (BM * SPAD2)      // 4608
#define B2_WORDS (BN * SPAD2)      // 3456
#define GT_SMEM (3 * (A2_WORDS + B2_WORDS) * 4)   // 96768

template <int MODE>
__global__ void __launch_bounds__(256) mma_gemm(const float* __restrict__ bias1,
                                                const float* __restrict__ bias2,
                                                int K) {
    extern __shared__ uint32_t sh[];
    uint32_t* As = sh;
    uint32_t* Bs = sh + 3 * A2_WORDS;
    const uint32_t sbA = smem_u32(As);
    const uint32_t sbB = smem_u32(Bs);

    const int tid = threadIdx.x;
    const int lane = tid & 31;
    const int warp = tid >> 5;
    const int warpM = warp & 3;
    const int warpN = warp >> 2;
    const int gr = lane >> 2;
    const int tg = lane & 3;

    const int m0 = blockIdx.y * BM;
    const int n0 = blockIdx.x * BN;

    const float* Asrc = (MODE == 0) ? g_xt : g_x1t;
    const float* W = (MODE == 0) ? g_wq : g_w1;

    // A: 4 chunks of 16B per thread per tile
    const float* aptr[4];
    uint32_t aoffB[4];
#pragma unroll
    for (int i = 0; i < 4; ++i) {
        int idx = tid + i * 256;
        int arow = idx >> 3, c8 = idx & 7;
        int rho = m0 + arow;
        const float* p;
        if (MODE == 0) {
            int b_ = rho / 343, n = rho - b_ * 343;
            int bb = b_ >> 6, win = b_ & 63;
            int wa = win >> 4, wb = (win >> 2) & 3, wc = win & 3;
            int ii = n / 49, jj = (n / 7) % 7, kk = n % 7;
            int hs = (wa * 7 + ii + 3) % 28;
            int ws = (wb * 7 + jj + 3) % 28;
            int ds = (wc * 7 + kk + 3) % 28;
            p = Asrc + ((size_t)bb * LTOT + (hs * 784 + ws * 28 + ds)) * CDIM;
        } else {
            p = Asrc + (size_t)rho * K;
        }
        aptr[i] = p + c8 * 4;
        aoffB[i] = (arow * SPAD2 + c8 * 4) * 4;
    }
    // B: 3 chunks per thread per tile
    const float* bptr[3];
    uint32_t boff[3];
#pragma unroll
    for (int i = 0; i < 3; ++i) {
        int idx = tid + i * 256;
        int brow = idx >> 3, c8 = idx & 7;
        bptr[i] = W + (size_t)(n0 + brow) * K + c8 * 4;
        boff[i] = (brow * SPAD2 + c8 * 4) * 4;
    }

    float acc[2][6][4];
#pragma unroll
    for (int mi = 0; mi < 2; ++mi)
#pragma unroll
        for (int ni = 0; ni < 6; ++ni)
#pragma unroll
            for (int e = 0; e < 4; ++e) acc[mi][ni][e] = 0.f;

    const int ntiles = K >> 5;
#pragma unroll
    for (int s = 0; s < 2; ++s) {
        const int kt = s * BK2;
#pragma unroll
        for (int i = 0; i < 4; ++i) cp16(sbA + s * (A2_WORDS * 4) + aoffB[i], aptr[i] + kt);
#pragma unroll
        for (int i = 0; i < 3; ++i) cp16(sbB + s * (B2_WORDS * 4) + boff[i], bptr[i] + kt);
        CP_COMMIT();
    }

    for (int t = 0; t < ntiles; ++t) {
        const int buf = t % 3;
        CP_WAIT1();
        __syncthreads();

        const uint32_t* Ab = As + buf * A2_WORDS;
        const uint32_t* Bb = Bs + buf * B2_WORDS;
#pragma unroll
        for (int kk = 0; kk < 32; kk += 8) {
            uint32_t afr[2][4];
#pragma unroll
            for (int mi = 0; mi < 2; ++mi) {
                int rb = warpM * 32 + mi * 16;
                afr[mi][0] = Ab[(rb + gr) * SPAD2 + kk + tg];
                afr[mi][1] = Ab[(rb + gr + 8) * SPAD2 + kk + tg];
                afr[mi][2] = Ab[(rb + gr) * SPAD2 + kk + tg + 4];
                afr[mi][3] = Ab[(rb + gr + 8) * SPAD2 + kk + tg + 4];
            }
            uint32_t bfr[6][2];
#pragma unroll
            for (int ni = 0; ni < 6; ++ni) {
                int nb = warpN * 48 + ni * 8 + gr;
                bfr[ni][0] = Bb[nb * SPAD2 + kk + tg];
                bfr[ni][1] = Bb[nb * SPAD2 + kk + tg + 4];
            }
#pragma unroll
            for (int mi = 0; mi < 2; ++mi)
#pragma unroll
                for (int ni = 0; ni < 6; ++ni)
                    mma_tf32(acc[mi][ni], afr[mi], bfr[ni]);
        }

        const int tn = t + 2;
        if (tn < ntiles) {
            const int s = tn % 3;
            const int kt = tn * BK2;
#pragma unroll
            for (int i = 0; i < 4; ++i)
                cp16(sbA + s * (A2_WORDS * 4) + aoffB[i], aptr[i] + kt);
#pragma unroll
            for (int i = 0; i < 3; ++i)
                cp16(sbB + s * (B2_WORDS * 4) + boff[i], bptr[i] + kt);
        }
        CP_COMMIT();
    }

    // ---------------- epilogue ----------------------------------------------------
#pragma unroll
    for (int mi = 0; mi < 2; ++mi) {
        int rows[2];
        rows[0] = m0 + warpM * 32 + mi * 16 + gr;
        rows[1] = rows[0] + 8;
#pragma unroll
        for (int half = 0; half < 2; ++half) {
            const int r = rows[half];
            int b_ = 0, n = 0;
            if (MODE == 0) {
                b_ = r / 343;
                n = r - b_ * 343;
            }
#pragma unroll
            for (int ni = 0; ni < 6; ++ni) {
                int c = n0 + warpN * 48 + ni * 8 + tg * 2;
                float v0 = acc[mi][ni][half * 2 + 0];
                float v1 = acc[mi][ni][half * 2 + 1];
                if (MODE == 0) {
                    int sct = c / 192;
                    int remc = c - sct * 192;
                    int hh = remc >> 5, dd = remc & 31;
                    float* dst = (sct == 0 ? g_q : (sct == 1 ? g_k : g_v)) +
                                 ((size_t)(b_ * 6 + hh) * NTOK + n) * HD + dd;
                    float e0 = 0.f, e1 = 0.f;
                    if (sct == 0) { e0 = bias1[remc]; e1 = bias1[remc + 1]; }
                    else if (sct == 2) { e0 = bias2[remc]; e1 = bias2[remc + 1]; }
                    *(float2*)dst = make_float2(v0 + e0, v1 + e1);
                } else {
                    float x0 = v0 + bias1[c], x1 = v1 + bias1[c + 1];
                    float g0 = 0.5f * x0 * (1.f + erff(x0 * 0.70710678118654752f));
                    float g1 = 0.5f * x1 * (1.f + erff(x1 * 0.70710678118654752f));
                    *(float2*)(g_hmid + (size_t)r * 768 + c) =
                        make_float2(__uint_as_float(f2tf32(g0)),
                                    __uint_as_float(f2tf32(g1)));
                }
            }
        }
    }
}

// ---------------- GEMM (BN=192) + fused LayerNorm + residual, BK=32 --------------
// MODE 0: PROJ  g_x1[pos] = x[pos] + LN(acc+bias) (window-reverse scatter); also g_x1t
// MODE 1: FC2   out[row] = g_x1[row] + LN(acc+bias)
#define B2L_WORDS (192 * SPAD2)    // 6912
#define LN_SMEM ((3 * (A2_WORDS + B2L_WORDS) + 128 * 4 * 2) * 4)

template <int MODE>
__global__ void __launch_bounds__(512) gemm_ln(const float* __restrict__ bias,
                                               const float* __restrict__ basex,
                                               const float* __restrict__ gw,
                                               const float* __restrict__ bw,
                                               float* __restrict__ outp,
                                               int K) {
    extern __shared__ uint32_t sh[];
    uint32_t* Asm = sh;
    uint32_t* Bsm = sh + 3 * A2_WORDS;
    float* part = (float*)(sh + 3 * A2_WORDS + 3 * B2L_WORDS);  // [128][4][2]
    const uint32_t sbA = smem_u32(Asm);
    const uint32_t sbB = smem_u32(Bsm);

    const int tid = threadIdx.x;
    const int lane = tid & 31;
    const int warp = tid >> 5;
    const int warpM = warp & 3;
    const int warpN = warp >> 2;
    const int gr = lane >> 2;
    const int tg = lane & 3;

    const int m0 = blockIdx.x * BM;

    const float* Asrc = (MODE == 0) ? g_attnout : g_hmid;
    const float* W = (MODE == 0) ? g_wp : g_w2;

    // A: 2 chunks; B: 3 chunks
    const float* aptr[2];
    uint32_t aoff[2];
#pragma unroll
    for (int i = 0; i < 2; ++i) {
        int idx = tid + i * 512;
        int arow = idx >> 3, c8 = idx & 7;
        aptr[i] = Asrc + (size_t)(m0 + arow) * K + c8 * 4;
        aoff[i] = (arow * SPAD2 + c8 * 4) * 4;
    }
    const float* bptr[3];
    uint32_t boff[3];
#pragma unroll
    for (int i = 0; i < 3; ++i) {
        int idx = tid + i * 512;
        int brow = idx >> 3, c8 = idx & 7;
        bptr[i] = W + (size_t)brow * K + c8 * 4;
        boff[i] = (brow * SPAD2 + c8 * 4) * 4;
    }

    float acc[2][6][4];
#pragma unroll
    for (int mi = 0; mi < 2; ++mi)
#pragma unroll
        for (int ni = 0; ni < 6; ++ni)
#pragma unroll
            for (int e = 0; e < 4; ++e) acc[mi][ni][e] = 0.f;

    const int ntiles = K >> 5;
#pragma unroll
    for (int s = 0; s < 2; ++s) {
        const int kt = s * BK2;
#pragma unroll
        for (int i = 0; i < 2; ++i) cp16(sbA + s * (A2_WORDS * 4) + aoff[i], aptr[i] + kt);
#pragma unroll
        for (int i = 0; i < 3; ++i) cp16(sbB + s * (B2L_WORDS * 4) + boff[i], bptr[i] + kt);
        CP_COMMIT();
    }

    for (int t = 0; t < ntiles; ++t) {
        const int buf = t % 3;
        CP_WAIT1();
        __syncthreads();

        const uint32_t* Ab = Asm + buf * A2_WORDS;
        const uint32_t* Bb = Bsm + buf * B2L_WORDS;
#pragma unroll
        for (int kk = 0; kk < 32; kk += 8) {
            uint32_t afr[2][4];
#pragma unroll
            for (int mi = 0; mi < 2; ++mi) {
                int rb = warpM * 32 + mi * 16;
                afr[mi][0] = Ab[(rb + gr) * SPAD2 + kk + tg];
                afr[mi][1] = Ab[(rb + gr + 8) * SPAD2 + kk + tg];
                afr[mi][2] = Ab[(rb + gr) * SPAD2 + kk + tg + 4];
                afr[mi][3] = Ab[(rb + gr + 8) * SPAD2 + kk + tg + 4];
            }
            uint32_t bfr[6][2];
#pragma unroll
            for (int ni = 0; ni < 6; ++ni) {
                int nb = warpN * 48 + ni * 8 + gr;
                bfr[ni][0] = Bb[nb * SPAD2 + kk + tg];
                bfr[ni][1] = Bb[nb * SPAD2 + kk + tg + 4];
            }
#pragma unroll
            for (int mi = 0; mi < 2; ++mi)
#pragma unroll
                for (int ni = 0; ni < 6; ++ni)
                    mma_tf32(acc[mi][ni], afr[mi], bfr[ni]);
        }

        const int tn = t + 2;
        if (tn < ntiles) {
            const int s = tn % 3;
            const int kt = tn * BK2;
#pragma unroll
            for (int i = 0; i < 2; ++i)
                cp16(sbA + s * (A2_WORDS * 4) + aoff[i], aptr[i] + kt);
#pragma unroll
            for (int i = 0; i < 3; ++i)
                cp16(sbB + s * (B2L_WORDS * 4) + boff[i], bptr[i] + kt);
        }
        CP_COMMIT();
    }
    __syncthreads();

    // ---------------- fused bias + LN partials -------------------------------------
#pragma unroll
    for (int mi = 0; mi < 2; ++mi) {
#pragma unroll
        for (int half = 0; half < 2; ++half) {
            const int rl = warpM * 32 + mi * 16 + gr + half * 8;
            float s = 0.f, sq = 0.f;
#pragma unroll
            for (int ni = 0; ni < 6; ++ni) {
                int c = warpN * 48 + ni * 8 + tg * 2;
                float v0 = acc[mi][ni][half * 2 + 0] + bias[c];
                float v1 = acc[mi][ni][half * 2 + 1] + bias[c + 1];
                acc[mi][ni][half * 2 + 0] = v0;
                acc[mi][ni][half * 2 + 1] = v1;
                s += v0 + v1;
                sq += v0 * v0 + v1 * v1;
            }
            s += __shfl_xor_sync(FULLMASK, s, 1);
            s += __shfl_xor_sync(FULLMASK, s, 2);
            sq += __shfl_xor_sync(FULLMASK, sq, 1);
            sq += __shfl_xor_sync(FULLMASK, sq, 2);
            if (tg == 0) {
                part[(rl * 4 + warpN) * 2 + 0] = s;
                part[(rl * 4 + warpN) * 2 + 1] = sq;
            }
        }
    }
    __syncthreads();

#pragma unroll
    for (int mi = 0; mi < 2; ++mi) {
#pragma unroll
        for (int half = 0; half < 2; ++half) {
            const int rl = warpM * 32 + mi * 16 + gr + half * 8;
            const int r = m0 + rl;
            float s = 0.f, sq = 0.f;
#pragma unroll
            for (int g2 = 0; g2 < 4; ++g2) {
                s += part[(rl * 4 + g2) * 2 + 0];
                sq += part[(rl * 4 + g2) * 2 + 1];
            }
            float mean = s * (1.f / 192.f);
            float var = sq * (1.f / 192.f) - mean * mean;
            float inv = rsqrtf(var + 1e-5f);

            const float* bsrow;
            float* orow;
            float* orow2 = nullptr;
            if (MODE == 0) {
                int b_ = r / 343, n = r - b_ * 343;
                int bb2 = b_ >> 6, win = b_ & 63;
                int wa = win >> 4, wb = (win >> 2) & 3, wc = win & 3;
                int i3 = n / 49, j3 = (n / 7) % 7, k3 = n % 7;
                int hd_ = (wa * 7 + i3 + 3) % 28;
                int wd_ = (wb * 7 + j3 + 3) % 28;
                int dd_ = (wc * 7 + k3 + 3) % 28;
                size_t pos = ((size_t)bb2 * LTOT + (hd_ * 784 + wd_ * 28 + dd_)) * CDIM;
                bsrow = basex + pos;
                orow = g_x1 + pos;
                orow2 = g_x1t + pos;
            } else {
                bsrow = g_x1 + (size_t)r * CDIM;
                orow = outp + (size_t)r * CDIM;
            }
#pragma unroll
            for (int ni = 0; ni < 6; ++ni) {
                int c = warpN * 48 + ni * 8 + tg * 2;
                float v0 = acc[mi][ni][half * 2 + 0];
                float v1 = acc[mi][ni][half * 2 + 1];
                float2 bse = *(const float2*)(bsrow + c);
                float2 gg = *(const float2*)(gw + c);
                float2 bb = *(const float2*)(bw + c);
                float o0 = bse.x + (v0 - mean) * inv * gg.x + bb.x;
                float o1 = bse.y + (v1 - mean) * inv * gg.y + bb.y;
                *(float2*)(orow + c) = make_float2(o0, o1);
                if (MODE == 0)
                    *(float2*)(orow2 + c) =
                        make_float2(__uint_as_float(f2tf32(o0)),
                                    __uint_as_float(f2tf32(o1)));
            }
        }
    }
}

// ---------------- tensor-core flash attention v4 (static max) --------------------
#define KS_WORDS (384 * 36)
#define VT_WORDS (32 * 388)
#define ATTN4_SMEM ((KS_WORDS + VT_WORDS) * 4 + 512)

__global__ void __launch_bounds__(256, 2) attn4_kernel(const float* __restrict__ logit_scale) {
    extern __shared__ uint32_t asmem[];
    uint32_t* Ks = asmem;                       // [384][36]
    uint32_t* Vt = asmem + KS_WORDS;            // [32][388]
    unsigned char* region = (unsigned char*)(Vt + VT_WORDS);

    const int bh = blockIdx.x;
    const int b_ = bh / 6, h = bh - (bh / 6) * 6;
    const int tid = threadIdx.x;
    const int lane = tid & 31, warp = tid >> 5;
    const int gr = lane >> 2, tg = lane & 3;

    const size_t kvbase = (size_t)bh * (NTOK * HD);
    const float* kg = g_k + kvbase;
    const float* vg = g_v + kvbase;
    const float* qg = g_q + kvbase;

    for (int r = warp; r < 384; r += 8) {
        if (r < NTOK) {
            float v = kg[r * 32 + lane];
            float s = v * v;
#pragma unroll
            for (int o = 16; o; o >>= 1) s += __shfl_xor_sync(FULLMASK, s, o);
            float inv = 1.f / fmaxf(sqrtf(s), 1e-12f);
            Ks[r * 36 + lane] = f2tf32(v * inv);
        } else {
            Ks[r * 36 + lane] = 0u;
        }
    }
    for (int idx = tid; idx < NTOK * 32; idx += 256) {
        int j = idx >> 5, d = idx & 31;
        Vt[d * 388 + j] = f2tf32(vg[idx]);
    }
    for (int idx = tid; idx < 32 * 45; idx += 256) {
        int d = idx / 45, j = NTOK + idx - (idx / 45) * 45;
        Vt[d * 388 + j] = 0u;
    }
    const int win = b_ & 63;
    const int wa = win >> 4, wb = (win >> 2) & 3, wc = win & 3;
    const bool maskedw = (wa == 3) || (wb == 3) || (wc == 3);
    if (maskedw) {
        for (int t = tid; t < 384; t += 256) {
            if (t < NTOK) {
                int ih = t / 49, iw = (t / 7) % 7, id = t % 7;
                int rH = (wa < 3) ? 0 : ((ih < 4) ? 1 : 2);
                int rW = (wb < 3) ? 0 : ((iw < 4) ? 1 : 2);
                int rD = (wc < 3) ? 0 : ((id < 4) ? 1 : 2);
                region[t] = (unsigned char)(rH * 9 + rW * 3 + rD);
            } else {
                region[t] = 0;
            }
        }
    }
    __syncthreads();

    const float scale = __expf(fminf(logit_scale[h], 4.6051701859880914f));
    const float Mstat = scale + 16.f;   // static logit upper bound (row max >= scale)
    const float* rpbh = g_rpb + (size_t)h * (343 * RPBS);

    for (int rb = 0; rb < 3; ++rb) {
        const int r0 = rb * 128 + warp * 16;
        if (r0 >= NTOK) continue;

        const int r_lo = r0 + gr, r_hi = r0 + gr + 8;
        const bool v_lo = r_lo < NTOK, v_hi = r_hi < NTOK;

        float qf[4][4];
        const float* qlo = qg + (size_t)(v_lo ? r_lo : 0) * 32;
        const float* qhi = qg + (size_t)(v_hi ? r_hi : 0) * 32;
#pragma unroll
        for (int kk = 0; kk < 4; ++kk) {
            qf[kk][0] = v_lo ? qlo[kk * 8 + tg] : 0.f;
            qf[kk][1] = v_hi ? qhi[kk * 8 + tg] : 0.f;
            qf[kk][2] = v_lo ? qlo[kk * 8 + tg + 4] : 0.f;
            qf[kk][3] = v_hi ? qhi[kk * 8 + tg + 4] : 0.f;
        }
        float s0 = 0.f, s1 = 0.f;
#pragma unroll
        for (int kk = 0; kk < 4; ++kk) {
            s0 += qf[kk][0] * qf[kk][0] + qf[kk][2] * qf[kk][2];
            s1 += qf[kk][1] * qf[kk][1] + qf[kk][3] * qf[kk][3];
        }
        s0 += __shfl_xor_sync(FULLMASK, s0, 1);
        s0 += __shfl_xor_sync(FULLMASK, s0, 2);
        s1 += __shfl_xor_sync(FULLMASK, s1, 1);
        s1 += __shfl_xor_sync(FULLMASK, s1, 2);
        const float i0 = scale / fmaxf(sqrtf(s0), 1e-12f);
        const float i1 = scale / fmaxf(sqrtf(s1), 1e-12f);
        uint32_t aQ[4][4];
#pragma unroll
        for (int kk = 0; kk < 4; ++kk) {
            aQ[kk][0] = f2tf32(qf[kk][0] * i0);
            aQ[kk][1] = f2tf32(qf[kk][1] * i1);
            aQ[kk][2] = f2tf32(qf[kk][2] * i0);
            aQ[kk][3] = f2tf32(qf[kk][3] * i1);
        }

        unsigned char rq0 = 0, rq1 = 0;
        if (maskedw) {
            rq0 = region[v_lo ? r_lo : (NTOK - 1)];
            rq1 = region[v_hi ? r_hi : (NTOK - 1)];
        }
        const float* rpr_lo = rpbh + (size_t)(v_lo ? r_lo : 0) * RPBS;
        const float* rpr_hi = rpbh + (size_t)(v_hi ? r_hi : 0) * RPBS;

        float l0 = 0.f, l1 = 0.f;
        float o[4][4];
#pragma unroll
        for (int nt = 0; nt < 4; ++nt)
#pragma unroll
            for (int e = 0; e < 4; ++e) o[nt][e] = 0.f;

        for (int ch = 0; ch < 6; ++ch) {
            const int j0 = ch * 64;
            float s[8][4];
#pragma unroll
            for (int nt = 0; nt < 8; ++nt)
#pragma unroll
                for (int e = 0; e < 4; ++e) s[nt][e] = 0.f;
#pragma unroll
            for (int kk = 0; kk < 4; ++kk) {
#pragma unroll
                for (int nt = 0; nt < 8; ++nt) {
                    uint32_t bb[2];
                    bb[0] = Ks[(j0 + nt * 8 + gr) * 36 + kk * 8 + tg];
                    bb[1] = Ks[(j0 + nt * 8 + gr) * 36 + kk * 8 + tg + 4];
                    mma_tf32(s[nt], aQ[kk], bb);
                }
            }
            // bias + mask + exp(static max) + per-thread sums
#pragma unroll
            for (int nt = 0; nt < 8; ++nt) {
                const int jc = j0 + nt * 8 + tg * 2;
                float2 blo = *(const float2*)(rpr_lo + jc);
                float2 bhi = *(const float2*)(rpr_hi + jc);
                float t0 = s[nt][0] + blo.x - Mstat;
                float t1 = s[nt][1] + blo.y - Mstat;
                float t2 = s[nt][2] + bhi.x - Mstat;
                float t3 = s[nt][3] + bhi.y - Mstat;
                if (maskedw) {
                    unsigned char rk0 = region[jc];
                    unsigned char rk1 = region[jc + 1];
                    if (rk0 != rq0) t0 -= 100.f;
                    if (rk1 != rq0) t1 -= 100.f;
                    if (rk0 != rq1) t2 -= 100.f;
                    if (rk1 != rq1) t3 -= 100.f;
                }
                float p0 = __expf(t0);
                float p1 = __expf(t1);
                float p2 = __expf(t2);
                float p3 = __expf(t3);
                if (ch == 5) {
                    if (jc >= NTOK) { p0 = 0.f; p2 = 0.f; }
                    if (jc + 1 >= NTOK) { p1 = 0.f; p3 = 0.f; }
                }
                l0 += p0 + p1;
                l1 += p2 + p3;
                s[nt][0] = p0;
                s[nt][1] = p1;
                s[nt][2] = p2;
                s[nt][3] = p3;
            }
            // O += P * V : acc-frag -> A-frag via intra-quad shuffles
            const int src0 = (lane & ~3) | (tg >> 1);
            const int src2 = src0 + 2;
            const bool odd = (tg & 1);
#pragma unroll
            for (int kk = 0; kk < 8; ++kk) {
                float v00 = __shfl_sync(FULLMASK, s[kk][0], src0);
                float v01 = __shfl_sync(FULLMASK, s[kk][1], src0);
                float v20 = __shfl_sync(FULLMASK, s[kk][0], src2);
                float v21 = __shfl_sync(FULLMASK, s[kk][1], src2);
                float v10 = __shfl_sync(FULLMASK, s[kk][2], src0);
                float v11 = __shfl_sync(FULLMASK, s[kk][3], src0);
                float v30 = __shfl_sync(FULLMASK, s[kk][2], src2);
                float v31 = __shfl_sync(FULLMASK, s[kk][3], src2);
                uint32_t aP[4];
                aP[0] = f2tf32(odd ? v01 : v00);
                aP[1] = f2tf32(odd ? v11 : v10);
                aP[2] = f2tf32(odd ? v21 : v20);
                aP[3] = f2tf32(odd ? v31 : v30);
#pragma unroll
                for (int nt = 0; nt < 4; ++nt) {
                    uint32_t bb[2];
                    bb[0] = Vt[(nt * 8 + gr) * 388 + j0 + kk * 8 + tg];
                    bb[1] = Vt[(nt * 8 + gr) * 388 + j0 + kk * 8 + tg + 4];
                    mma_tf32(o[nt], aP, bb);
                }
            }
        }

        // single end-of-loop row-sum reduction
        l0 += __shfl_xor_sync(FULLMASK, l0, 1);
        l0 += __shfl_xor_sync(FULLMASK, l0, 2);
        l1 += __shfl_xor_sync(FULLMASK, l1, 1);
        l1 += __shfl_xor_sync(FULLMASK, l1, 2);

        if (v_lo) {
            const float il0 = 1.f / l0;
            float* dst = g_attnout + ((size_t)b_ * NTOK + r_lo) * CDIM + h * HD;
#pragma unroll
            for (int nt = 0; nt < 4; ++nt)
                *(float2*)(dst + nt * 8 + tg * 2) =
                    make_float2(__uint_as_float(f2tf32(o[nt][0] * il0)),
                                __uint_as_float(f2tf32(o[nt][1] * il0)));
        }
        if (v_hi) {
            const float il1 = 1.f / l1;
            float* dst = g_attnout + ((size_t)b_ * NTOK + r_hi) * CDIM + h * HD;
#pragma unroll
            for (int nt = 0; nt < 4; ++nt)
                *(float2*)(dst + nt * 8 + tg * 2) =
                    make_float2(__uint_as_float(f2tf32(o[nt][2] * il1)),
                                __uint_as_float(f2tf32(o[nt][3] * il1)));
        }
    }
}

// ---------------- launch ---------------------------------------------------------
extern "C" void kernel_launch(void* const* d_in, const int* in_sizes, int n_in,
                              void* d_out, int out_size) {
    (void)in_sizes; (void)n_in; (void)out_size;
    const float* x = (const float*)d_in[0];
    const float* qkv_w = (const float*)d_in[1];
    const float* q_bias = (const float*)d_in[2];
    const float* v_bias = (const float*)d_in[3];
    const float* logit_scale = (const float*)d_in[4];
    const float* cpb_w1 = (const float*)d_in[5];
    const float* cpb_b1 = (const float*)d_in[6];
    const float* cpb_w2 = (const float*)d_in[7];
    const float* proj_w = (const float*)d_in[8];
    const float* proj_b = (const float*)d_in[9];
    const float* norm1_g = (const float*)d_in[10];
    const float* norm1_b = (const float*)d_in[11];
    const float* fc1_w = (const float*)d_in[12];
    const float* fc1_b = (const float*)d_in[13];
    const float* fc2_w = (const float*)d_in[14];
    const float* fc2_b = (const float*)d_in[15];
    const float* norm2_g = (const float*)d_in[16];
    const float* norm2_b = (const float*)d_in[17];
    float* out = (float*)d_out;

    static bool attr_done = false;
    if (!attr_done) {
        cudaFuncSetAttribute(attn4_kernel, cudaFuncAttributeMaxDynamicSharedMemorySize,
                             ATTN4_SMEM);
        cudaFuncSetAttribute(mma_gemm<0>, cudaFuncAttributeMaxDynamicSharedMemorySize,
                             GT_SMEM);
        cudaFuncSetAttribute(mma_gemm<2>, cudaFuncAttributeMaxDynamicSharedMemorySize,
                             GT_SMEM);
        cudaFuncSetAttribute(gemm_ln<0>, cudaFuncAttributeMaxDynamicSharedMemorySize,
                             LN_SMEM);
        cudaFuncSetAttribute(gemm_ln<1>, cudaFuncAttributeMaxDynamicSharedMemorySize,
                             LN_SMEM);
        attr_done = true;
    }

    // tf32 pre-conversion of all GEMM operands (one fused kernel)
    cvt_all<<<1024, 256>>>(x, qkv_w, proj_w, fc1_w, fc2_w);

    // constants
    cpb_kernel<<<2197, 256>>>(cpb_w1, cpb_b1, cpb_w2);
    rpb_kernel<<<888, 256>>>();

    // qkv (fused shift + window gather): M=43904, N=576, K=192
    mma_gemm<0><<<dim3(6, 343), 256, GT_SMEM>>>(q_bias, v_bias, 192);

    // attention (tensor-core flash, static max)
    attn4_kernel<<<768, 256, ATTN4_SMEM>>>(logit_scale);

    // proj + LN + residual (fused window reverse + roll scatter): N=192, K=192
    gemm_ln<0><<<343, 512, LN_SMEM>>>(proj_b, x, norm1_g, norm1_b, nullptr, 192);

    // fc1: N=768, K=192 (GELU)
    mma_gemm<2><<<dim3(8, 343), 256, GT_SMEM>>>(fc1_b, nullptr, 192);

    // fc2 + LN + residual: N=192, K=768
    gemm_ln<1><<<343, 512, LN_SMEM>>>(fc2_b, nullptr, norm2_g, norm2_b, out, 768);
}